// round 12
// baseline (speedup 1.0000x reference)
#include <cuda.h>
#include <cuda_runtime.h>
#include <cuda_bf16.h>
#include <math.h>
#include <stdint.h>

#define SEQ     4096
#define BATCH   2
#define ROWS    (BATCH*SEQ)     // 8192
#define DIMK    2048
#define D_INNER 4096
#define NHEADS  64
#define NPROJ   8480            // 8384 (in_proj) + 32 (theta) + 64 (lambda)
#define NPROJ_PAD 8576          // 67 * 128
#define OFF_Z   0
#define OFF_XC  4096
#define OFF_B   8192
#define OFF_C   8256
#define OFF_DT  8320
#define OFF_TH  8384
#define OFF_LAM 8416
#define NCHUNK  64
#define RMS_EPS 1.1920929e-07f

// ---------------- device scratch (no allocation allowed) ----------------
__device__ __nv_bfloat16 g_Wq [NPROJ_PAD * DIMK];
__device__ float         g_Ws [NPROJ_PAD * 16];
__device__ __nv_bfloat16 g_Woq[DIMK * D_INNER];
__device__ float         g_Wos[DIMK * 32];
__device__ __nv_bfloat16 g_xh [ROWS * DIMK];
__device__ __nv_bfloat16 g_xl [ROWS * DIMK];
__device__ __nv_bfloat16 g_Yh [ROWS * D_INNER];
__device__ __nv_bfloat16 g_Yl [ROWS * D_INNER];
__device__ float g_P [ROWS * NPROJ];
__device__ float g_Bv[ROWS * 64];
__device__ float g_Cv[ROWS * 64];
__device__ float g_Ad[ROWS * 64];
__device__ float g_ga[ROWS * 64];
__device__ float g_be[ROWS * 64];
__device__ float g_td[ROWS * 32];
__device__ float g_Y [ROWS * D_INNER];
__device__ float g_S [BATCH * NCHUNK * NHEADS * 64 * 64];
__device__ float g_eA[BATCH * NCHUNK * NHEADS * 64];
__device__ float g_cd[BATCH * NCHUNK * NHEADS];

__device__ __forceinline__ float siluf(float x) { return x / (1.f + expf(-x)); }

__device__ __forceinline__ uint32_t s2u(const void* p) {
    uint32_t a;
    asm("{ .reg .u64 t; cvta.to.shared.u64 t, %1; cvt.u32.u64 %0, t; }" : "=r"(a) : "l"(p));
    return a;
}

__device__ __forceinline__ void sp2(float v, __nv_bfloat16* ph, __nv_bfloat16* pl) {
    __nv_bfloat16 h = __float2bfloat16(v);
    *ph = h;
    *pl = __float2bfloat16(v - __bfloat162float(h));
}

#define LDSM4(r0,r1,r2,r3,a) \
    asm volatile("ldmatrix.sync.aligned.m8n8.x4.shared.b16 {%0,%1,%2,%3}, [%4];" \
        : "=r"(r0),"=r"(r1),"=r"(r2),"=r"(r3) : "r"(a))

#define LDSM4T(r0,r1,r2,r3,a) \
    asm volatile("ldmatrix.sync.aligned.m8n8.x4.trans.shared.b16 {%0,%1,%2,%3}, [%4];" \
        : "=r"(r0),"=r"(r1),"=r"(r2),"=r"(r3) : "r"(a))

#define MMA16816(d,a,b0,b1) \
    asm volatile("mma.sync.aligned.m16n8k16.row.col.f32.bf16.bf16.f32 " \
        "{%0,%1,%2,%3}, {%4,%5,%6,%7}, {%8,%9}, {%0,%1,%2,%3};" \
        : "+f"((d)[0]),"+f"((d)[1]),"+f"((d)[2]),"+f"((d)[3]) \
        : "r"((a)[0]),"r"((a)[1]),"r"((a)[2]),"r"((a)[3]),"r"(b0),"r"(b1))

// ================= TMA-fed quant-aware emulated-fp32 GEMM (unchanged from R10) =================
#define TILE_B  16384
#define STAGE_B (3*TILE_B)
#define MB_OFF  (3*STAGE_B)
#define SSB_OFF (MB_OFF + 64)

#define SWZ(o) ((o) ^ ((((uint32_t)(o)) >> 3) & 0x70u))

#define MBAR_INIT(a, c) asm volatile("mbarrier.init.shared.b64 [%0], %1;" :: "r"(a), "r"(c) : "memory")
#define FENCE_ASYNC()   asm volatile("fence.proxy.async.shared::cta;" ::: "memory")
#define MBAR_EXPECT(a, bytes) \
    asm volatile("mbarrier.arrive.expect_tx.shared.b64 _, [%0], %1;" :: "r"(a), "r"(bytes) : "memory")

__device__ __forceinline__ void mbar_wait(uint32_t a, uint32_t ph) {
    asm volatile(
        "{\n\t.reg .pred P;\n\t"
        "WL%=:\n\tmbarrier.try_wait.parity.acquire.cta.shared::cta.b64 P, [%0], %1, 0x989680;\n\t"
        "@P bra WD%=;\n\tbra WL%=;\n\tWD%=:\n\t}"
        :: "r"(a), "r"(ph) : "memory");
}

__device__ __forceinline__ void tma2d(uint32_t dst, const CUtensorMap* m, int x, int y, uint32_t mbar) {
    asm volatile(
        "cp.async.bulk.tensor.2d.shared::cta.global.tile.mbarrier::complete_tx::bytes "
        "[%0], [%1, {%2, %3}], [%4];"
        :: "r"(dst), "l"(m), "r"(x), "r"(y), "r"(mbar) : "memory");
}

template<int NG>
__global__ void __launch_bounds__(512, 1)
k_mmt(const __grid_constant__ CUtensorMap tAh,
      const __grid_constant__ CUtensorMap tAl,
      const __grid_constant__ CUtensorMap tBq,
      const float* __restrict__ Bs, float* __restrict__ C,
      int Nw, int Nlim, int K)
{
    extern __shared__ __align__(1024) uint8_t sh8[];
    float* ss = (float*)(sh8 + SSB_OFF);
    const uint32_t sb = s2u(sh8);
    const uint32_t mb = sb + MB_OFF;
    const int tid  = threadIdx.x;
    const int lane = tid & 31;
    const int wid  = tid >> 5;
    const int m0 = blockIdx.x * 128;
    const int n0 = blockIdx.y * 128;
    const int mw = (wid >> 2) * 32;
    const int nw = (wid & 3) * 32;

    if (tid == 0) {
        MBAR_INIT(mb + 0, 1);
        MBAR_INIT(mb + 8, 1);
        MBAR_INIT(mb + 16, 1);
    }
    for (int idx = tid; idx < 128 * NG; idx += 512) {
        int g = idx >> 7, nl = idx & 127;
        ss[g * 132 + nl] = Bs[(size_t)(n0 + nl) * NG + g];
    }
    __syncthreads();

    const int NK = K >> 6;

#define TFILL(buf, kc) do {                                   \
        uint32_t mba = mb + (buf) * 8;                        \
        MBAR_EXPECT(mba, 3 * TILE_B);                         \
        uint32_t d = sb + (buf) * STAGE_B;                    \
        tma2d(d,             &tAh, (kc) * 64, m0, mba);       \
        tma2d(d + TILE_B,    &tAl, (kc) * 64, m0, mba);       \
        tma2d(d + 2*TILE_B,  &tBq, (kc) * 64, n0, mba);       \
    } while (0)

    if (tid == 0) {
        FENCE_ASYNC();
        TFILL(0, 0);
        TFILL(1, 1);
    }

    float acc[2][4][4];
#pragma unroll
    for (int i = 0; i < 2; i++)
#pragma unroll
        for (int j = 0; j < 4; j++)
#pragma unroll
            for (int k = 0; k < 4; k++) acc[i][j][k] = 0.f;

    const int rowoff = (lane & 7) + ((lane >> 3) & 1) * 8;
    const int colb2  = (lane >> 4) * 16;
    const int c0 = (lane & 3) * 2;

    for (int g = 0; g < NG; g++) {
        float accg[2][4][4];
#pragma unroll
        for (int i = 0; i < 2; i++)
#pragma unroll
            for (int j = 0; j < 4; j++)
#pragma unroll
                for (int k = 0; k < 4; k++) accg[i][j][k] = 0.f;

#pragma unroll
        for (int kq = 0; kq < 2; kq++) {
            const int kc = g * 2 + kq;
            const int buf = kc % 3;
            const uint32_t ph = (kc / 3) & 1;

            mbar_wait(mb + buf * 8, ph);
            __syncthreads();

            if (tid == 0 && kc + 2 < NK) {
                FENCE_ASYNC();
                TFILL((kc + 2) % 3, kc + 2);
            }

            const uint32_t stg = sb + buf * STAGE_B;
#pragma unroll
            for (int kk = 0; kk < 4; kk++) {
                uint32_t afr[2][2][4];
                uint32_t bfr[2][4];
#pragma unroll
                for (int hl = 0; hl < 2; hl++)
#pragma unroll
                    for (int mi = 0; mi < 2; mi++) {
                        uint32_t off = (uint32_t)(mw + mi * 16 + rowoff) * 128 + kk * 32 + colb2;
                        uint32_t a = stg + hl * TILE_B + SWZ(off);
                        LDSM4(afr[hl][mi][0], afr[hl][mi][1], afr[hl][mi][2], afr[hl][mi][3], a);
                    }
#pragma unroll
                for (int nj = 0; nj < 2; nj++) {
                    uint32_t off = (uint32_t)(nw + nj * 16 + rowoff) * 128 + kk * 32 + colb2;
                    uint32_t a = stg + 2 * TILE_B + SWZ(off);
                    LDSM4(bfr[nj][0], bfr[nj][1], bfr[nj][2], bfr[nj][3], a);
                }
#pragma unroll
                for (int term = 0; term < 2; term++)
#pragma unroll
                    for (int mi = 0; mi < 2; mi++)
#pragma unroll
                        for (int ni = 0; ni < 4; ni++) {
                            int nj = ni >> 1, s = ni & 1;
                            MMA16816(accg[mi][ni], afr[term][mi],
                                     bfr[nj][s], bfr[nj][s + 2]);
                        }
            }
        }

#pragma unroll
        for (int ni = 0; ni < 4; ni++) {
            float2 sv = *(const float2*)&ss[g * 132 + nw + ni * 8 + c0];
#pragma unroll
            for (int mi = 0; mi < 2; mi++) {
                acc[mi][ni][0] = fmaf(sv.x, accg[mi][ni][0], acc[mi][ni][0]);
                acc[mi][ni][1] = fmaf(sv.y, accg[mi][ni][1], acc[mi][ni][1]);
                acc[mi][ni][2] = fmaf(sv.x, accg[mi][ni][2], acc[mi][ni][2]);
                acc[mi][ni][3] = fmaf(sv.y, accg[mi][ni][3], acc[mi][ni][3]);
            }
        }
    }

    const int r0 = lane >> 2;
#pragma unroll
    for (int mi = 0; mi < 2; mi++) {
#pragma unroll
        for (int ni = 0; ni < 4; ni++) {
            int m = m0 + mw + mi * 16 + r0;
            int n = n0 + nw + ni * 8 + c0;
            if (n < Nlim) {
                *(float2*)&C[(size_t)m * Nw + n]       = make_float2(acc[mi][ni][0], acc[mi][ni][1]);
                *(float2*)&C[(size_t)(m + 8) * Nw + n] = make_float2(acc[mi][ni][2], acc[mi][ni][3]);
            }
        }
    }
#undef TFILL
}

// ---------------- fq4 dequantization -> q (bf16, exact) + group scale ----------------
__global__ void k_dequantq(const float* __restrict__ src, __nv_bfloat16* __restrict__ dq,
                           float* __restrict__ ds, int ngroups)
{
    int g = blockIdx.x * 4 + (threadIdx.x >> 5);
    if (g >= ngroups) return;
    int lane = threadIdx.x & 31;
    const float* s = src + (size_t)g * 128;
    float v[4];
    float m = 0.f;
#pragma unroll
    for (int i = 0; i < 4; i++) { v[i] = s[lane + 32*i]; m = fmaxf(m, fabsf(v[i])); }
#pragma unroll
    for (int o = 16; o; o >>= 1) m = fmaxf(m, __shfl_xor_sync(0xffffffffu, m, o));
    float scale = fmaxf(m, 1e-10f) / 7.0f;
    if (lane == 0) ds[g] = scale;
#pragma unroll
    for (int i = 0; i < 4; i++) {
        float q = rintf(v[i] / scale);
        q = fminf(fmaxf(q, -8.f), 7.f);
        dq[(size_t)g * 128 + lane + 32*i] = __float2bfloat16(q);
    }
}

// ---------------- split fp32 -> bf16 hi/lo ----------------
__global__ void k_split(const float* __restrict__ src, __nv_bfloat16* __restrict__ dh,
                        __nv_bfloat16* __restrict__ dl)
{
    size_t i = ((size_t)blockIdx.x * 256 + threadIdx.x) * 4;
    float4 v = *(const float4*)(src + i);
    float vv[4] = {v.x, v.y, v.z, v.w};
#pragma unroll
    for (int k = 0; k < 4; k++) sp2(vv[k], dh + i + k, dl + i + k);
}

// ---------------- pointwise epilogue per (b,l) row: 64 threads ----------------
__global__ void k_point(const float* __restrict__ Bb, const float* __restrict__ Cb,
                        const float* __restrict__ Alog, const float* __restrict__ dtb)
{
    int row = blockIdx.x;
    int t = threadIdx.x;
    const float* pr = g_P + (size_t)row * NPROJ;
    __shared__ float red[6];

    float dtr = pr[OFF_DT + t] + dtb[t];
    float dt = (dtr > 20.f) ? dtr : log1pf(expf(dtr));
    float Ad = -expf(Alog[t]) * dt;
    float lam = 1.f / (1.f + expf(-pr[OFF_LAM + t]));
    g_Ad[row*64 + t] = Ad;
    g_ga[row*64 + t] = lam * dt;
    g_be[row*64 + t] = (1.f - lam) * dt * expf(Ad);

    float bv = pr[OFF_B + t];
    float cv = pr[OFF_C + t];

    float s0 = dt, s1 = bv*bv, s2 = cv*cv;
#pragma unroll
    for (int o = 16; o; o >>= 1) {
        s0 += __shfl_xor_sync(0xffffffffu, s0, o);
        s1 += __shfl_xor_sync(0xffffffffu, s1, o);
        s2 += __shfl_xor_sync(0xffffffffu, s2, o);
    }
    int w = t >> 5;
    if ((t & 31) == 0) { red[w*3+0] = s0; red[w*3+1] = s1; red[w*3+2] = s2; }
    __syncthreads();
    float dt_avg = (red[0] + red[3]) * (1.f/64.f);
    float rb = rsqrtf((red[1] + red[4]) * (1.f/64.f) + RMS_EPS);
    float rc = rsqrtf((red[2] + red[5]) * (1.f/64.f) + RMS_EPS);

    g_Bv[row*64 + t] = bv * rb + Bb[t];
    g_Cv[row*64 + t] = cv * rc + Cb[t];
    if (t < 32) g_td[row*32 + t] = pr[OFF_TH + t] * dt_avg;
}

// ---------------- cumsum of theta*dt_avg over L per (b, n) ----------------
__global__ void k_scan()
{
    int b = blockIdx.x >> 5;
    int n = blockIdx.x & 31;
    int tid = threadIdx.x;
    __shared__ float ps[256];
    float loc[16];
    float run = 0.f;
    int base = (b*SEQ + tid*16) * 32 + n;
#pragma unroll
    for (int j = 0; j < 16; j++) { run += g_td[base + j*32]; loc[j] = run; }
    ps[tid] = run;
    __syncthreads();
#pragma unroll
    for (int o = 1; o < 256; o <<= 1) {
        float v = (tid >= o) ? ps[tid - o] : 0.f;
        __syncthreads();
        ps[tid] += v;
        __syncthreads();
    }
    float off = (tid > 0) ? ps[tid - 1] : 0.f;
#pragma unroll
    for (int j = 0; j < 16; j++) g_td[base + j*32] = loc[j] + off;
}

// ---------------- rope on B and C (in place) ----------------
__global__ void k_rope()
{
    int row = blockIdx.x;
    int t = threadIdx.x;
    float a = g_td[row*32 + t];
    float ca = cosf(a), sa = sinf(a);
    float br = g_Bv[row*64 + t], bi = g_Bv[row*64 + 32 + t];
    g_Bv[row*64 + t]      = br*ca - bi*sa;
    g_Bv[row*64 + 32 + t] = br*sa + bi*ca;
    float cr = g_Cv[row*64 + t], ci = g_Cv[row*64 + 32 + t];
    g_Cv[row*64 + t]      = cr*ca - ci*sa;
    g_Cv[row*64 + 32 + t] = cr*sa + ci*ca;
}

// ================= tensor-core intra-chunk: Y_diag + per-chunk states =================
// smem: 10 bf16 arrays [64][72] (Xh,Xl,Xwh,Xwl,Bh,Bl,Ch,Cl,Gh,Gl) + sA[64],sW[64]
#define CP 72                         // half pitch
#define AOF(i) ((i) * 64 * CP)        // half offset of array i
#define SM_CHUNK_BYTES (10 * 64 * CP * 2 + 512)

__launch_bounds__(256)
__global__ void k_chunk()
{
    extern __shared__ __nv_bfloat16 smh[];
    float* sA = (float*)(smh + 10 * 64 * CP);
    float* sW = sA + 64;
    const uint32_t sb = s2u(smh);

    const int h = blockIdx.x, c = blockIdx.y, b = blockIdx.z;
    const int tid = threadIdx.x;
    const int lane = tid & 31;
    const int wid  = tid >> 5;

    // ---- Phase A: cumsum of A_disc, decay weights ----
    if (tid < 64) {
        int row_g = b*SEQ + c*64 + tid;
        sA[tid] = g_Ad[row_g*64 + h];
    }
    __syncthreads();
#pragma unroll
    for (int o = 1; o < 64; o <<= 1) {
        float v = (tid < 64 && tid >= o) ? sA[tid - o] : 0.f;
        __syncthreads();
        if (tid < 64) sA[tid] += v;
        __syncthreads();
    }
    float Alast = sA[63];
    if (tid < 64) {
        sW[tid] = expf(Alast - sA[tid]);
        g_eA[((b*NCHUNK + c)*NHEADS + h)*64 + tid] = expf(sA[tid]);
    }
    if (tid == 0) g_cd[(b*NCHUNK + c)*NHEADS + h] = expf(Alast);
    __syncthreads();

    // ---- Phase B: load + convert to bf16 hi/lo ----
    {
        int l = tid >> 2;
        int pg = (tid & 3) * 16;
        int row_g = b*SEQ + c*64 + l;
        float ga = g_ga[row_g*64 + h];
        float be = g_be[row_g*64 + h];
        float w  = sW[l];
        const float* xp = g_P + (size_t)row_g*NPROJ + OFF_XC + h*64 + pg;
        const float* bp = g_Bv + row_g*64 + pg;
        const float* cp = g_Cv + row_g*64 + pg;
        bool hasprev = (c*64 + l) > 0;
#pragma unroll
        for (int j = 0; j < 4; j++) {
            float4 xc = *(const float4*)(xp + j*4);
            float xv[4] = { siluf(xc.x)*ga, siluf(xc.y)*ga, siluf(xc.z)*ga, siluf(xc.w)*ga };
            if (hasprev) {
                float4 xq = *(const float4*)(xp - NPROJ + j*4);
                xv[0] += siluf(xq.x)*be; xv[1] += siluf(xq.y)*be;
                xv[2] += siluf(xq.z)*be; xv[3] += siluf(xq.w)*be;
            }
            float4 bb = *(const float4*)(bp + j*4);
            float4 cc = *(const float4*)(cp + j*4);
            float bv[4] = {bb.x, bb.y, bb.z, bb.w};
            float cv[4] = {cc.x, cc.y, cc.z, cc.w};
#pragma unroll
            for (int e = 0; e < 4; e++) {
                int col = pg + j*4 + e;
                int off = l*CP + col;
                sp2(xv[e],   smh + AOF(0) + off, smh + AOF(1) + off);
                sp2(w*xv[e], smh + AOF(2) + off, smh + AOF(3) + off);
                sp2(bv[e],   smh + AOF(4) + off, smh + AOF(5) + off);
                sp2(cv[e],   smh + AOF(6) + off, smh + AOF(7) + off);
            }
        }
    }
    __syncthreads();

    const int mi = wid >> 1;          // 4 m-tiles of 16
    const int nh = wid & 1;           // n half (32)
    const int rowoff   = (lane & 7) + ((lane >> 3) & 1) * 8;
    const int colb     = (lane >> 4) * 16;
    const int rowoff_t = (lane & 7) + ((lane >> 4) & 1) * 8;
    const int colb_t   = ((lane >> 3) & 1) * 16;
    const int r0 = lane >> 2, c0 = (lane & 3) * 2;

    // ---- Matmul 1: G[l][s] = C . B^T (3-term), scale+mask, store hi/lo ----
    {
        float ag[4][4];
#pragma unroll
        for (int i = 0; i < 4; i++)
#pragma unroll
            for (int j = 0; j < 4; j++) ag[i][j] = 0.f;
#pragma unroll
        for (int k = 0; k < 4; k++) {
            uint32_t af[2][4], bf[2][2][4];
#pragma unroll
            for (int hl = 0; hl < 2; hl++) {
                uint32_t a = sb + (AOF(6 + hl) + (mi*16 + rowoff)*CP)*2 + k*32 + colb;
                LDSM4(af[hl][0], af[hl][1], af[hl][2], af[hl][3], a);
#pragma unroll
                for (int nj = 0; nj < 2; nj++) {
                    uint32_t bA = sb + (AOF(4 + hl) + (nh*32 + nj*16 + rowoff)*CP)*2 + k*32 + colb;
                    LDSM4(bf[hl][nj][0], bf[hl][nj][1], bf[hl][nj][2], bf[hl][nj][3], bA);
                }
            }
#pragma unroll
            for (int t3 = 0; t3 < 3; t3++) {
                int ah = (t3 == 1) ? 1 : 0;
                int bh = (t3 == 2) ? 1 : 0;
#pragma unroll
                for (int ni = 0; ni < 4; ni++) {
                    int nj = ni >> 1, s = ni & 1;
                    MMA16816(ag[ni], af[ah], bf[bh][nj][s], bf[bh][nj][s + 2]);
                }
            }
        }
        // mask + scale + store
        float al0 = sA[mi*16 + r0], al1 = sA[mi*16 + r0 + 8];
#pragma unroll
        for (int ni = 0; ni < 4; ni++) {
            int s0i = nh*32 + ni*8 + c0;
#pragma unroll
            for (int e = 0; e < 2; e++) {
                int s = s0i + e;
                float as = sA[s];
                int l0i = mi*16 + r0;
                float v0 = (s <= l0i)     ? ag[ni][e]     * expf(al0 - as) : 0.f;
                float v1 = (s <= l0i + 8) ? ag[ni][e + 2] * expf(al1 - as) : 0.f;
                sp2(v0, smh + AOF(8) + l0i*CP + s,       smh + AOF(9) + l0i*CP + s);
                sp2(v1, smh + AOF(8) + (l0i+8)*CP + s,   smh + AOF(9) + (l0i+8)*CP + s);
            }
        }
    }

    // ---- Matmul 3: S[p][n] = (wX)^T . B  (trans loads; independent of G) ----
    {
        float as3[4][4];
#pragma unroll
        for (int i = 0; i < 4; i++)
#pragma unroll
            for (int j = 0; j < 4; j++) as3[i][j] = 0.f;
#pragma unroll
        for (int k = 0; k < 4; k++) {     // k over l
            uint32_t af[2][4], bf[2][2][4];
#pragma unroll
            for (int hl = 0; hl < 2; hl++) {
                uint32_t a = sb + (AOF(2 + hl) + (k*16 + rowoff_t)*CP + mi*16)*2 + colb_t;
                LDSM4T(af[hl][0], af[hl][1], af[hl][2], af[hl][3], a);
#pragma unroll
                for (int nj = 0; nj < 2; nj++) {
                    uint32_t bA = sb + (AOF(4 + hl) + (k*16 + rowoff_t)*CP + nh*32 + nj*16)*2 + colb_t;
                    LDSM4T(bf[hl][nj][0], bf[hl][nj][1], bf[hl][nj][2], bf[hl][nj][3], bA);
                }
            }
#pragma unroll
            for (int t3 = 0; t3 < 3; t3++) {
                int ah = (t3 == 1) ? 1 : 0;
                int bh = (t3 == 2) ? 1 : 0;
#pragma unroll
                for (int ni = 0; ni < 4; ni++) {
                    int nj = ni >> 1, s = ni & 1;
                    MMA16816(as3[ni], af[ah], bf[bh][nj][s], bf[bh][nj][s + 2]);
                }
            }
        }
        size_t base = (size_t)((b*NCHUNK + c)*NHEADS + h) * 4096;
#pragma unroll
        for (int ni = 0; ni < 4; ni++) {
            int n = nh*32 + ni*8 + c0;
            int p = mi*16 + r0;
            *(float2*)&g_S[base + p*64 + n]       = make_float2(as3[ni][0], as3[ni][1]);
            *(float2*)&g_S[base + (p+8)*64 + n]   = make_float2(as3[ni][2], as3[ni][3]);
        }
    }
    __syncthreads();   // G visible to all warps

    // ---- Matmul 2: Y_diag[l][p] = G . X  (A = G, B = X^T via trans) ----
    {
        float ay[4][4];
#pragma unroll
        for (int i = 0; i < 4; i++)
#pragma unroll
            for (int j = 0; j < 4; j++) ay[i][j] = 0.f;
#pragma unroll
        for (int k = 0; k < 4; k++) {     // k over s
            uint32_t af[2][4], bf[2][2][4];
#pragma unroll
            for (int hl = 0; hl < 2; hl++) {
                uint32_t a = sb + (AOF(8 + hl) + (mi*16 + rowoff)*CP)*2 + k*32 + colb;
                LDSM4(af[hl][0], af[hl][1], af[hl][2], af[hl][3], a);
#pragma unroll
                for (int nj = 0; nj < 2; nj++) {
                    uint32_t bA = sb + (AOF(0 + hl) + (k*16 + rowoff_t)*CP + nh*32 + nj*16)*2 + colb_t;
                    LDSM4T(bf[hl][nj][0], bf[hl][nj][1], bf[hl][nj][2], bf[hl][nj][3], bA);
                }
            }
#pragma unroll
            for (int t3 = 0; t3 < 3; t3++) {
                int ah = (t3 == 1) ? 1 : 0;
                int bh = (t3 == 2) ? 1 : 0;
#pragma unroll
                for (int ni = 0; ni < 4; ni++) {
                    int nj = ni >> 1, s = ni & 1;
                    MMA16816(ay[ni], af[ah], bf[bh][nj][s], bf[bh][nj][s + 2]);
                }
            }
        }
#pragma unroll
        for (int ni = 0; ni < 4; ni++) {
            int p = nh*32 + ni*8 + c0;
            int l = mi*16 + r0;
            int rg0 = b*SEQ + c*64 + l;
            *(float2*)&g_Y[(size_t)rg0*D_INNER + h*64 + p]       = make_float2(ay[ni][0], ay[ni][1]);
            *(float2*)&g_Y[(size_t)(rg0+8)*D_INNER + h*64 + p]   = make_float2(ay[ni][2], ay[ni][3]);
        }
    }
}

// ---------------- inter-chunk scan: 512 CTAs, one (b,h,quarter) each ----------------
__global__ void k_cscan()
{
    int q = blockIdx.x & 3;
    int h = (blockIdx.x >> 2) & 63;
    int b = blockIdx.x >> 8;
    int tid = threadIdx.x;
    int off = q * 1024 + tid * 4;
    float s0 = 0.f, s1 = 0.f, s2 = 0.f, s3 = 0.f;
    const float* cdp = g_cd + b * NCHUNK * NHEADS + h;
    for (int c = 0; c < NCHUNK; c++) {
        size_t base = ((size_t)((b*NCHUNK + c)*NHEADS + h) << 12) + off;
        float cd = cdp[c * NHEADS];
        float4 t = *(const float4*)&g_S[base];
        *(float4*)&g_S[base] = make_float4(s0, s1, s2, s3);
        s0 = fmaf(cd, s0, t.x);
        s1 = fmaf(cd, s1, t.y);
        s2 = fmaf(cd, s2, t.z);
        s3 = fmaf(cd, s3, t.w);
    }
}

// ================= tensor-core Y_off + D skip + z gating =================
// smem: 4 bf16 arrays [64][72]: Ch, Cl, Sh, Sl
#define SM_OFF_BYTES (4 * 64 * CP * 2)
__launch_bounds__(256)
__global__ void k_off(const float* __restrict__ Dp)
{
    extern __shared__ __nv_bfloat16 smh[];
    const uint32_t sb = s2u(smh);
    const int h = blockIdx.x, c = blockIdx.y, b = blockIdx.z;
    const int tid = threadIdx.x;
    const int lane = tid & 31;
    const int wid  = tid >> 5;
    size_t sbase = (size_t)((b*NCHUNK + c)*NHEADS + h) * 4096;

    // load + convert C and S to hi/lo
    {
        int r = tid >> 2;
        int cg = (tid & 3) * 16;
        int row_g = b*SEQ + c*64 + r;
#pragma unroll
        for (int j = 0; j < 4; j++) {
            float4 cv = *(const float4*)&g_Cv[row_g*64 + cg + j*4];
            float4 sv = *(const float4*)&g_S[sbase + r*64 + cg + j*4];
            float cvv[4] = {cv.x, cv.y, cv.z, cv.w};
            float svv[4] = {sv.x, sv.y, sv.z, sv.w};
#pragma unroll
            for (int e = 0; e < 4; e++) {
                int off = r*CP + cg + j*4 + e;
                sp2(cvv[e], smh + AOF(0) + off, smh + AOF(1) + off);
                sp2(svv[e], smh + AOF(2) + off, smh + AOF(3) + off);
            }
        }
    }
    __syncthreads();

    const int mi = wid >> 1;
    const int nh = wid & 1;
    const int rowoff = (lane & 7) + ((lane >> 3) & 1) * 8;
    const int colb   = (lane >> 4) * 16;
    const int r0 = lane >> 2, c0 = (lane & 3) * 2;

    float acc[4][4];
#pragma unroll
    for (int i = 0; i < 4; i++)
#pragma unroll
        for (int j = 0; j < 4; j++) acc[i][j] = 0.f;

#pragma unroll
    for (int k = 0; k < 4; k++) {        // k over n (state dim)
        uint32_t af[2][4], bf[2][2][4];
#pragma unroll
        for (int hl = 0; hl < 2; hl++) {
            uint32_t a = sb + (AOF(0 + hl) + (mi*16 + rowoff)*CP)*2 + k*32 + colb;
            LDSM4(af[hl][0], af[hl][1], af[hl][2], af[hl][3], a);
#pragma unroll
            for (int nj = 0; nj < 2; nj++) {
                uint32_t bA = sb + (AOF(2 + hl) + (nh*32 + nj*16 + rowoff)*CP)*2 + k*32 + colb;
                LDSM4(bf[hl][nj][0], bf[hl][nj][1], bf[hl][nj][2], bf[hl][nj][3], bA);
            }
        }
#pragma unroll
        for (int t3 = 0; t3 < 3; t3++) {
            int ah = (t3 == 1) ? 1 : 0;
            int bh = (t3 == 2) ? 1 : 0;
#pragma unroll
            for (int ni = 0; ni < 4; ni++) {
                int nj = ni >> 1, s = ni & 1;
                MMA16816(acc[ni], af[ah], bf[bh][nj][s], bf[bh][nj][s + 2]);
            }
        }
    }

    // epilogue: fragment (l, p)
    float Dh = Dp[h];
#pragma unroll
    for (int rr = 0; rr < 2; rr++) {
        int l = mi*16 + r0 + rr*8;
        int row_g = b*SEQ + c*64 + l;
        float e = g_eA[((b*NCHUNK + c)*NHEADS + h)*64 + l];
        const float* pr = g_P + (size_t)row_g*NPROJ;
#pragma unroll
        for (int ni = 0; ni < 4; ni++) {
            int p = nh*32 + ni*8 + c0;
            float2 xc = *(const float2*)&pr[OFF_XC + h*64 + p];
            float2 zz = *(const float2*)&pr[OFF_Z  + h*64 + p];
            float* yp = &g_Y[(size_t)row_g*D_INNER + h*64 + p];
            float2 yd = *(const float2*)yp;
            float a0 = acc[ni][rr*2 + 0], a1 = acc[ni][rr*2 + 1];
            float2 o;
            o.x = (yd.x + e*a0 + Dh*siluf(xc.x)) * siluf(zz.x);
            o.y = (yd.y + e*a1 + Dh*siluf(xc.y)) * siluf(zz.y);
            *(float2*)yp = o;
        }
    }
}

// ---------------- rmsnorm over 4096 per row -> bf16 hi/lo ----------------
__global__ void k_rms()
{
    int row = blockIdx.x;
    int tid = threadIdx.x;
    const float* Yp = g_Y + (size_t)row * D_INNER;
    float4 v[4];
    float ss = 0.f;
#pragma unroll
    for (int i = 0; i < 4; i++) {
        v[i] = *(const float4*)&Yp[tid*16 + i*4];
        ss += v[i].x*v[i].x + v[i].y*v[i].y + v[i].z*v[i].z + v[i].w*v[i].w;
    }
#pragma unroll
    for (int o = 16; o; o >>= 1) ss += __shfl_xor_sync(0xffffffffu, ss, o);
    __shared__ float red[8];
    if ((tid & 31) == 0) red[tid >> 5] = ss;
    __syncthreads();
    float tot = 0.f;
#pragma unroll
    for (int i = 0; i < 8; i++) tot += red[i];
    float r = rsqrtf(tot * (1.f/4096.f) + RMS_EPS);
    size_t base = (size_t)row * D_INNER + tid*16;
#pragma unroll
    for (int i = 0; i < 4; i++) {
        float vv[4] = {v[i].x*r, v[i].y*r, v[i].z*r, v[i].w*r};
#pragma unroll
        for (int k = 0; k < 4; k++)
            sp2(vv[k], g_Yh + base + i*4 + k, g_Yl + base + i*4 + k);
    }
}

// ---------------- host: tensormap construction ----------------
typedef CUresult (*PFN_encodeTiled)(
    CUtensorMap*, CUtensorMapDataType, cuuint32_t, void*,
    const cuuint64_t*, const cuuint64_t*, const cuuint32_t*, const cuuint32_t*,
    CUtensorMapInterleave, CUtensorMapSwizzle, CUtensorMapL2promotion, CUtensorMapFloatOOBfill);

static void mk2d(PFN_encodeTiled enc, CUtensorMap* m, void* ptr, uint64_t k, uint64_t rows)
{
    cuuint64_t dims[2]    = {k, rows};
    cuuint64_t strides[1] = {k * 2};
    cuuint32_t box[2]     = {64, 128};
    cuuint32_t es[2]      = {1, 1};
    enc(m, CU_TENSOR_MAP_DATA_TYPE_BFLOAT16, 2, ptr, dims, strides, box, es,
        CU_TENSOR_MAP_INTERLEAVE_NONE, CU_TENSOR_MAP_SWIZZLE_128B,
        CU_TENSOR_MAP_L2_PROMOTION_L2_128B, CU_TENSOR_MAP_FLOAT_OOB_FILL_NONE);
}

// ---------------- launcher ----------------
extern "C" void kernel_launch(void* const* d_in, const int* in_sizes, int n_in,
                              void* d_out, int out_size)
{
    const float* x    = (const float*)d_in[0];
    const float* Win  = (const float*)d_in[1];
    const float* Wth  = (const float*)d_in[2];
    const float* Wla  = (const float*)d_in[3];
    const float* Wout = (const float*)d_in[4];
    const float* Bb   = (const float*)d_in[5];
    const float* Cb   = (const float*)d_in[6];
    const float* Alog = (const float*)d_in[7];
    const float* Dp   = (const float*)d_in[8];
    const float* dtb  = (const float*)d_in[9];
    float* out = (float*)d_out;

    __nv_bfloat16 *pWq, *pWoq, *pxh, *pxl, *pYh, *pYl;
    float *pWs, *pWos, *pP;
    cudaGetSymbolAddress((void**)&pWq,  g_Wq);
    cudaGetSymbolAddress((void**)&pWs,  g_Ws);
    cudaGetSymbolAddress((void**)&pWoq, g_Woq);
    cudaGetSymbolAddress((void**)&pWos, g_Wos);
    cudaGetSymbolAddress((void**)&pxh,  g_xh);
    cudaGetSymbolAddress((void**)&pxl,  g_xl);
    cudaGetSymbolAddress((void**)&pYh,  g_Yh);
    cudaGetSymbolAddress((void**)&pYl,  g_Yl);
    cudaGetSymbolAddress((void**)&pP,   g_P);

    PFN_encodeTiled enc = nullptr;
    {
        void* fp = nullptr;
        cudaDriverEntryPointQueryResult qr;
        cudaGetDriverEntryPoint("cuTensorMapEncodeTiled", &fp, cudaEnableDefault, &qr);
        enc = (PFN_encodeTiled)fp;
    }
    CUtensorMap t1Ah, t1Al, t1Bq, t2Ah, t2Al, t2Bq;
    mk2d(enc, &t1Ah, pxh,  DIMK,    ROWS);
    mk2d(enc, &t1Al, pxl,  DIMK,    ROWS);
    mk2d(enc, &t1Bq, pWq,  DIMK,    NPROJ_PAD);
    mk2d(enc, &t2Ah, pYh,  D_INNER, ROWS);
    mk2d(enc, &t2Al, pYl,  D_INNER, ROWS);
    mk2d(enc, &t2Bq, pWoq, D_INNER, DIMK);

    const int smem1 = SSB_OFF + 16 * 132 * 4;
    const int smem2 = SSB_OFF + 32 * 132 * 4;

    cudaFuncSetAttribute(k_chunk,    cudaFuncAttributeMaxDynamicSharedMemorySize, SM_CHUNK_BYTES);
    cudaFuncSetAttribute(k_off,      cudaFuncAttributeMaxDynamicSharedMemorySize, SM_OFF_BYTES);
    cudaFuncSetAttribute(k_mmt<16>,  cudaFuncAttributeMaxDynamicSharedMemorySize, smem1);
    cudaFuncSetAttribute(k_mmt<32>,  cudaFuncAttributeMaxDynamicSharedMemorySize, smem2);

    k_dequantq<<<(8384*16 + 3)/4, 128>>>(Win, pWq, pWs, 8384*16);
    k_dequantq<<<(512 + 3)/4,    128>>>(Wth, pWq + (size_t)8384*DIMK, pWs + (size_t)8384*16, 512);
    k_dequantq<<<(1024 + 3)/4,   128>>>(Wla, pWq + (size_t)8416*DIMK, pWs + (size_t)8416*16, 1024);
    k_dequantq<<<65536/4,        128>>>(Wout, pWoq, pWos, 65536);

    k_split<<<ROWS*DIMK/1024, 256>>>(x, pxh, pxl);

    k_mmt<16><<<dim3(ROWS/128, NPROJ_PAD/128), 512, smem1>>>(
        t1Ah, t1Al, t1Bq, pWs, pP, NPROJ, NPROJ, DIMK);

    k_point<<<ROWS, 64>>>(Bb, Cb, Alog, dtb);
    k_scan <<<64, 256>>>();
    k_rope <<<ROWS, 32>>>();

    k_chunk<<<dim3(NHEADS, NCHUNK, BATCH), 256, SM_CHUNK_BYTES>>>();
    k_cscan<<<512, 256>>>();
    k_off  <<<dim3(NHEADS, NCHUNK, BATCH), 256, SM_OFF_BYTES>>>(Dp);

    k_rms<<<ROWS, 256>>>();

    k_mmt<32><<<dim3(ROWS/128, DIMK/128), 512, smem2>>>(
        t2Ah, t2Al, t2Bq, pWos, out, DIMK, DIMK, D_INNER);
}

// round 13
// speedup vs baseline: 1.1160x; 1.1160x over previous
#include <cuda.h>
#include <cuda_runtime.h>
#include <cuda_bf16.h>
#include <math.h>
#include <stdint.h>

#define SEQ     4096
#define BATCH   2
#define ROWS    (BATCH*SEQ)     // 8192
#define DIMK    2048
#define D_INNER 4096
#define NHEADS  64
#define NPROJ   8480
#define NPROJ_PAD 8576          // 67 * 128
#define OFF_Z   0
#define OFF_XC  4096
#define OFF_B   8192
#define OFF_C   8256
#define OFF_DT  8320
#define OFF_TH  8384
#define OFF_LAM 8416
#define NCHUNK  64
#define RMS_EPS 1.1920929e-07f

// ---------------- device scratch (no allocation allowed) ----------------
__device__ __nv_bfloat16 g_Wq [NPROJ_PAD * DIMK];
__device__ float         g_Ws [NPROJ_PAD * 16];
__device__ __nv_bfloat16 g_Woq[DIMK * D_INNER];
__device__ float         g_Wos[DIMK * 32];
__device__ __nv_bfloat16 g_xh [ROWS * DIMK];
__device__ __nv_bfloat16 g_xl [ROWS * DIMK];
__device__ __nv_bfloat16 g_Yh [ROWS * D_INNER];
__device__ __nv_bfloat16 g_Yl [ROWS * D_INNER];
__device__ float g_P [ROWS * NPROJ];
__device__ float g_Bv[ROWS * 64];
__device__ float g_Cv[ROWS * 64];
__device__ float g_Ad[ROWS * 64];
__device__ float g_ga[ROWS * 64];
__device__ float g_be[ROWS * 64];
__device__ float g_td[ROWS * 32];
__device__ float g_Y [ROWS * D_INNER];
__device__ float g_S [BATCH * NCHUNK * NHEADS * 64 * 64];
__device__ float g_eA[BATCH * NCHUNK * NHEADS * 64];
__device__ float g_cd[BATCH * NCHUNK * NHEADS];

__device__ __forceinline__ float siluf(float x) { return x / (1.f + expf(-x)); }

__device__ __forceinline__ uint32_t s2u(const void* p) {
    uint32_t a;
    asm("{ .reg .u64 t; cvta.to.shared.u64 t, %1; cvt.u32.u64 %0, t; }" : "=r"(a) : "l"(p));
    return a;
}

// ================= TMA-fed quant-aware emulated-fp32 GEMM =================
// Identical math to R10; CTA rasterization is stripe-swizzled (8 m-tiles per stripe,
// n swept innermost) so each wave's A working set stays L2-resident.
#define TILE_B  16384
#define STAGE_B (3*TILE_B)
#define MB_OFF  (3*STAGE_B)
#define SSB_OFF (MB_OFF + 64)

#define SWZ(o) ((o) ^ ((((uint32_t)(o)) >> 3) & 0x70u))

#define LDSM4(r0,r1,r2,r3,a) \
    asm volatile("ldmatrix.sync.aligned.m8n8.x4.shared.b16 {%0,%1,%2,%3}, [%4];" \
        : "=r"(r0),"=r"(r1),"=r"(r2),"=r"(r3) : "r"(a))

#define MMA16816(d,a,b0,b1) \
    asm volatile("mma.sync.aligned.m16n8k16.row.col.f32.bf16.bf16.f32 " \
        "{%0,%1,%2,%3}, {%4,%5,%6,%7}, {%8,%9}, {%0,%1,%2,%3};" \
        : "+f"((d)[0]),"+f"((d)[1]),"+f"((d)[2]),"+f"((d)[3]) \
        : "r"((a)[0]),"r"((a)[1]),"r"((a)[2]),"r"((a)[3]),"r"(b0),"r"(b1))

#define MBAR_INIT(a, c) asm volatile("mbarrier.init.shared.b64 [%0], %1;" :: "r"(a), "r"(c) : "memory")
#define FENCE_ASYNC()   asm volatile("fence.proxy.async.shared::cta;" ::: "memory")
#define MBAR_EXPECT(a, bytes) \
    asm volatile("mbarrier.arrive.expect_tx.shared.b64 _, [%0], %1;" :: "r"(a), "r"(bytes) : "memory")

__device__ __forceinline__ void mbar_wait(uint32_t a, uint32_t ph) {
    asm volatile(
        "{\n\t.reg .pred P;\n\t"
        "WL%=:\n\tmbarrier.try_wait.parity.acquire.cta.shared::cta.b64 P, [%0], %1, 0x989680;\n\t"
        "@P bra WD%=;\n\tbra WL%=;\n\tWD%=:\n\t}"
        :: "r"(a), "r"(ph) : "memory");
}

__device__ __forceinline__ void tma2d(uint32_t dst, const CUtensorMap* m, int x, int y, uint32_t mbar) {
    asm volatile(
        "cp.async.bulk.tensor.2d.shared::cta.global.tile.mbarrier::complete_tx::bytes "
        "[%0], [%1, {%2, %3}], [%4];"
        :: "r"(dst), "l"(m), "r"(x), "r"(y), "r"(mbar) : "memory");
}

template<int NG, int NN>
__global__ void __launch_bounds__(512, 1)
k_mmt(const __grid_constant__ CUtensorMap tAh,
      const __grid_constant__ CUtensorMap tAl,
      const __grid_constant__ CUtensorMap tBq,
      const float* __restrict__ Bs, float* __restrict__ C,
      int Nw, int Nlim, int K)
{
    extern __shared__ __align__(1024) uint8_t sh8[];
    float* ss = (float*)(sh8 + SSB_OFF);
    const uint32_t sb = s2u(sh8);
    const uint32_t mb = sb + MB_OFF;
    const int tid  = threadIdx.x;
    const int lane = tid & 31;
    const int wid  = tid >> 5;

    // stripe-swizzled rasterization: 8 m-tiles per stripe, n innermost
    const int L = blockIdx.x;
    const int per = 8 * NN;
    const int stripe = L / per;
    const int r = L % per;
    const int m0 = (stripe * 8 + (r % 8)) * 128;
    const int n0 = (r / 8) * 128;

    const int mw = (wid >> 2) * 32;
    const int nw = (wid & 3) * 32;

    if (tid == 0) {
        MBAR_INIT(mb + 0, 1);
        MBAR_INIT(mb + 8, 1);
        MBAR_INIT(mb + 16, 1);
    }
    for (int idx = tid; idx < 128 * NG; idx += 512) {
        int g = idx >> 7, nl = idx & 127;
        ss[g * 132 + nl] = Bs[(size_t)(n0 + nl) * NG + g];
    }
    __syncthreads();

    const int NK = K >> 6;

#define TFILL(buf, kc) do {                                   \
        uint32_t mba = mb + (buf) * 8;                        \
        MBAR_EXPECT(mba, 3 * TILE_B);                         \
        uint32_t d = sb + (buf) * STAGE_B;                    \
        tma2d(d,             &tAh, (kc) * 64, m0, mba);       \
        tma2d(d + TILE_B,    &tAl, (kc) * 64, m0, mba);       \
        tma2d(d + 2*TILE_B,  &tBq, (kc) * 64, n0, mba);       \
    } while (0)

    if (tid == 0) {
        FENCE_ASYNC();
        TFILL(0, 0);
        TFILL(1, 1);
    }

    float acc[2][4][4];
#pragma unroll
    for (int i = 0; i < 2; i++)
#pragma unroll
        for (int j = 0; j < 4; j++)
#pragma unroll
            for (int k = 0; k < 4; k++) acc[i][j][k] = 0.f;

    const int rowoff = (lane & 7) + ((lane >> 3) & 1) * 8;
    const int colb2  = (lane >> 4) * 16;
    const int c0 = (lane & 3) * 2;

    for (int g = 0; g < NG; g++) {
        float accg[2][4][4];
#pragma unroll
        for (int i = 0; i < 2; i++)
#pragma unroll
            for (int j = 0; j < 4; j++)
#pragma unroll
                for (int k = 0; k < 4; k++) accg[i][j][k] = 0.f;

#pragma unroll
        for (int kq = 0; kq < 2; kq++) {
            const int kc = g * 2 + kq;
            const int buf = kc % 3;
            const uint32_t ph = (kc / 3) & 1;

            mbar_wait(mb + buf * 8, ph);
            __syncthreads();

            if (tid == 0 && kc + 2 < NK) {
                FENCE_ASYNC();
                TFILL((kc + 2) % 3, kc + 2);
            }

            const uint32_t stg = sb + buf * STAGE_B;
#pragma unroll
            for (int kk = 0; kk < 4; kk++) {
                uint32_t afr[2][2][4];
                uint32_t bfr[2][4];
#pragma unroll
                for (int hl = 0; hl < 2; hl++)
#pragma unroll
                    for (int mi = 0; mi < 2; mi++) {
                        uint32_t off = (uint32_t)(mw + mi * 16 + rowoff) * 128 + kk * 32 + colb2;
                        uint32_t a = stg + hl * TILE_B + SWZ(off);
                        LDSM4(afr[hl][mi][0], afr[hl][mi][1], afr[hl][mi][2], afr[hl][mi][3], a);
                    }
#pragma unroll
                for (int nj = 0; nj < 2; nj++) {
                    uint32_t off = (uint32_t)(nw + nj * 16 + rowoff) * 128 + kk * 32 + colb2;
                    uint32_t a = stg + 2 * TILE_B + SWZ(off);
                    LDSM4(bfr[nj][0], bfr[nj][1], bfr[nj][2], bfr[nj][3], a);
                }
#pragma unroll
                for (int term = 0; term < 2; term++)
#pragma unroll
                    for (int mi = 0; mi < 2; mi++)
#pragma unroll
                        for (int ni = 0; ni < 4; ni++) {
                            int nj = ni >> 1, s = ni & 1;
                            MMA16816(accg[mi][ni], afr[term][mi],
                                     bfr[nj][s], bfr[nj][s + 2]);
                        }
            }
        }

#pragma unroll
        for (int ni = 0; ni < 4; ni++) {
            float2 sv = *(const float2*)&ss[g * 132 + nw + ni * 8 + c0];
#pragma unroll
            for (int mi = 0; mi < 2; mi++) {
                acc[mi][ni][0] = fmaf(sv.x, accg[mi][ni][0], acc[mi][ni][0]);
                acc[mi][ni][1] = fmaf(sv.y, accg[mi][ni][1], acc[mi][ni][1]);
                acc[mi][ni][2] = fmaf(sv.x, accg[mi][ni][2], acc[mi][ni][2]);
                acc[mi][ni][3] = fmaf(sv.y, accg[mi][ni][3], acc[mi][ni][3]);
            }
        }
    }

    const int r0 = lane >> 2;
#pragma unroll
    for (int mi = 0; mi < 2; mi++) {
#pragma unroll
        for (int ni = 0; ni < 4; ni++) {
            int m = m0 + mw + mi * 16 + r0;
            int n = n0 + nw + ni * 8 + c0;
            if (n < Nlim) {
                *(float2*)&C[(size_t)m * Nw + n]       = make_float2(acc[mi][ni][0], acc[mi][ni][1]);
                *(float2*)&C[(size_t)(m + 8) * Nw + n] = make_float2(acc[mi][ni][2], acc[mi][ni][3]);
            }
        }
    }
#undef TFILL
}

// ---------------- fq4 dequantization -> q (bf16, exact) + group scale ----------------
__global__ void k_dequantq(const float* __restrict__ src, __nv_bfloat16* __restrict__ dq,
                           float* __restrict__ ds, int ngroups)
{
    int g = blockIdx.x * 4 + (threadIdx.x >> 5);
    if (g >= ngroups) return;
    int lane = threadIdx.x & 31;
    const float* s = src + (size_t)g * 128;
    float v[4];
    float m = 0.f;
#pragma unroll
    for (int i = 0; i < 4; i++) { v[i] = s[lane + 32*i]; m = fmaxf(m, fabsf(v[i])); }
#pragma unroll
    for (int o = 16; o; o >>= 1) m = fmaxf(m, __shfl_xor_sync(0xffffffffu, m, o));
    float scale = fmaxf(m, 1e-10f) / 7.0f;
    if (lane == 0) ds[g] = scale;
#pragma unroll
    for (int i = 0; i < 4; i++) {
        float q = rintf(v[i] / scale);
        q = fminf(fmaxf(q, -8.f), 7.f);
        dq[(size_t)g * 128 + lane + 32*i] = __float2bfloat16(q);
    }
}

// ---------------- split fp32 -> bf16 hi/lo ----------------
__global__ void k_split(const float* __restrict__ src, __nv_bfloat16* __restrict__ dh,
                        __nv_bfloat16* __restrict__ dl)
{
    size_t i = ((size_t)blockIdx.x * 256 + threadIdx.x) * 4;
    float4 v = *(const float4*)(src + i);
    float vv[4] = {v.x, v.y, v.z, v.w};
#pragma unroll
    for (int k = 0; k < 4; k++) {
        __nv_bfloat16 h = __float2bfloat16(vv[k]);
        dh[i + k] = h;
        dl[i + k] = __float2bfloat16(vv[k] - __bfloat162float(h));
    }
}

// ---------------- pointwise epilogue per (b,l) row: 64 threads ----------------
__global__ void k_point(const float* __restrict__ Bb, const float* __restrict__ Cb,
                        const float* __restrict__ Alog, const float* __restrict__ dtb)
{
    int row = blockIdx.x;
    int t = threadIdx.x;
    const float* pr = g_P + (size_t)row * NPROJ;
    __shared__ float red[6];

    float dtr = pr[OFF_DT + t] + dtb[t];
    float dt = (dtr > 20.f) ? dtr : log1pf(expf(dtr));
    float Ad = -expf(Alog[t]) * dt;
    float lam = 1.f / (1.f + expf(-pr[OFF_LAM + t]));
    g_Ad[row*64 + t] = Ad;
    g_ga[row*64 + t] = lam * dt;
    g_be[row*64 + t] = (1.f - lam) * dt * expf(Ad);

    float bv = pr[OFF_B + t];
    float cv = pr[OFF_C + t];

    float s0 = dt, s1 = bv*bv, s2 = cv*cv;
#pragma unroll
    for (int o = 16; o; o >>= 1) {
        s0 += __shfl_xor_sync(0xffffffffu, s0, o);
        s1 += __shfl_xor_sync(0xffffffffu, s1, o);
        s2 += __shfl_xor_sync(0xffffffffu, s2, o);
    }
    int w = t >> 5;
    if ((t & 31) == 0) { red[w*3+0] = s0; red[w*3+1] = s1; red[w*3+2] = s2; }
    __syncthreads();
    float dt_avg = (red[0] + red[3]) * (1.f/64.f);
    float rb = rsqrtf((red[1] + red[4]) * (1.f/64.f) + RMS_EPS);
    float rc = rsqrtf((red[2] + red[5]) * (1.f/64.f) + RMS_EPS);

    g_Bv[row*64 + t] = bv * rb + Bb[t];
    g_Cv[row*64 + t] = cv * rc + Cb[t];
    if (t < 32) g_td[row*32 + t] = pr[OFF_TH + t] * dt_avg;
}

// ---------------- cumsum of theta*dt_avg over L per (b, n) ----------------
__global__ void k_scan()
{
    int b = blockIdx.x >> 5;
    int n = blockIdx.x & 31;
    int tid = threadIdx.x;
    __shared__ float ps[256];
    float loc[16];
    float run = 0.f;
    int base = (b*SEQ + tid*16) * 32 + n;
#pragma unroll
    for (int j = 0; j < 16; j++) { run += g_td[base + j*32]; loc[j] = run; }
    ps[tid] = run;
    __syncthreads();
#pragma unroll
    for (int o = 1; o < 256; o <<= 1) {
        float v = (tid >= o) ? ps[tid - o] : 0.f;
        __syncthreads();
        ps[tid] += v;
        __syncthreads();
    }
    float off = (tid > 0) ? ps[tid - 1] : 0.f;
#pragma unroll
    for (int j = 0; j < 16; j++) g_td[base + j*32] = loc[j] + off;
}

// ---------------- rope on B and C (in place) ----------------
__global__ void k_rope()
{
    int row = blockIdx.x;
    int t = threadIdx.x;
    float a = g_td[row*32 + t];
    float ca = cosf(a), sa = sinf(a);
    float br = g_Bv[row*64 + t], bi = g_Bv[row*64 + 32 + t];
    g_Bv[row*64 + t]      = br*ca - bi*sa;
    g_Bv[row*64 + 32 + t] = br*sa + bi*ca;
    float cr = g_Cv[row*64 + t], ci = g_Cv[row*64 + 32 + t];
    g_Cv[row*64 + t]      = cr*ca - ci*sa;
    g_Cv[row*64 + 32 + t] = cr*sa + ci*ca;
}

// ---------------- intra-chunk: Y_diag + per-chunk states (R10 FFMA version) ----------------
#define SM_CHUNK_BYTES ((4352*5 + 128) * 4)
__launch_bounds__(256)
__global__ void k_chunk()
{
    extern __shared__ float sm[];
    float* sX  = sm;
    float* sB  = sm + 4352;
    float* sBT = sm + 8704;
    float* sCT = sm + 13056;
    float* sGT = sm + 17408;
    float* sA  = sm + 21760;
    float* sW  = sm + 21824;

    const int h = blockIdx.x, c = blockIdx.y, b = blockIdx.z;
    const int tid = threadIdx.x;

    if (tid < 64) {
        int row_g = b*SEQ + c*64 + tid;
        sA[tid] = g_Ad[row_g*64 + h];
    }
    __syncthreads();
#pragma unroll
    for (int o = 1; o < 64; o <<= 1) {
        float v = (tid < 64 && tid >= o) ? sA[tid - o] : 0.f;
        __syncthreads();
        if (tid < 64) sA[tid] += v;
        __syncthreads();
    }
    float Alast = sA[63];
    if (tid < 64) {
        sW[tid] = expf(Alast - sA[tid]);
        g_eA[((b*NCHUNK + c)*NHEADS + h)*64 + tid] = expf(sA[tid]);
    }
    if (tid == 0) g_cd[(b*NCHUNK + c)*NHEADS + h] = expf(Alast);

#pragma unroll
    for (int it = 0; it < 4; it++) {
        int idx = tid + it*256;
        int l = idx >> 4;
        int p4 = (idx & 15) << 2;
        int row_g = b*SEQ + c*64 + l;
        const float* xp = g_P + (size_t)row_g*NPROJ + OFF_XC + h*64 + p4;
        float4 xc = *(const float4*)xp;
        float ga = g_ga[row_g*64 + h];
        float be = g_be[row_g*64 + h];
        float4 xv;
        xv.x = siluf(xc.x)*ga; xv.y = siluf(xc.y)*ga; xv.z = siluf(xc.z)*ga; xv.w = siluf(xc.w)*ga;
        if (c*64 + l > 0) {
            float4 xq = *(const float4*)(xp - NPROJ);
            xv.x += siluf(xq.x)*be; xv.y += siluf(xq.y)*be; xv.z += siluf(xq.z)*be; xv.w += siluf(xq.w)*be;
        }
        *(float4*)&sX[l*68 + p4] = xv;
        float4 bb = *(const float4*)&g_Bv[row_g*64 + p4];
        *(float4*)&sB[l*68 + p4] = bb;
        sBT[(p4+0)*68 + l] = bb.x; sBT[(p4+1)*68 + l] = bb.y;
        sBT[(p4+2)*68 + l] = bb.z; sBT[(p4+3)*68 + l] = bb.w;
        float4 cc = *(const float4*)&g_Cv[row_g*64 + p4];
        sCT[(p4+0)*68 + l] = cc.x; sCT[(p4+1)*68 + l] = cc.y;
        sCT[(p4+2)*68 + l] = cc.z; sCT[(p4+3)*68 + l] = cc.w;
    }
    __syncthreads();

    const int ti = tid >> 4, tj = tid & 15;

    if (tj <= ti) {
        const int l0 = ti*4, s0 = tj*4;
        float acc[4][4];
#pragma unroll
        for (int i = 0; i < 4; i++)
#pragma unroll
            for (int j = 0; j < 4; j++) acc[i][j] = 0.f;
#pragma unroll
        for (int n = 0; n < 64; n++) {
            float4 cl = *(const float4*)&sCT[n*68 + l0];
            float4 bs = *(const float4*)&sBT[n*68 + s0];
            float clv[4] = {cl.x, cl.y, cl.z, cl.w};
            float bsv[4] = {bs.x, bs.y, bs.z, bs.w};
#pragma unroll
            for (int i = 0; i < 4; i++)
#pragma unroll
                for (int j = 0; j < 4; j++)
                    acc[i][j] = fmaf(clv[i], bsv[j], acc[i][j]);
        }
        float al[4];
#pragma unroll
        for (int i = 0; i < 4; i++) al[i] = sA[l0 + i];
#pragma unroll
        for (int j = 0; j < 4; j++) {
            int s = s0 + j;
            float as = sA[s];
#pragma unroll
            for (int i = 0; i < 4; i++) {
                int l = l0 + i;
                sGT[s*68 + l] = (s <= l) ? acc[i][j] * expf(al[i] - as) : 0.f;
            }
        }
    }
    __syncthreads();

    {
        const int l0 = ti*4, p0 = tj*4;
        float acc[4][4];
#pragma unroll
        for (int i = 0; i < 4; i++)
#pragma unroll
            for (int j = 0; j < 4; j++) acc[i][j] = 0.f;
        const int smax = l0 + 4;
#pragma unroll 4
        for (int s = 0; s < smax; s++) {
            float4 gt = *(const float4*)&sGT[s*68 + l0];
            float4 xr = *(const float4*)&sX[s*68 + p0];
            float gv[4] = {gt.x, gt.y, gt.z, gt.w};
            float xvv[4] = {xr.x, xr.y, xr.z, xr.w};
#pragma unroll
            for (int i = 0; i < 4; i++)
#pragma unroll
                for (int j = 0; j < 4; j++)
                    acc[i][j] = fmaf(gv[i], xvv[j], acc[i][j]);
        }
#pragma unroll
        for (int i = 0; i < 4; i++) {
            int row_g = b*SEQ + c*64 + l0 + i;
            *(float4*)&g_Y[(size_t)row_g*D_INNER + h*64 + p0] =
                make_float4(acc[i][0], acc[i][1], acc[i][2], acc[i][3]);
        }
    }

    {
        const int p0 = ti*4, n0 = tj*4;
        float acc[4][4];
#pragma unroll
        for (int i = 0; i < 4; i++)
#pragma unroll
            for (int j = 0; j < 4; j++) acc[i][j] = 0.f;
#pragma unroll
        for (int l = 0; l < 64; l++) {
            float w = sW[l];
            float4 xr = *(const float4*)&sX[l*68 + p0];
            float4 br = *(const float4*)&sB[l*68 + n0];
            float wx[4] = {w*xr.x, w*xr.y, w*xr.z, w*xr.w};
            float bvv[4] = {br.x, br.y, br.z, br.w};
#pragma unroll
            for (int i = 0; i < 4; i++)
#pragma unroll
                for (int j = 0; j < 4; j++)
                    acc[i][j] = fmaf(wx[i], bvv[j], acc[i][j]);
        }
        size_t base = (size_t)((b*NCHUNK + c)*NHEADS + h) * 4096;
#pragma unroll
        for (int i = 0; i < 4; i++)
            *(float4*)&g_S[base + (p0 + i)*64 + n0] =
                make_float4(acc[i][0], acc[i][1], acc[i][2], acc[i][3]);
    }
}

// ---------------- inter-chunk scan: 512 CTAs ----------------
__global__ void k_cscan()
{
    int q = blockIdx.x & 3;
    int h = (blockIdx.x >> 2) & 63;
    int b = blockIdx.x >> 8;
    int tid = threadIdx.x;
    int off = q * 1024 + tid * 4;
    float s0 = 0.f, s1 = 0.f, s2 = 0.f, s3 = 0.f;
    const float* cdp = g_cd + b * NCHUNK * NHEADS + h;
    for (int c = 0; c < NCHUNK; c++) {
        size_t base = ((size_t)((b*NCHUNK + c)*NHEADS + h) << 12) + off;
        float cd = cdp[c * NHEADS];
        float4 t = *(const float4*)&g_S[base];
        *(float4*)&g_S[base] = make_float4(s0, s1, s2, s3);
        s0 = fmaf(cd, s0, t.x);
        s1 = fmaf(cd, s1, t.y);
        s2 = fmaf(cd, s2, t.z);
        s3 = fmaf(cd, s3, t.w);
    }
}

// ---------------- Y_off + D skip + z gating (R10 FFMA version) ----------------
__launch_bounds__(256)
__global__ void k_off(const float* __restrict__ Dp)
{
    __shared__ float sST[64*68];
    __shared__ float sCT[64*68];
    const int h = blockIdx.x, c = blockIdx.y, b = blockIdx.z;
    const int tid = threadIdx.x;
    size_t sbase = (size_t)((b*NCHUNK + c)*NHEADS + h) * 4096;
#pragma unroll
    for (int it = 0; it < 4; it++) {
        int idx = tid + it*256;
        int r = idx >> 4;
        int n4 = (idx & 15) << 2;
        float4 sv = *(const float4*)&g_S[sbase + r*64 + n4];
        sST[(n4+0)*68 + r] = sv.x; sST[(n4+1)*68 + r] = sv.y;
        sST[(n4+2)*68 + r] = sv.z; sST[(n4+3)*68 + r] = sv.w;
        int row_g = b*SEQ + c*64 + r;
        float4 cv = *(const float4*)&g_Cv[row_g*64 + n4];
        sCT[(n4+0)*68 + r] = cv.x; sCT[(n4+1)*68 + r] = cv.y;
        sCT[(n4+2)*68 + r] = cv.z; sCT[(n4+3)*68 + r] = cv.w;
    }
    __syncthreads();
    const int ti = tid >> 4, tj = tid & 15;
    const int l0 = ti*4, p0 = tj*4;
    float acc[4][4];
#pragma unroll
    for (int i = 0; i < 4; i++)
#pragma unroll
        for (int j = 0; j < 4; j++) acc[i][j] = 0.f;
#pragma unroll
    for (int n = 0; n < 64; n++) {
        float4 cl = *(const float4*)&sCT[n*68 + l0];
        float4 sp = *(const float4*)&sST[n*68 + p0];
        float clv[4] = {cl.x, cl.y, cl.z, cl.w};
        float spv[4] = {sp.x, sp.y, sp.z, sp.w};
#pragma unroll
        for (int i = 0; i < 4; i++)
#pragma unroll
            for (int j = 0; j < 4; j++)
                acc[i][j] = fmaf(clv[i], spv[j], acc[i][j]);
    }
    float Dh = Dp[h];
#pragma unroll
    for (int i = 0; i < 4; i++) {
        int l = l0 + i;
        int row_g = b*SEQ + c*64 + l;
        float e = g_eA[((b*NCHUNK + c)*NHEADS + h)*64 + l];
        const float* pr = g_P + (size_t)row_g*NPROJ;
        float4 xc = *(const float4*)&pr[OFF_XC + h*64 + p0];
        float4 zz = *(const float4*)&pr[OFF_Z  + h*64 + p0];
        float* yp = &g_Y[(size_t)row_g*D_INNER + h*64 + p0];
        float4 yd = *(const float4*)yp;
        float4 o;
        o.x = (yd.x + e*acc[i][0] + Dh*siluf(xc.x)) * siluf(zz.x);
        o.y = (yd.y + e*acc[i][1] + Dh*siluf(xc.y)) * siluf(zz.y);
        o.z = (yd.z + e*acc[i][2] + Dh*siluf(xc.z)) * siluf(zz.z);
        o.w = (yd.w + e*acc[i][3] + Dh*siluf(xc.w)) * siluf(zz.w);
        *(float4*)yp = o;
    }
}

// ---------------- rmsnorm over 4096 per row -> bf16 hi/lo ----------------
__global__ void k_rms()
{
    int row = blockIdx.x;
    int tid = threadIdx.x;
    const float* Yp = g_Y + (size_t)row * D_INNER;
    float4 v[4];
    float ss = 0.f;
#pragma unroll
    for (int i = 0; i < 4; i++) {
        v[i] = *(const float4*)&Yp[tid*16 + i*4];
        ss += v[i].x*v[i].x + v[i].y*v[i].y + v[i].z*v[i].z + v[i].w*v[i].w;
    }
#pragma unroll
    for (int o = 16; o; o >>= 1) ss += __shfl_xor_sync(0xffffffffu, ss, o);
    __shared__ float red[8];
    if ((tid & 31) == 0) red[tid >> 5] = ss;
    __syncthreads();
    float tot = 0.f;
#pragma unroll
    for (int i = 0; i < 8; i++) tot += red[i];
    float r = rsqrtf(tot * (1.f/4096.f) + RMS_EPS);
    size_t base = (size_t)row * D_INNER + tid*16;
#pragma unroll
    for (int i = 0; i < 4; i++) {
        float vv[4] = {v[i].x*r, v[i].y*r, v[i].z*r, v[i].w*r};
#pragma unroll
        for (int k = 0; k < 4; k++) {
            __nv_bfloat16 h = __float2bfloat16(vv[k]);
            g_Yh[base + i*4 + k] = h;
            g_Yl[base + i*4 + k] = __float2bfloat16(vv[k] - __bfloat162float(h));
        }
    }
}

// ---------------- host: tensormap construction ----------------
typedef CUresult (*PFN_encodeTiled)(
    CUtensorMap*, CUtensorMapDataType, cuuint32_t, void*,
    const cuuint64_t*, const cuuint64_t*, const cuuint32_t*, const cuuint32_t*,
    CUtensorMapInterleave, CUtensorMapSwizzle, CUtensorMapL2promotion, CUtensorMapFloatOOBfill);

static void mk2d(PFN_encodeTiled enc, CUtensorMap* m, void* ptr, uint64_t k, uint64_t rows)
{
    cuuint64_t dims[2]    = {k, rows};
    cuuint64_t strides[1] = {k * 2};
    cuuint32_t box[2]     = {64, 128};
    cuuint32_t es[2]      = {1, 1};
    enc(m, CU_TENSOR_MAP_DATA_TYPE_BFLOAT16, 2, ptr, dims, strides, box, es,
        CU_TENSOR_MAP_INTERLEAVE_NONE, CU_TENSOR_MAP_SWIZZLE_128B,
        CU_TENSOR_MAP_L2_PROMOTION_L2_128B, CU_TENSOR_MAP_FLOAT_OOB_FILL_NONE);
}

// ---------------- launcher ----------------
extern "C" void kernel_launch(void* const* d_in, const int* in_sizes, int n_in,
                              void* d_out, int out_size)
{
    const float* x    = (const float*)d_in[0];
    const float* Win  = (const float*)d_in[1];
    const float* Wth  = (const float*)d_in[2];
    const float* Wla  = (const float*)d_in[3];
    const float* Wout = (const float*)d_in[4];
    const float* Bb   = (const float*)d_in[5];
    const float* Cb   = (const float*)d_in[6];
    const float* Alog = (const float*)d_in[7];
    const float* Dp   = (const float*)d_in[8];
    const float* dtb  = (const float*)d_in[9];
    float* out = (float*)d_out;

    __nv_bfloat16 *pWq, *pWoq, *pxh, *pxl, *pYh, *pYl;
    float *pWs, *pWos, *pP;
    cudaGetSymbolAddress((void**)&pWq,  g_Wq);
    cudaGetSymbolAddress((void**)&pWs,  g_Ws);
    cudaGetSymbolAddress((void**)&pWoq, g_Woq);
    cudaGetSymbolAddress((void**)&pWos, g_Wos);
    cudaGetSymbolAddress((void**)&pxh,  g_xh);
    cudaGetSymbolAddress((void**)&pxl,  g_xl);
    cudaGetSymbolAddress((void**)&pYh,  g_Yh);
    cudaGetSymbolAddress((void**)&pYl,  g_Yl);
    cudaGetSymbolAddress((void**)&pP,   g_P);

    PFN_encodeTiled enc = nullptr;
    {
        void* fp = nullptr;
        cudaDriverEntryPointQueryResult qr;
        cudaGetDriverEntryPoint("cuTensorMapEncodeTiled", &fp, cudaEnableDefault, &qr);
        enc = (PFN_encodeTiled)fp;
    }
    CUtensorMap t1Ah, t1Al, t1Bq, t2Ah, t2Al, t2Bq;
    mk2d(enc, &t1Ah, pxh,  DIMK,    ROWS);
    mk2d(enc, &t1Al, pxl,  DIMK,    ROWS);
    mk2d(enc, &t1Bq, pWq,  DIMK,    NPROJ_PAD);
    mk2d(enc, &t2Ah, pYh,  D_INNER, ROWS);
    mk2d(enc, &t2Al, pYl,  D_INNER, ROWS);
    mk2d(enc, &t2Bq, pWoq, D_INNER, DIMK);

    const int smem1 = SSB_OFF + 16 * 132 * 4;
    const int smem2 = SSB_OFF + 32 * 132 * 4;

    cudaFuncSetAttribute(k_chunk,        cudaFuncAttributeMaxDynamicSharedMemorySize, SM_CHUNK_BYTES);
    cudaFuncSetAttribute((k_mmt<16,67>), cudaFuncAttributeMaxDynamicSharedMemorySize, smem1);
    cudaFuncSetAttribute((k_mmt<32,16>), cudaFuncAttributeMaxDynamicSharedMemorySize, smem2);

    k_dequantq<<<(8384*16 + 3)/4, 128>>>(Win, pWq, pWs, 8384*16);
    k_dequantq<<<(512 + 3)/4,    128>>>(Wth, pWq + (size_t)8384*DIMK, pWs + (size_t)8384*16, 512);
    k_dequantq<<<(1024 + 3)/4,   128>>>(Wla, pWq + (size_t)8416*DIMK, pWs + (size_t)8416*16, 1024);
    k_dequantq<<<65536/4,        128>>>(Wout, pWoq, pWos, 65536);

    k_split<<<ROWS*DIMK/1024, 256>>>(x, pxh, pxl);

    // in-projection GEMM: stripe-swizzled 1-D grid (64 m-tiles x 67 n-tiles)
    k_mmt<16,67><<<64*67, 512, smem1>>>(
        t1Ah, t1Al, t1Bq, pWs, pP, NPROJ, NPROJ, DIMK);

    k_point<<<ROWS, 64>>>(Bb, Cb, Alog, dtb);
    k_scan <<<64, 256>>>();
    k_rope <<<ROWS, 32>>>();

    k_chunk<<<dim3(NHEADS, NCHUNK, BATCH), 256, SM_CHUNK_BYTES>>>();
    k_cscan<<<512, 256>>>();
    k_off  <<<dim3(NHEADS, NCHUNK, BATCH), 256>>>(Dp);

    k_rms<<<ROWS, 256>>>();

    // out-projection GEMM: stripe-swizzled 1-D grid (64 m-tiles x 16 n-tiles)
    k_mmt<32,16><<<64*16, 512, smem2>>>(
        t2Ah, t2Al, t2Bq, pWos, out, DIMK, DIMK, D_INNER);
}

// round 14
// speedup vs baseline: 1.1460x; 1.0268x over previous
#include <cuda.h>
#include <cuda_runtime.h>
#include <cuda_bf16.h>
#include <math.h>
#include <stdint.h>

#define SEQ     4096
#define BATCH   2
#define ROWS    (BATCH*SEQ)     // 8192
#define DIMK    2048
#define D_INNER 4096
#define NHEADS  64
#define NPROJ   8480
#define NPROJ_PAD 8576          // 67 * 128
#define OFF_Z   0
#define OFF_XC  4096
#define OFF_B   8192
#define OFF_C   8256
#define OFF_DT  8320
#define OFF_TH  8384
#define OFF_LAM 8416
#define NCHUNK  64
#define RMS_EPS 1.1920929e-07f

// ---------------- device scratch (no allocation allowed) ----------------
__device__ __nv_bfloat16 g_Wq [NPROJ_PAD * DIMK];
__device__ float         g_Ws [NPROJ_PAD * 16];
__device__ __nv_bfloat16 g_Woq[DIMK * D_INNER];
__device__ float         g_Wos[DIMK * 32];
__device__ __nv_bfloat16 g_xh [ROWS * DIMK];
__device__ __nv_bfloat16 g_xl [ROWS * DIMK];
__device__ __nv_bfloat16 g_Yh [ROWS * D_INNER];
__device__ __nv_bfloat16 g_Yl [ROWS * D_INNER];
__device__ float g_P [ROWS * NPROJ];
__device__ float g_Bv[ROWS * 64];
__device__ float g_Cv[ROWS * 64];
__device__ float g_Ad[ROWS * 64];
__device__ float g_ga[ROWS * 64];
__device__ float g_be[ROWS * 64];
__device__ float g_td[ROWS * 32];
__device__ float g_Y [ROWS * D_INNER];
__device__ float g_S [BATCH * NCHUNK * NHEADS * 64 * 64];
__device__ float g_eA[BATCH * NCHUNK * NHEADS * 64];
__device__ float g_cd[BATCH * NCHUNK * NHEADS];

__device__ __forceinline__ float siluf(float x) { return x / (1.f + expf(-x)); }

__device__ __forceinline__ uint32_t s2u(const void* p) {
    uint32_t a;
    asm("{ .reg .u64 t; cvta.to.shared.u64 t, %1; cvt.u32.u64 %0, t; }" : "=r"(a) : "l"(p));
    return a;
}

// ================= TMA-fed quant-aware emulated-fp32 GEMM =================
// R11 math + producer/consumer empty-mbarrier pipeline (no per-chunk __syncthreads).
#define TILE_B  16384
#define STAGE_B (3*TILE_B)
#define MB_OFF  (3*STAGE_B)            // 147456: full[3] then empty[3] mbarriers
#define SSB_OFF (MB_OFF + 64)

#define SWZ(o) ((o) ^ ((((uint32_t)(o)) >> 3) & 0x70u))

#define LDSM4(r0,r1,r2,r3,a) \
    asm volatile("ldmatrix.sync.aligned.m8n8.x4.shared.b16 {%0,%1,%2,%3}, [%4];" \
        : "=r"(r0),"=r"(r1),"=r"(r2),"=r"(r3) : "r"(a))

#define MMA16816(d,a,b0,b1) \
    asm volatile("mma.sync.aligned.m16n8k16.row.col.f32.bf16.bf16.f32 " \
        "{%0,%1,%2,%3}, {%4,%5,%6,%7}, {%8,%9}, {%0,%1,%2,%3};" \
        : "+f"((d)[0]),"+f"((d)[1]),"+f"((d)[2]),"+f"((d)[3]) \
        : "r"((a)[0]),"r"((a)[1]),"r"((a)[2]),"r"((a)[3]),"r"(b0),"r"(b1))

#define MBAR_INIT(a, c) asm volatile("mbarrier.init.shared.b64 [%0], %1;" :: "r"(a), "r"(c) : "memory")
#define FENCE_ASYNC()   asm volatile("fence.proxy.async.shared::cta;" ::: "memory")
#define MBAR_EXPECT(a, bytes) \
    asm volatile("mbarrier.arrive.expect_tx.shared.b64 _, [%0], %1;" :: "r"(a), "r"(bytes) : "memory")
#define MBAR_ARRIVE(a) \
    asm volatile("mbarrier.arrive.release.cta.shared::cta.b64 _, [%0];" :: "r"(a) : "memory")

__device__ __forceinline__ void mbar_wait(uint32_t a, uint32_t ph) {
    asm volatile(
        "{\n\t.reg .pred P;\n\t"
        "WL%=:\n\tmbarrier.try_wait.parity.acquire.cta.shared::cta.b64 P, [%0], %1, 0x989680;\n\t"
        "@P bra WD%=;\n\tbra WL%=;\n\tWD%=:\n\t}"
        :: "r"(a), "r"(ph) : "memory");
}

__device__ __forceinline__ void tma2d(uint32_t dst, const CUtensorMap* m, int x, int y, uint32_t mbar) {
    asm volatile(
        "cp.async.bulk.tensor.2d.shared::cta.global.tile.mbarrier::complete_tx::bytes "
        "[%0], [%1, {%2, %3}], [%4];"
        :: "r"(dst), "l"(m), "r"(x), "r"(y), "r"(mbar) : "memory");
}

template<int NG>
__global__ void __launch_bounds__(512, 1)
k_mmt(const __grid_constant__ CUtensorMap tAh,
      const __grid_constant__ CUtensorMap tAl,
      const __grid_constant__ CUtensorMap tBq,
      const float* __restrict__ Bs, float* __restrict__ C,
      int Nw, int Nlim, int K)
{
    extern __shared__ __align__(1024) uint8_t sh8[];
    float* ss = (float*)(sh8 + SSB_OFF);
    const uint32_t sb = s2u(sh8);
    const uint32_t mb = sb + MB_OFF;        // full[0..2] at +0/8/16, empty[0..2] at +24/32/40
    const int tid  = threadIdx.x;
    const int lane = tid & 31;
    const int wid  = tid >> 5;
    const int m0 = blockIdx.x * 128;
    const int n0 = blockIdx.y * 128;
    const int mw = (wid >> 2) * 32;
    const int nw = (wid & 3) * 32;

    if (tid == 0) {
        MBAR_INIT(mb + 0, 1);
        MBAR_INIT(mb + 8, 1);
        MBAR_INIT(mb + 16, 1);
        MBAR_INIT(mb + 24, 16);
        MBAR_INIT(mb + 32, 16);
        MBAR_INIT(mb + 40, 16);
    }
    for (int idx = tid; idx < 128 * NG; idx += 512) {
        int g = idx >> 7, nl = idx & 127;
        ss[g * 132 + nl] = Bs[(size_t)(n0 + nl) * NG + g];
    }
    __syncthreads();

    const int NK = K >> 6;

#define TFILL(buf, kc) do {                                   \
        uint32_t mba = mb + (buf) * 8;                        \
        MBAR_EXPECT(mba, 3 * TILE_B);                         \
        uint32_t d = sb + (buf) * STAGE_B;                    \
        tma2d(d,             &tAh, (kc) * 64, m0, mba);       \
        tma2d(d + TILE_B,    &tAl, (kc) * 64, m0, mba);       \
        tma2d(d + 2*TILE_B,  &tBq, (kc) * 64, n0, mba);       \
    } while (0)

    // prologue: fill stages 0,1; every warp pre-arrives on all empty barriers
    if (tid == 0) {
        FENCE_ASYNC();
        TFILL(0, 0);
        TFILL(1, 1);
    }
    if (lane == 0) {
        MBAR_ARRIVE(mb + 24);
        MBAR_ARRIVE(mb + 32);
        MBAR_ARRIVE(mb + 40);
    }

    float acc[2][4][4];
#pragma unroll
    for (int i = 0; i < 2; i++)
#pragma unroll
        for (int j = 0; j < 4; j++)
#pragma unroll
            for (int k = 0; k < 4; k++) acc[i][j][k] = 0.f;

    const int rowoff = (lane & 7) + ((lane >> 3) & 1) * 8;
    const int colb2  = (lane >> 4) * 16;
    const int c0 = (lane & 3) * 2;

    for (int g = 0; g < NG; g++) {
        float accg[2][4][4];
#pragma unroll
        for (int i = 0; i < 2; i++)
#pragma unroll
            for (int j = 0; j < 4; j++)
#pragma unroll
                for (int k = 0; k < 4; k++) accg[i][j][k] = 0.f;

#pragma unroll
        for (int kq = 0; kq < 2; kq++) {
            const int kc = g * 2 + kq;
            const int buf = kc % 3;

            // data ready?
            mbar_wait(mb + buf * 8, (kc / 3) & 1);

            // producer: refill stage (kc+2)%3 once all warps have released it
            if (tid == 0 && kc + 2 < NK) {
                const int tbuf = (kc + 2) % 3;
                mbar_wait(mb + 24 + tbuf * 8, ((kc + 2) / 3) & 1);
                FENCE_ASYNC();
                TFILL(tbuf, kc + 2);
            }

            const uint32_t stg = sb + buf * STAGE_B;
#pragma unroll
            for (int kk = 0; kk < 4; kk++) {
                uint32_t afr[2][2][4];
                uint32_t bfr[2][4];
#pragma unroll
                for (int hl = 0; hl < 2; hl++)
#pragma unroll
                    for (int mi = 0; mi < 2; mi++) {
                        uint32_t off = (uint32_t)(mw + mi * 16 + rowoff) * 128 + kk * 32 + colb2;
                        uint32_t a = stg + hl * TILE_B + SWZ(off);
                        LDSM4(afr[hl][mi][0], afr[hl][mi][1], afr[hl][mi][2], afr[hl][mi][3], a);
                    }
#pragma unroll
                for (int nj = 0; nj < 2; nj++) {
                    uint32_t off = (uint32_t)(nw + nj * 16 + rowoff) * 128 + kk * 32 + colb2;
                    uint32_t a = stg + 2 * TILE_B + SWZ(off);
                    LDSM4(bfr[nj][0], bfr[nj][1], bfr[nj][2], bfr[nj][3], a);
                }
#pragma unroll
                for (int term = 0; term < 2; term++)
#pragma unroll
                    for (int mi = 0; mi < 2; mi++)
#pragma unroll
                        for (int ni = 0; ni < 4; ni++) {
                            int nj = ni >> 1, s = ni & 1;
                            MMA16816(accg[mi][ni], afr[term][mi],
                                     bfr[nj][s], bfr[nj][s + 2]);
                        }
            }

            // this warp is done reading stage buf
            if (lane == 0) MBAR_ARRIVE(mb + 24 + buf * 8);
        }

#pragma unroll
        for (int ni = 0; ni < 4; ni++) {
            float2 sv = *(const float2*)&ss[g * 132 + nw + ni * 8 + c0];
#pragma unroll
            for (int mi = 0; mi < 2; mi++) {
                acc[mi][ni][0] = fmaf(sv.x, accg[mi][ni][0], acc[mi][ni][0]);
                acc[mi][ni][1] = fmaf(sv.y, accg[mi][ni][1], acc[mi][ni][1]);
                acc[mi][ni][2] = fmaf(sv.x, accg[mi][ni][2], acc[mi][ni][2]);
                acc[mi][ni][3] = fmaf(sv.y, accg[mi][ni][3], acc[mi][ni][3]);
            }
        }
    }

    const int r0 = lane >> 2;
#pragma unroll
    for (int mi = 0; mi < 2; mi++) {
#pragma unroll
        for (int ni = 0; ni < 4; ni++) {
            int m = m0 + mw + mi * 16 + r0;
            int n = n0 + nw + ni * 8 + c0;
            if (n < Nlim) {
                *(float2*)&C[(size_t)m * Nw + n]       = make_float2(acc[mi][ni][0], acc[mi][ni][1]);
                *(float2*)&C[(size_t)(m + 8) * Nw + n] = make_float2(acc[mi][ni][2], acc[mi][ni][3]);
            }
        }
    }
#undef TFILL
}

// ---------------- fq4 dequantization -> q (bf16, exact) + group scale ----------------
__global__ void k_dequantq(const float* __restrict__ src, __nv_bfloat16* __restrict__ dq,
                           float* __restrict__ ds, int ngroups)
{
    int g = blockIdx.x * 4 + (threadIdx.x >> 5);
    if (g >= ngroups) return;
    int lane = threadIdx.x & 31;
    const float* s = src + (size_t)g * 128;
    float v[4];
    float m = 0.f;
#pragma unroll
    for (int i = 0; i < 4; i++) { v[i] = s[lane + 32*i]; m = fmaxf(m, fabsf(v[i])); }
#pragma unroll
    for (int o = 16; o; o >>= 1) m = fmaxf(m, __shfl_xor_sync(0xffffffffu, m, o));
    float scale = fmaxf(m, 1e-10f) / 7.0f;
    if (lane == 0) ds[g] = scale;
#pragma unroll
    for (int i = 0; i < 4; i++) {
        float q = rintf(v[i] / scale);
        q = fminf(fmaxf(q, -8.f), 7.f);
        dq[(size_t)g * 128 + lane + 32*i] = __float2bfloat16(q);
    }
}

// ---------------- split fp32 -> bf16 hi/lo ----------------
__global__ void k_split(const float* __restrict__ src, __nv_bfloat16* __restrict__ dh,
                        __nv_bfloat16* __restrict__ dl)
{
    size_t i = ((size_t)blockIdx.x * 256 + threadIdx.x) * 4;
    float4 v = *(const float4*)(src + i);
    float vv[4] = {v.x, v.y, v.z, v.w};
#pragma unroll
    for (int k = 0; k < 4; k++) {
        __nv_bfloat16 h = __float2bfloat16(vv[k]);
        dh[i + k] = h;
        dl[i + k] = __float2bfloat16(vv[k] - __bfloat162float(h));
    }
}

// ---------------- pointwise epilogue per (b,l) row: 64 threads ----------------
__global__ void k_point(const float* __restrict__ Bb, const float* __restrict__ Cb,
                        const float* __restrict__ Alog, const float* __restrict__ dtb)
{
    int row = blockIdx.x;
    int t = threadIdx.x;
    const float* pr = g_P + (size_t)row * NPROJ;
    __shared__ float red[6];

    float dtr = pr[OFF_DT + t] + dtb[t];
    float dt = (dtr > 20.f) ? dtr : log1pf(expf(dtr));
    float Ad = -expf(Alog[t]) * dt;
    float lam = 1.f / (1.f + expf(-pr[OFF_LAM + t]));
    g_Ad[row*64 + t] = Ad;
    g_ga[row*64 + t] = lam * dt;
    g_be[row*64 + t] = (1.f - lam) * dt * expf(Ad);

    float bv = pr[OFF_B + t];
    float cv = pr[OFF_C + t];

    float s0 = dt, s1 = bv*bv, s2 = cv*cv;
#pragma unroll
    for (int o = 16; o; o >>= 1) {
        s0 += __shfl_xor_sync(0xffffffffu, s0, o);
        s1 += __shfl_xor_sync(0xffffffffu, s1, o);
        s2 += __shfl_xor_sync(0xffffffffu, s2, o);
    }
    int w = t >> 5;
    if ((t & 31) == 0) { red[w*3+0] = s0; red[w*3+1] = s1; red[w*3+2] = s2; }
    __syncthreads();
    float dt_avg = (red[0] + red[3]) * (1.f/64.f);
    float rb = rsqrtf((red[1] + red[4]) * (1.f/64.f) + RMS_EPS);
    float rc = rsqrtf((red[2] + red[5]) * (1.f/64.f) + RMS_EPS);

    g_Bv[row*64 + t] = bv * rb + Bb[t];
    g_Cv[row*64 + t] = cv * rc + Cb[t];
    if (t < 32) g_td[row*32 + t] = pr[OFF_TH + t] * dt_avg;
}

// ---------------- cumsum of theta*dt_avg over L per (b, n) ----------------
__global__ void k_scan()
{
    int b = blockIdx.x >> 5;
    int n = blockIdx.x & 31;
    int tid = threadIdx.x;
    __shared__ float ps[256];
    float loc[16];
    float run = 0.f;
    int base = (b*SEQ + tid*16) * 32 + n;
#pragma unroll
    for (int j = 0; j < 16; j++) { run += g_td[base + j*32]; loc[j] = run; }
    ps[tid] = run;
    __syncthreads();
#pragma unroll
    for (int o = 1; o < 256; o <<= 1) {
        float v = (tid >= o) ? ps[tid - o] : 0.f;
        __syncthreads();
        ps[tid] += v;
        __syncthreads();
    }
    float off = (tid > 0) ? ps[tid - 1] : 0.f;
#pragma unroll
    for (int j = 0; j < 16; j++) g_td[base + j*32] = loc[j] + off;
}

// ---------------- rope on B and C (in place) ----------------
__global__ void k_rope()
{
    int row = blockIdx.x;
    int t = threadIdx.x;
    float a = g_td[row*32 + t];
    float ca = cosf(a), sa = sinf(a);
    float br = g_Bv[row*64 + t], bi = g_Bv[row*64 + 32 + t];
    g_Bv[row*64 + t]      = br*ca - bi*sa;
    g_Bv[row*64 + 32 + t] = br*sa + bi*ca;
    float cr = g_Cv[row*64 + t], ci = g_Cv[row*64 + 32 + t];
    g_Cv[row*64 + t]      = cr*ca - ci*sa;
    g_Cv[row*64 + 32 + t] = cr*sa + ci*ca;
}

// ---------------- intra-chunk: Y_diag + per-chunk states (FFMA) ----------------
#define SM_CHUNK_BYTES ((4352*5 + 128) * 4)
__launch_bounds__(256)
__global__ void k_chunk()
{
    extern __shared__ float sm[];
    float* sX  = sm;
    float* sB  = sm + 4352;
    float* sBT = sm + 8704;
    float* sCT = sm + 13056;
    float* sGT = sm + 17408;
    float* sA  = sm + 21760;
    float* sW  = sm + 21824;

    const int h = blockIdx.x, c = blockIdx.y, b = blockIdx.z;
    const int tid = threadIdx.x;

    if (tid < 64) {
        int row_g = b*SEQ + c*64 + tid;
        sA[tid] = g_Ad[row_g*64 + h];
    }
    __syncthreads();
#pragma unroll
    for (int o = 1; o < 64; o <<= 1) {
        float v = (tid < 64 && tid >= o) ? sA[tid - o] : 0.f;
        __syncthreads();
        if (tid < 64) sA[tid] += v;
        __syncthreads();
    }
    float Alast = sA[63];
    if (tid < 64) {
        sW[tid] = expf(Alast - sA[tid]);
        g_eA[((b*NCHUNK + c)*NHEADS + h)*64 + tid] = expf(sA[tid]);
    }
    if (tid == 0) g_cd[(b*NCHUNK + c)*NHEADS + h] = expf(Alast);

#pragma unroll
    for (int it = 0; it < 4; it++) {
        int idx = tid + it*256;
        int l = idx >> 4;
        int p4 = (idx & 15) << 2;
        int row_g = b*SEQ + c*64 + l;
        const float* xp = g_P + (size_t)row_g*NPROJ + OFF_XC + h*64 + p4;
        float4 xc = *(const float4*)xp;
        float ga = g_ga[row_g*64 + h];
        float be = g_be[row_g*64 + h];
        float4 xv;
        xv.x = siluf(xc.x)*ga; xv.y = siluf(xc.y)*ga; xv.z = siluf(xc.z)*ga; xv.w = siluf(xc.w)*ga;
        if (c*64 + l > 0) {
            float4 xq = *(const float4*)(xp - NPROJ);
            xv.x += siluf(xq.x)*be; xv.y += siluf(xq.y)*be; xv.z += siluf(xq.z)*be; xv.w += siluf(xq.w)*be;
        }
        *(float4*)&sX[l*68 + p4] = xv;
        float4 bb = *(const float4*)&g_Bv[row_g*64 + p4];
        *(float4*)&sB[l*68 + p4] = bb;
        sBT[(p4+0)*68 + l] = bb.x; sBT[(p4+1)*68 + l] = bb.y;
        sBT[(p4+2)*68 + l] = bb.z; sBT[(p4+3)*68 + l] = bb.w;
        float4 cc = *(const float4*)&g_Cv[row_g*64 + p4];
        sCT[(p4+0)*68 + l] = cc.x; sCT[(p4+1)*68 + l] = cc.y;
        sCT[(p4+2)*68 + l] = cc.z; sCT[(p4+3)*68 + l] = cc.w;
    }
    __syncthreads();

    const int ti = tid >> 4, tj = tid & 15;

    if (tj <= ti) {
        const int l0 = ti*4, s0 = tj*4;
        float acc[4][4];
#pragma unroll
        for (int i = 0; i < 4; i++)
#pragma unroll
            for (int j = 0; j < 4; j++) acc[i][j] = 0.f;
#pragma unroll
        for (int n = 0; n < 64; n++) {
            float4 cl = *(const float4*)&sCT[n*68 + l0];
            float4 bs = *(const float4*)&sBT[n*68 + s0];
            float clv[4] = {cl.x, cl.y, cl.z, cl.w};
            float bsv[4] = {bs.x, bs.y, bs.z, bs.w};
#pragma unroll
            for (int i = 0; i < 4; i++)
#pragma unroll
                for (int j = 0; j < 4; j++)
                    acc[i][j] = fmaf(clv[i], bsv[j], acc[i][j]);
        }
        float al[4];
#pragma unroll
        for (int i = 0; i < 4; i++) al[i] = sA[l0 + i];
#pragma unroll
        for (int j = 0; j < 4; j++) {
            int s = s0 + j;
            float as = sA[s];
#pragma unroll
            for (int i = 0; i < 4; i++) {
                int l = l0 + i;
                sGT[s*68 + l] = (s <= l) ? acc[i][j] * expf(al[i] - as) : 0.f;
            }
        }
    }
    __syncthreads();

    {
        const int l0 = ti*4, p0 = tj*4;
        float acc[4][4];
#pragma unroll
        for (int i = 0; i < 4; i++)
#pragma unroll
            for (int j = 0; j < 4; j++) acc[i][j] = 0.f;
        const int smax = l0 + 4;
#pragma unroll 4
        for (int s = 0; s < smax; s++) {
            float4 gt = *(const float4*)&sGT[s*68 + l0];
            float4 xr = *(const float4*)&sX[s*68 + p0];
            float gv[4] = {gt.x, gt.y, gt.z, gt.w};
            float xvv[4] = {xr.x, xr.y, xr.z, xr.w};
#pragma unroll
            for (int i = 0; i < 4; i++)
#pragma unroll
                for (int j = 0; j < 4; j++)
                    acc[i][j] = fmaf(gv[i], xvv[j], acc[i][j]);
        }
#pragma unroll
        for (int i = 0; i < 4; i++) {
            int row_g = b*SEQ + c*64 + l0 + i;
            *(float4*)&g_Y[(size_t)row_g*D_INNER + h*64 + p0] =
                make_float4(acc[i][0], acc[i][1], acc[i][2], acc[i][3]);
        }
    }

    {
        const int p0 = ti*4, n0 = tj*4;
        float acc[4][4];
#pragma unroll
        for (int i = 0; i < 4; i++)
#pragma unroll
            for (int j = 0; j < 4; j++) acc[i][j] = 0.f;
#pragma unroll
        for (int l = 0; l < 64; l++) {
            float w = sW[l];
            float4 xr = *(const float4*)&sX[l*68 + p0];
            float4 br = *(const float4*)&sB[l*68 + n0];
            float wx[4] = {w*xr.x, w*xr.y, w*xr.z, w*xr.w};
            float bvv[4] = {br.x, br.y, br.z, br.w};
#pragma unroll
            for (int i = 0; i < 4; i++)
#pragma unroll
                for (int j = 0; j < 4; j++)
                    acc[i][j] = fmaf(wx[i], bvv[j], acc[i][j]);
        }
        size_t base = (size_t)((b*NCHUNK + c)*NHEADS + h) * 4096;
#pragma unroll
        for (int i = 0; i < 4; i++)
            *(float4*)&g_S[base + (p0 + i)*64 + n0] =
                make_float4(acc[i][0], acc[i][1], acc[i][2], acc[i][3]);
    }
}

// ---------------- inter-chunk scan: 512 CTAs ----------------
__global__ void k_cscan()
{
    int q = blockIdx.x & 3;
    int h = (blockIdx.x >> 2) & 63;
    int b = blockIdx.x >> 8;
    int tid = threadIdx.x;
    int off = q * 1024 + tid * 4;
    float s0 = 0.f, s1 = 0.f, s2 = 0.f, s3 = 0.f;
    const float* cdp = g_cd + b * NCHUNK * NHEADS + h;
    for (int c = 0; c < NCHUNK; c++) {
        size_t base = ((size_t)((b*NCHUNK + c)*NHEADS + h) << 12) + off;
        float cd = cdp[c * NHEADS];
        float4 t = *(const float4*)&g_S[base];
        *(float4*)&g_S[base] = make_float4(s0, s1, s2, s3);
        s0 = fmaf(cd, s0, t.x);
        s1 = fmaf(cd, s1, t.y);
        s2 = fmaf(cd, s2, t.z);
        s3 = fmaf(cd, s3, t.w);
    }
}

// ---------------- Y_off + D skip + z gating (FFMA) ----------------
__launch_bounds__(256)
__global__ void k_off(const float* __restrict__ Dp)
{
    __shared__ float sST[64*68];
    __shared__ float sCT[64*68];
    const int h = blockIdx.x, c = blockIdx.y, b = blockIdx.z;
    const int tid = threadIdx.x;
    size_t sbase = (size_t)((b*NCHUNK + c)*NHEADS + h) * 4096;
#pragma unroll
    for (int it = 0; it < 4; it++) {
        int idx = tid + it*256;
        int r = idx >> 4;
        int n4 = (idx & 15) << 2;
        float4 sv = *(const float4*)&g_S[sbase + r*64 + n4];
        sST[(n4+0)*68 + r] = sv.x; sST[(n4+1)*68 + r] = sv.y;
        sST[(n4+2)*68 + r] = sv.z; sST[(n4+3)*68 + r] = sv.w;
        int row_g = b*SEQ + c*64 + r;
        float4 cv = *(const float4*)&g_Cv[row_g*64 + n4];
        sCT[(n4+0)*68 + r] = cv.x; sCT[(n4+1)*68 + r] = cv.y;
        sCT[(n4+2)*68 + r] = cv.z; sCT[(n4+3)*68 + r] = cv.w;
    }
    __syncthreads();
    const int ti = tid >> 4, tj = tid & 15;
    const int l0 = ti*4, p0 = tj*4;
    float acc[4][4];
#pragma unroll
    for (int i = 0; i < 4; i++)
#pragma unroll
        for (int j = 0; j < 4; j++) acc[i][j] = 0.f;
#pragma unroll
    for (int n = 0; n < 64; n++) {
        float4 cl = *(const float4*)&sCT[n*68 + l0];
        float4 sp = *(const float4*)&sST[n*68 + p0];
        float clv[4] = {cl.x, cl.y, cl.z, cl.w};
        float spv[4] = {sp.x, sp.y, sp.z, sp.w};
#pragma unroll
        for (int i = 0; i < 4; i++)
#pragma unroll
            for (int j = 0; j < 4; j++)
                acc[i][j] = fmaf(clv[i], spv[j], acc[i][j]);
    }
    float Dh = Dp[h];
#pragma unroll
    for (int i = 0; i < 4; i++) {
        int l = l0 + i;
        int row_g = b*SEQ + c*64 + l;
        float e = g_eA[((b*NCHUNK + c)*NHEADS + h)*64 + l];
        const float* pr = g_P + (size_t)row_g*NPROJ;
        float4 xc = *(const float4*)&pr[OFF_XC + h*64 + p0];
        float4 zz = *(const float4*)&pr[OFF_Z  + h*64 + p0];
        float* yp = &g_Y[(size_t)row_g*D_INNER + h*64 + p0];
        float4 yd = *(const float4*)yp;
        float4 o;
        o.x = (yd.x + e*acc[i][0] + Dh*siluf(xc.x)) * siluf(zz.x);
        o.y = (yd.y + e*acc[i][1] + Dh*siluf(xc.y)) * siluf(zz.y);
        o.z = (yd.z + e*acc[i][2] + Dh*siluf(xc.z)) * siluf(zz.z);
        o.w = (yd.w + e*acc[i][3] + Dh*siluf(xc.w)) * siluf(zz.w);
        *(float4*)yp = o;
    }
}

// ---------------- rmsnorm over 4096 per row -> bf16 hi/lo ----------------
__global__ void k_rms()
{
    int row = blockIdx.x;
    int tid = threadIdx.x;
    const float* Yp = g_Y + (size_t)row * D_INNER;
    float4 v[4];
    float ss = 0.f;
#pragma unroll
    for (int i = 0; i < 4; i++) {
        v[i] = *(const float4*)&Yp[tid*16 + i*4];
        ss += v[i].x*v[i].x + v[i].y*v[i].y + v[i].z*v[i].z + v[i].w*v[i].w;
    }
#pragma unroll
    for (int o = 16; o; o >>= 1) ss += __shfl_xor_sync(0xffffffffu, ss, o);
    __shared__ float red[8];
    if ((tid & 31) == 0) red[tid >> 5] = ss;
    __syncthreads();
    float tot = 0.f;
#pragma unroll
    for (int i = 0; i < 8; i++) tot += red[i];
    float r = rsqrtf(tot * (1.f/4096.f) + RMS_EPS);
    size_t base = (size_t)row * D_INNER + tid*16;
#pragma unroll
    for (int i = 0; i < 4; i++) {
        float vv[4] = {v[i].x*r, v[i].y*r, v[i].z*r, v[i].w*r};
#pragma unroll
        for (int k = 0; k < 4; k++) {
            __nv_bfloat16 h = __float2bfloat16(vv[k]);
            g_Yh[base + i*4 + k] = h;
            g_Yl[base + i*4 + k] = __float2bfloat16(vv[k] - __bfloat162float(h));
        }
    }
}

// ---------------- host: tensormap construction ----------------
typedef CUresult (*PFN_encodeTiled)(
    CUtensorMap*, CUtensorMapDataType, cuuint32_t, void*,
    const cuuint64_t*, const cuuint64_t*, const cuuint32_t*, const cuuint32_t*,
    CUtensorMapInterleave, CUtensorMapSwizzle, CUtensorMapL2promotion, CUtensorMapFloatOOBfill);

static void mk2d(PFN_encodeTiled enc, CUtensorMap* m, void* ptr, uint64_t k, uint64_t rows)
{
    cuuint64_t dims[2]    = {k, rows};
    cuuint64_t strides[1] = {k * 2};
    cuuint32_t box[2]     = {64, 128};
    cuuint32_t es[2]      = {1, 1};
    enc(m, CU_TENSOR_MAP_DATA_TYPE_BFLOAT16, 2, ptr, dims, strides, box, es,
        CU_TENSOR_MAP_INTERLEAVE_NONE, CU_TENSOR_MAP_SWIZZLE_128B,
        CU_TENSOR_MAP_L2_PROMOTION_L2_128B, CU_TENSOR_MAP_FLOAT_OOB_FILL_NONE);
}

// ---------------- launcher ----------------
extern "C" void kernel_launch(void* const* d_in, const int* in_sizes, int n_in,
                              void* d_out, int out_size)
{
    const float* x    = (const float*)d_in[0];
    const float* Win  = (const float*)d_in[1];
    const float* Wth  = (const float*)d_in[2];
    const float* Wla  = (const float*)d_in[3];
    const float* Wout = (const float*)d_in[4];
    const float* Bb   = (const float*)d_in[5];
    const float* Cb   = (const float*)d_in[6];
    const float* Alog = (const float*)d_in[7];
    const float* Dp   = (const float*)d_in[8];
    const float* dtb  = (const float*)d_in[9];
    float* out = (float*)d_out;

    __nv_bfloat16 *pWq, *pWoq, *pxh, *pxl, *pYh, *pYl;
    float *pWs, *pWos, *pP;
    cudaGetSymbolAddress((void**)&pWq,  g_Wq);
    cudaGetSymbolAddress((void**)&pWs,  g_Ws);
    cudaGetSymbolAddress((void**)&pWoq, g_Woq);
    cudaGetSymbolAddress((void**)&pWos, g_Wos);
    cudaGetSymbolAddress((void**)&pxh,  g_xh);
    cudaGetSymbolAddress((void**)&pxl,  g_xl);
    cudaGetSymbolAddress((void**)&pYh,  g_Yh);
    cudaGetSymbolAddress((void**)&pYl,  g_Yl);
    cudaGetSymbolAddress((void**)&pP,   g_P);

    PFN_encodeTiled enc = nullptr;
    {
        void* fp = nullptr;
        cudaDriverEntryPointQueryResult qr;
        cudaGetDriverEntryPoint("cuTensorMapEncodeTiled", &fp, cudaEnableDefault, &qr);
        enc = (PFN_encodeTiled)fp;
    }
    CUtensorMap t1Ah, t1Al, t1Bq, t2Ah, t2Al, t2Bq;
    mk2d(enc, &t1Ah, pxh,  DIMK,    ROWS);
    mk2d(enc, &t1Al, pxl,  DIMK,    ROWS);
    mk2d(enc, &t1Bq, pWq,  DIMK,    NPROJ_PAD);
    mk2d(enc, &t2Ah, pYh,  D_INNER, ROWS);
    mk2d(enc, &t2Al, pYl,  D_INNER, ROWS);
    mk2d(enc, &t2Bq, pWoq, D_INNER, DIMK);

    const int smem1 = SSB_OFF + 16 * 132 * 4;
    const int smem2 = SSB_OFF + 32 * 132 * 4;

    cudaFuncSetAttribute(k_chunk,    cudaFuncAttributeMaxDynamicSharedMemorySize, SM_CHUNK_BYTES);
    cudaFuncSetAttribute(k_mmt<16>,  cudaFuncAttributeMaxDynamicSharedMemorySize, smem1);
    cudaFuncSetAttribute(k_mmt<32>,  cudaFuncAttributeMaxDynamicSharedMemorySize, smem2);

    k_dequantq<<<(8384*16 + 3)/4, 128>>>(Win, pWq, pWs, 8384*16);
    k_dequantq<<<(512 + 3)/4,    128>>>(Wth, pWq + (size_t)8384*DIMK, pWs + (size_t)8384*16, 512);
    k_dequantq<<<(1024 + 3)/4,   128>>>(Wla, pWq + (size_t)8416*DIMK, pWs + (size_t)8416*16, 1024);
    k_dequantq<<<65536/4,        128>>>(Wout, pWoq, pWos, 65536);

    k_split<<<ROWS*DIMK/1024, 256>>>(x, pxh, pxl);

    k_mmt<16><<<dim3(ROWS/128, NPROJ_PAD/128), 512, smem1>>>(
        t1Ah, t1Al, t1Bq, pWs, pP, NPROJ, NPROJ, DIMK);

    k_point<<<ROWS, 64>>>(Bb, Cb, Alog, dtb);
    k_scan <<<64, 256>>>();
    k_rope <<<ROWS, 32>>>();

    k_chunk<<<dim3(NHEADS, NCHUNK, BATCH), 256, SM_CHUNK_BYTES>>>();
    k_cscan<<<512, 256>>>();
    k_off  <<<dim3(NHEADS, NCHUNK, BATCH), 256>>>(Dp);

    k_rms<<<ROWS, 256>>>();

    k_mmt<32><<<dim3(ROWS/128, DIMK/128), 512, smem2>>>(
        t2Ah, t2Al, t2Bq, pWos, out, DIMK, DIMK, D_INNER);
}

// round 15
// speedup vs baseline: 1.2498x; 1.0906x over previous
#include <cuda.h>
#include <cuda_runtime.h>
#include <cuda_bf16.h>
#include <math.h>
#include <stdint.h>

#define SEQ     4096
#define BATCH   2
#define ROWS    (BATCH*SEQ)     // 8192
#define DIMK    2048
#define D_INNER 4096
#define NHEADS  64
#define NPROJ   8480
#define NPROJ_PAD 8576          // 67 * 128
#define OFF_Z   0
#define OFF_XC  4096
#define OFF_B   8192
#define OFF_C   8256
#define OFF_DT  8320
#define OFF_TH  8384
#define OFF_LAM 8416
#define NCHUNK  64
#define RMS_EPS 1.1920929e-07f

// ---------------- device scratch (no allocation allowed) ----------------
__device__ __nv_bfloat16 g_Wq [NPROJ_PAD * DIMK];
__device__ float         g_Ws [NPROJ_PAD * 16];
__device__ __nv_bfloat16 g_Woq[DIMK * D_INNER];
__device__ float         g_Wos[DIMK * 32];
__device__ __nv_bfloat16 g_xh [ROWS * DIMK];
__device__ __nv_bfloat16 g_xl [ROWS * DIMK];
__device__ __nv_bfloat16 g_Yh [ROWS * D_INNER];
__device__ __nv_bfloat16 g_Yl [ROWS * D_INNER];
__device__ float g_P [ROWS * NPROJ];
__device__ float g_Bv[ROWS * 64];
__device__ float g_Cv[ROWS * 64];
__device__ float g_Ad[ROWS * 64];
__device__ float g_ga[ROWS * 64];
__device__ float g_be[ROWS * 64];
__device__ float g_td[ROWS * 32];
__device__ float g_Y [ROWS * D_INNER];          // Y_diag (+D skip) between chunk and off
__device__ float g_S [BATCH * NCHUNK * NHEADS * 64 * 64];
__device__ float g_eA[BATCH * NCHUNK * NHEADS * 64];
__device__ float g_cd[BATCH * NCHUNK * NHEADS];

__device__ __forceinline__ float siluf(float x) { return x / (1.f + expf(-x)); }

__device__ __forceinline__ uint32_t s2u(const void* p) {
    uint32_t a;
    asm("{ .reg .u64 t; cvta.to.shared.u64 t, %1; cvt.u32.u64 %0, t; }" : "=r"(a) : "l"(p));
    return a;
}

__device__ __forceinline__ void sp2(float v, __nv_bfloat16* ph, __nv_bfloat16* pl) {
    __nv_bfloat16 h = __float2bfloat16(v);
    *ph = h;
    *pl = __float2bfloat16(v - __bfloat162float(h));
}

// ================= TMA-fed quant-aware emulated-fp32 GEMM (R13) =================
#define TILE_B  16384
#define STAGE_B (3*TILE_B)
#define MB_OFF  (3*STAGE_B)
#define SSB_OFF (MB_OFF + 64)

#define SWZ(o) ((o) ^ ((((uint32_t)(o)) >> 3) & 0x70u))

#define LDSM4(r0,r1,r2,r3,a) \
    asm volatile("ldmatrix.sync.aligned.m8n8.x4.shared.b16 {%0,%1,%2,%3}, [%4];" \
        : "=r"(r0),"=r"(r1),"=r"(r2),"=r"(r3) : "r"(a))

#define MMA16816(d,a,b0,b1) \
    asm volatile("mma.sync.aligned.m16n8k16.row.col.f32.bf16.bf16.f32 " \
        "{%0,%1,%2,%3}, {%4,%5,%6,%7}, {%8,%9}, {%0,%1,%2,%3};" \
        : "+f"((d)[0]),"+f"((d)[1]),"+f"((d)[2]),"+f"((d)[3]) \
        : "r"((a)[0]),"r"((a)[1]),"r"((a)[2]),"r"((a)[3]),"r"(b0),"r"(b1))

#define MBAR_INIT(a, c) asm volatile("mbarrier.init.shared.b64 [%0], %1;" :: "r"(a), "r"(c) : "memory")
#define FENCE_ASYNC()   asm volatile("fence.proxy.async.shared::cta;" ::: "memory")
#define MBAR_EXPECT(a, bytes) \
    asm volatile("mbarrier.arrive.expect_tx.shared.b64 _, [%0], %1;" :: "r"(a), "r"(bytes) : "memory")
#define MBAR_ARRIVE(a) \
    asm volatile("mbarrier.arrive.release.cta.shared::cta.b64 _, [%0];" :: "r"(a) : "memory")

__device__ __forceinline__ void mbar_wait(uint32_t a, uint32_t ph) {
    asm volatile(
        "{\n\t.reg .pred P;\n\t"
        "WL%=:\n\tmbarrier.try_wait.parity.acquire.cta.shared::cta.b64 P, [%0], %1, 0x989680;\n\t"
        "@P bra WD%=;\n\tbra WL%=;\n\tWD%=:\n\t}"
        :: "r"(a), "r"(ph) : "memory");
}

__device__ __forceinline__ void tma2d(uint32_t dst, const CUtensorMap* m, int x, int y, uint32_t mbar) {
    asm volatile(
        "cp.async.bulk.tensor.2d.shared::cta.global.tile.mbarrier::complete_tx::bytes "
        "[%0], [%1, {%2, %3}], [%4];"
        :: "r"(dst), "l"(m), "r"(x), "r"(y), "r"(mbar) : "memory");
}

template<int NG>
__global__ void __launch_bounds__(512, 1)
k_mmt(const __grid_constant__ CUtensorMap tAh,
      const __grid_constant__ CUtensorMap tAl,
      const __grid_constant__ CUtensorMap tBq,
      const float* __restrict__ Bs, float* __restrict__ C,
      int Nw, int Nlim, int K)
{
    extern __shared__ __align__(1024) uint8_t sh8[];
    float* ss = (float*)(sh8 + SSB_OFF);
    const uint32_t sb = s2u(sh8);
    const uint32_t mb = sb + MB_OFF;
    const int tid  = threadIdx.x;
    const int lane = tid & 31;
    const int wid  = tid >> 5;
    const int m0 = blockIdx.x * 128;
    const int n0 = blockIdx.y * 128;
    const int mw = (wid >> 2) * 32;
    const int nw = (wid & 3) * 32;

    if (tid == 0) {
        MBAR_INIT(mb + 0, 1);
        MBAR_INIT(mb + 8, 1);
        MBAR_INIT(mb + 16, 1);
        MBAR_INIT(mb + 24, 16);
        MBAR_INIT(mb + 32, 16);
        MBAR_INIT(mb + 40, 16);
    }
    for (int idx = tid; idx < 128 * NG; idx += 512) {
        int g = idx >> 7, nl = idx & 127;
        ss[g * 132 + nl] = Bs[(size_t)(n0 + nl) * NG + g];
    }
    __syncthreads();

    const int NK = K >> 6;

#define TFILL(buf, kc) do {                                   \
        uint32_t mba = mb + (buf) * 8;                        \
        MBAR_EXPECT(mba, 3 * TILE_B);                         \
        uint32_t d = sb + (buf) * STAGE_B;                    \
        tma2d(d,             &tAh, (kc) * 64, m0, mba);       \
        tma2d(d + TILE_B,    &tAl, (kc) * 64, m0, mba);       \
        tma2d(d + 2*TILE_B,  &tBq, (kc) * 64, n0, mba);       \
    } while (0)

    if (tid == 0) {
        FENCE_ASYNC();
        TFILL(0, 0);
        TFILL(1, 1);
    }
    if (lane == 0) {
        MBAR_ARRIVE(mb + 24);
        MBAR_ARRIVE(mb + 32);
        MBAR_ARRIVE(mb + 40);
    }

    float acc[2][4][4];
#pragma unroll
    for (int i = 0; i < 2; i++)
#pragma unroll
        for (int j = 0; j < 4; j++)
#pragma unroll
            for (int k = 0; k < 4; k++) acc[i][j][k] = 0.f;

    const int rowoff = (lane & 7) + ((lane >> 3) & 1) * 8;
    const int colb2  = (lane >> 4) * 16;
    const int c0 = (lane & 3) * 2;

    for (int g = 0; g < NG; g++) {
        float accg[2][4][4];
#pragma unroll
        for (int i = 0; i < 2; i++)
#pragma unroll
            for (int j = 0; j < 4; j++)
#pragma unroll
                for (int k = 0; k < 4; k++) accg[i][j][k] = 0.f;

#pragma unroll
        for (int kq = 0; kq < 2; kq++) {
            const int kc = g * 2 + kq;
            const int buf = kc % 3;

            mbar_wait(mb + buf * 8, (kc / 3) & 1);

            if (tid == 0 && kc + 2 < NK) {
                const int tbuf = (kc + 2) % 3;
                mbar_wait(mb + 24 + tbuf * 8, ((kc + 2) / 3) & 1);
                FENCE_ASYNC();
                TFILL(tbuf, kc + 2);
            }

            const uint32_t stg = sb + buf * STAGE_B;
#pragma unroll
            for (int kk = 0; kk < 4; kk++) {
                uint32_t afr[2][2][4];
                uint32_t bfr[2][4];
#pragma unroll
                for (int hl = 0; hl < 2; hl++)
#pragma unroll
                    for (int mi = 0; mi < 2; mi++) {
                        uint32_t off = (uint32_t)(mw + mi * 16 + rowoff) * 128 + kk * 32 + colb2;
                        uint32_t a = stg + hl * TILE_B + SWZ(off);
                        LDSM4(afr[hl][mi][0], afr[hl][mi][1], afr[hl][mi][2], afr[hl][mi][3], a);
                    }
#pragma unroll
                for (int nj = 0; nj < 2; nj++) {
                    uint32_t off = (uint32_t)(nw + nj * 16 + rowoff) * 128 + kk * 32 + colb2;
                    uint32_t a = stg + 2 * TILE_B + SWZ(off);
                    LDSM4(bfr[nj][0], bfr[nj][1], bfr[nj][2], bfr[nj][3], a);
                }
#pragma unroll
                for (int term = 0; term < 2; term++)
#pragma unroll
                    for (int mi = 0; mi < 2; mi++)
#pragma unroll
                        for (int ni = 0; ni < 4; ni++) {
                            int nj = ni >> 1, s = ni & 1;
                            MMA16816(accg[mi][ni], afr[term][mi],
                                     bfr[nj][s], bfr[nj][s + 2]);
                        }
            }

            if (lane == 0) MBAR_ARRIVE(mb + 24 + buf * 8);
        }

#pragma unroll
        for (int ni = 0; ni < 4; ni++) {
            float2 sv = *(const float2*)&ss[g * 132 + nw + ni * 8 + c0];
#pragma unroll
            for (int mi = 0; mi < 2; mi++) {
                acc[mi][ni][0] = fmaf(sv.x, accg[mi][ni][0], acc[mi][ni][0]);
                acc[mi][ni][1] = fmaf(sv.y, accg[mi][ni][1], acc[mi][ni][1]);
                acc[mi][ni][2] = fmaf(sv.x, accg[mi][ni][2], acc[mi][ni][2]);
                acc[mi][ni][3] = fmaf(sv.y, accg[mi][ni][3], acc[mi][ni][3]);
            }
        }
    }

    const int r0 = lane >> 2;
#pragma unroll
    for (int mi = 0; mi < 2; mi++) {
#pragma unroll
        for (int ni = 0; ni < 4; ni++) {
            int m = m0 + mw + mi * 16 + r0;
            int n = n0 + nw + ni * 8 + c0;
            if (n < Nlim) {
                *(float2*)&C[(size_t)m * Nw + n]       = make_float2(acc[mi][ni][0], acc[mi][ni][1]);
                *(float2*)&C[(size_t)(m + 8) * Nw + n] = make_float2(acc[mi][ni][2], acc[mi][ni][3]);
            }
        }
    }
#undef TFILL
}

// ---------------- fq4 dequantization -> q (bf16, exact) + group scale ----------------
__global__ void k_dequantq(const float* __restrict__ src, __nv_bfloat16* __restrict__ dq,
                           float* __restrict__ ds, int ngroups)
{
    int g = blockIdx.x * 4 + (threadIdx.x >> 5);
    if (g >= ngroups) return;
    int lane = threadIdx.x & 31;
    const float* s = src + (size_t)g * 128;
    float v[4];
    float m = 0.f;
#pragma unroll
    for (int i = 0; i < 4; i++) { v[i] = s[lane + 32*i]; m = fmaxf(m, fabsf(v[i])); }
#pragma unroll
    for (int o = 16; o; o >>= 1) m = fmaxf(m, __shfl_xor_sync(0xffffffffu, m, o));
    float scale = fmaxf(m, 1e-10f) / 7.0f;
    if (lane == 0) ds[g] = scale;
#pragma unroll
    for (int i = 0; i < 4; i++) {
        float q = rintf(v[i] / scale);
        q = fminf(fmaxf(q, -8.f), 7.f);
        dq[(size_t)g * 128 + lane + 32*i] = __float2bfloat16(q);
    }
}

// ---------------- split fp32 -> bf16 hi/lo ----------------
__global__ void k_split(const float* __restrict__ src, __nv_bfloat16* __restrict__ dh,
                        __nv_bfloat16* __restrict__ dl)
{
    size_t i = ((size_t)blockIdx.x * 256 + threadIdx.x) * 4;
    float4 v = *(const float4*)(src + i);
    float vv[4] = {v.x, v.y, v.z, v.w};
#pragma unroll
    for (int k = 0; k < 4; k++) sp2(vv[k], dh + i + k, dl + i + k);
}

// ---------------- pointwise epilogue per (b,l) row: 64 threads ----------------
__global__ void k_point(const float* __restrict__ Bb, const float* __restrict__ Cb,
                        const float* __restrict__ Alog, const float* __restrict__ dtb)
{
    int row = blockIdx.x;
    int t = threadIdx.x;
    const float* pr = g_P + (size_t)row * NPROJ;
    __shared__ float red[6];

    float dtr = pr[OFF_DT + t] + dtb[t];
    float dt = (dtr > 20.f) ? dtr : log1pf(expf(dtr));
    float Ad = -expf(Alog[t]) * dt;
    float lam = 1.f / (1.f + expf(-pr[OFF_LAM + t]));
    g_Ad[row*64 + t] = Ad;
    g_ga[row*64 + t] = lam * dt;
    g_be[row*64 + t] = (1.f - lam) * dt * expf(Ad);

    float bv = pr[OFF_B + t];
    float cv = pr[OFF_C + t];

    float s0 = dt, s1 = bv*bv, s2 = cv*cv;
#pragma unroll
    for (int o = 16; o; o >>= 1) {
        s0 += __shfl_xor_sync(0xffffffffu, s0, o);
        s1 += __shfl_xor_sync(0xffffffffu, s1, o);
        s2 += __shfl_xor_sync(0xffffffffu, s2, o);
    }
    int w = t >> 5;
    if ((t & 31) == 0) { red[w*3+0] = s0; red[w*3+1] = s1; red[w*3+2] = s2; }
    __syncthreads();
    float dt_avg = (red[0] + red[3]) * (1.f/64.f);
    float rb = rsqrtf((red[1] + red[4]) * (1.f/64.f) + RMS_EPS);
    float rc = rsqrtf((red[2] + red[5]) * (1.f/64.f) + RMS_EPS);

    g_Bv[row*64 + t] = bv * rb + Bb[t];
    g_Cv[row*64 + t] = cv * rc + Cb[t];
    if (t < 32) g_td[row*32 + t] = pr[OFF_TH + t] * dt_avg;
}

// ---------------- cumsum of theta*dt_avg over L per (b, n) ----------------
__global__ void k_scan()
{
    int b = blockIdx.x >> 5;
    int n = blockIdx.x & 31;
    int tid = threadIdx.x;
    __shared__ float ps[256];
    float loc[16];
    float run = 0.f;
    int base = (b*SEQ + tid*16) * 32 + n;
#pragma unroll
    for (int j = 0; j < 16; j++) { run += g_td[base + j*32]; loc[j] = run; }
    ps[tid] = run;
    __syncthreads();
#pragma unroll
    for (int o = 1; o < 256; o <<= 1) {
        float v = (tid >= o) ? ps[tid - o] : 0.f;
        __syncthreads();
        ps[tid] += v;
        __syncthreads();
    }
    float off = (tid > 0) ? ps[tid - 1] : 0.f;
#pragma unroll
    for (int j = 0; j < 16; j++) g_td[base + j*32] = loc[j] + off;
}

// ---------------- rope on B and C (in place) ----------------
__global__ void k_rope()
{
    int row = blockIdx.x;
    int t = threadIdx.x;
    float a = g_td[row*32 + t];
    float ca = cosf(a), sa = sinf(a);
    float br = g_Bv[row*64 + t], bi = g_Bv[row*64 + 32 + t];
    g_Bv[row*64 + t]      = br*ca - bi*sa;
    g_Bv[row*64 + 32 + t] = br*sa + bi*ca;
    float cr = g_Cv[row*64 + t], ci = g_Cv[row*64 + 32 + t];
    g_Cv[row*64 + t]      = cr*ca - ci*sa;
    g_Cv[row*64 + 32 + t] = cr*sa + ci*ca;
}

// ---------------- intra-chunk: Y_diag (+ D skip) + per-chunk states ----------------
#define SM_CHUNK_BYTES ((4352*5 + 128) * 4)
__launch_bounds__(256)
__global__ void k_chunk(const float* __restrict__ Dp)
{
    extern __shared__ float sm[];
    float* sX  = sm;
    float* sB  = sm + 4352;
    float* sBT = sm + 8704;
    float* sCT = sm + 13056;
    float* sGT = sm + 17408;
    float* sA  = sm + 21760;
    float* sW  = sm + 21824;

    const int h = blockIdx.x, c = blockIdx.y, b = blockIdx.z;
    const int tid = threadIdx.x;

    if (tid < 64) {
        int row_g = b*SEQ + c*64 + tid;
        sA[tid] = g_Ad[row_g*64 + h];
    }
    __syncthreads();
#pragma unroll
    for (int o = 1; o < 64; o <<= 1) {
        float v = (tid < 64 && tid >= o) ? sA[tid - o] : 0.f;
        __syncthreads();
        if (tid < 64) sA[tid] += v;
        __syncthreads();
    }
    float Alast = sA[63];
    if (tid < 64) {
        sW[tid] = expf(Alast - sA[tid]);
        g_eA[((b*NCHUNK + c)*NHEADS + h)*64 + tid] = expf(sA[tid]);
    }
    if (tid == 0) g_cd[(b*NCHUNK + c)*NHEADS + h] = expf(Alast);

#pragma unroll
    for (int it = 0; it < 4; it++) {
        int idx = tid + it*256;
        int l = idx >> 4;
        int p4 = (idx & 15) << 2;
        int row_g = b*SEQ + c*64 + l;
        const float* xp = g_P + (size_t)row_g*NPROJ + OFF_XC + h*64 + p4;
        float4 xc = *(const float4*)xp;
        float ga = g_ga[row_g*64 + h];
        float be = g_be[row_g*64 + h];
        float4 xv;
        xv.x = siluf(xc.x)*ga; xv.y = siluf(xc.y)*ga; xv.z = siluf(xc.z)*ga; xv.w = siluf(xc.w)*ga;
        if (c*64 + l > 0) {
            float4 xq = *(const float4*)(xp - NPROJ);
            xv.x += siluf(xq.x)*be; xv.y += siluf(xq.y)*be; xv.z += siluf(xq.z)*be; xv.w += siluf(xq.w)*be;
        }
        *(float4*)&sX[l*68 + p4] = xv;
        float4 bb = *(const float4*)&g_Bv[row_g*64 + p4];
        *(float4*)&sB[l*68 + p4] = bb;
        sBT[(p4+0)*68 + l] = bb.x; sBT[(p4+1)*68 + l] = bb.y;
        sBT[(p4+2)*68 + l] = bb.z; sBT[(p4+3)*68 + l] = bb.w;
        float4 cc = *(const float4*)&g_Cv[row_g*64 + p4];
        sCT[(p4+0)*68 + l] = cc.x; sCT[(p4+1)*68 + l] = cc.y;
        sCT[(p4+2)*68 + l] = cc.z; sCT[(p4+3)*68 + l] = cc.w;
    }
    __syncthreads();

    const int ti = tid >> 4, tj = tid & 15;

    if (tj <= ti) {
        const int l0 = ti*4, s0 = tj*4;
        float acc[4][4];
#pragma unroll
        for (int i = 0; i < 4; i++)
#pragma unroll
            for (int j = 0; j < 4; j++) acc[i][j] = 0.f;
#pragma unroll
        for (int n = 0; n < 64; n++) {
            float4 cl = *(const float4*)&sCT[n*68 + l0];
            float4 bs = *(const float4*)&sBT[n*68 + s0];
            float clv[4] = {cl.x, cl.y, cl.z, cl.w};
            float bsv[4] = {bs.x, bs.y, bs.z, bs.w};
#pragma unroll
            for (int i = 0; i < 4; i++)
#pragma unroll
                for (int j = 0; j < 4; j++)
                    acc[i][j] = fmaf(clv[i], bsv[j], acc[i][j]);
        }
        float al[4];
#pragma unroll
        for (int i = 0; i < 4; i++) al[i] = sA[l0 + i];
#pragma unroll
        for (int j = 0; j < 4; j++) {
            int s = s0 + j;
            float as = sA[s];
#pragma unroll
            for (int i = 0; i < 4; i++) {
                int l = l0 + i;
                sGT[s*68 + l] = (s <= l) ? acc[i][j] * expf(al[i] - as) : 0.f;
            }
        }
    }
    __syncthreads();

    {
        const int l0 = ti*4, p0 = tj*4;
        float acc[4][4];
#pragma unroll
        for (int i = 0; i < 4; i++)
#pragma unroll
            for (int j = 0; j < 4; j++) acc[i][j] = 0.f;
        const int smax = l0 + 4;
#pragma unroll 4
        for (int s = 0; s < smax; s++) {
            float4 gt = *(const float4*)&sGT[s*68 + l0];
            float4 xr = *(const float4*)&sX[s*68 + p0];
            float gv[4] = {gt.x, gt.y, gt.z, gt.w};
            float xvv[4] = {xr.x, xr.y, xr.z, xr.w};
#pragma unroll
            for (int i = 0; i < 4; i++)
#pragma unroll
                for (int j = 0; j < 4; j++)
                    acc[i][j] = fmaf(gv[i], xvv[j], acc[i][j]);
        }
        // fused D skip: Y_diag += Dh * silu(xc)   (xc tile is L1-hot from Phase B)
        float Dh = Dp[h];
#pragma unroll
        for (int i = 0; i < 4; i++) {
            int row_g = b*SEQ + c*64 + l0 + i;
            float4 xc = *(const float4*)&g_P[(size_t)row_g*NPROJ + OFF_XC + h*64 + p0];
            float4 o;
            o.x = acc[i][0] + Dh*siluf(xc.x);
            o.y = acc[i][1] + Dh*siluf(xc.y);
            o.z = acc[i][2] + Dh*siluf(xc.z);
            o.w = acc[i][3] + Dh*siluf(xc.w);
            *(float4*)&g_Y[(size_t)row_g*D_INNER + h*64 + p0] = o;
        }
    }

    {
        const int p0 = ti*4, n0 = tj*4;
        float acc[4][4];
#pragma unroll
        for (int i = 0; i < 4; i++)
#pragma unroll
            for (int j = 0; j < 4; j++) acc[i][j] = 0.f;
#pragma unroll
        for (int l = 0; l < 64; l++) {
            float w = sW[l];
            float4 xr = *(const float4*)&sX[l*68 + p0];
            float4 br = *(const float4*)&sB[l*68 + n0];
            float wx[4] = {w*xr.x, w*xr.y, w*xr.z, w*xr.w};
            float bvv[4] = {br.x, br.y, br.z, br.w};
#pragma unroll
            for (int i = 0; i < 4; i++)
#pragma unroll
                for (int j = 0; j < 4; j++)
                    acc[i][j] = fmaf(wx[i], bvv[j], acc[i][j]);
        }
        size_t base = (size_t)((b*NCHUNK + c)*NHEADS + h) * 4096;
#pragma unroll
        for (int i = 0; i < 4; i++)
            *(float4*)&g_S[base + (p0 + i)*64 + n0] =
                make_float4(acc[i][0], acc[i][1], acc[i][2], acc[i][3]);
    }
}

// ---------------- inter-chunk scan: 512 CTAs ----------------
__global__ void k_cscan()
{
    int q = blockIdx.x & 3;
    int h = (blockIdx.x >> 2) & 63;
    int b = blockIdx.x >> 8;
    int tid = threadIdx.x;
    int off = q * 1024 + tid * 4;
    float s0 = 0.f, s1 = 0.f, s2 = 0.f, s3 = 0.f;
    const float* cdp = g_cd + b * NCHUNK * NHEADS + h;
    for (int c = 0; c < NCHUNK; c++) {
        size_t base = ((size_t)((b*NCHUNK + c)*NHEADS + h) << 12) + off;
        float cd = cdp[c * NHEADS];
        float4 t = *(const float4*)&g_S[base];
        *(float4*)&g_S[base] = make_float4(s0, s1, s2, s3);
        s0 = fmaf(cd, s0, t.x);
        s1 = fmaf(cd, s1, t.y);
        s2 = fmaf(cd, s2, t.z);
        s3 = fmaf(cd, s3, t.w);
    }
}

// ---------------- Y_off + z gating -> bf16 hi/lo ----------------
__launch_bounds__(256)
__global__ void k_off()
{
    __shared__ float sST[64*68];
    __shared__ float sCT[64*68];
    const int h = blockIdx.x, c = blockIdx.y, b = blockIdx.z;
    const int tid = threadIdx.x;
    size_t sbase = (size_t)((b*NCHUNK + c)*NHEADS + h) * 4096;
#pragma unroll
    for (int it = 0; it < 4; it++) {
        int idx = tid + it*256;
        int r = idx >> 4;
        int n4 = (idx & 15) << 2;
        float4 sv = *(const float4*)&g_S[sbase + r*64 + n4];
        sST[(n4+0)*68 + r] = sv.x; sST[(n4+1)*68 + r] = sv.y;
        sST[(n4+2)*68 + r] = sv.z; sST[(n4+3)*68 + r] = sv.w;
        int row_g = b*SEQ + c*64 + r;
        float4 cv = *(const float4*)&g_Cv[row_g*64 + n4];
        sCT[(n4+0)*68 + r] = cv.x; sCT[(n4+1)*68 + r] = cv.y;
        sCT[(n4+2)*68 + r] = cv.z; sCT[(n4+3)*68 + r] = cv.w;
    }
    __syncthreads();
    const int ti = tid >> 4, tj = tid & 15;
    const int l0 = ti*4, p0 = tj*4;
    float acc[4][4];
#pragma unroll
    for (int i = 0; i < 4; i++)
#pragma unroll
        for (int j = 0; j < 4; j++) acc[i][j] = 0.f;
#pragma unroll
    for (int n = 0; n < 64; n++) {
        float4 cl = *(const float4*)&sCT[n*68 + l0];
        float4 sp = *(const float4*)&sST[n*68 + p0];
        float clv[4] = {cl.x, cl.y, cl.z, cl.w};
        float spv[4] = {sp.x, sp.y, sp.z, sp.w};
#pragma unroll
        for (int i = 0; i < 4; i++)
#pragma unroll
            for (int j = 0; j < 4; j++)
                acc[i][j] = fmaf(clv[i], spv[j], acc[i][j]);
    }
#pragma unroll
    for (int i = 0; i < 4; i++) {
        int l = l0 + i;
        int row_g = b*SEQ + c*64 + l;
        float e = g_eA[((b*NCHUNK + c)*NHEADS + h)*64 + l];
        const float* pr = g_P + (size_t)row_g*NPROJ;
        float4 zz = *(const float4*)&pr[OFF_Z + h*64 + p0];
        const float* yp = &g_Y[(size_t)row_g*D_INNER + h*64 + p0];
        float4 yd = *(const float4*)yp;
        float o0 = (yd.x + e*acc[i][0]) * siluf(zz.x);
        float o1 = (yd.y + e*acc[i][1]) * siluf(zz.y);
        float o2 = (yd.z + e*acc[i][2]) * siluf(zz.z);
        float o3 = (yd.w + e*acc[i][3]) * siluf(zz.w);
        size_t ob = (size_t)row_g*D_INNER + h*64 + p0;
        __nv_bfloat16 hbuf[4], lbuf[4];
        sp2(o0, hbuf + 0, lbuf + 0);
        sp2(o1, hbuf + 1, lbuf + 1);
        sp2(o2, hbuf + 2, lbuf + 2);
        sp2(o3, hbuf + 3, lbuf + 3);
        *(uint2*)(g_Yh + ob) = *(uint2*)hbuf;
        *(uint2*)(g_Yl + ob) = *(uint2*)lbuf;
    }
}

// ---------------- rmsnorm: read hi/lo, scale, rewrite hi/lo ----------------
__global__ void k_rms()
{
    int row = blockIdx.x;
    int tid = threadIdx.x;
    size_t base = (size_t)row * D_INNER + tid*16;
    __nv_bfloat16 hb[16], lb[16];
    *(uint4*)(hb)     = *(const uint4*)(g_Yh + base);
    *(uint4*)(hb + 8) = *(const uint4*)(g_Yh + base + 8);
    *(uint4*)(lb)     = *(const uint4*)(g_Yl + base);
    *(uint4*)(lb + 8) = *(const uint4*)(g_Yl + base + 8);
    float v[16];
    float ss = 0.f;
#pragma unroll
    for (int i = 0; i < 16; i++) {
        v[i] = __bfloat162float(hb[i]) + __bfloat162float(lb[i]);
        ss += v[i]*v[i];
    }
#pragma unroll
    for (int o = 16; o; o >>= 1) ss += __shfl_xor_sync(0xffffffffu, ss, o);
    __shared__ float red[8];
    if ((tid & 31) == 0) red[tid >> 5] = ss;
    __syncthreads();
    float tot = 0.f;
#pragma unroll
    for (int i = 0; i < 8; i++) tot += red[i];
    float r = rsqrtf(tot * (1.f/4096.f) + RMS_EPS);
#pragma unroll
    for (int i = 0; i < 16; i++) sp2(v[i]*r, hb + i, lb + i);
    *(uint4*)(g_Yh + base)     = *(uint4*)(hb);
    *(uint4*)(g_Yh + base + 8) = *(uint4*)(hb + 8);
    *(uint4*)(g_Yl + base)     = *(uint4*)(lb);
    *(uint4*)(g_Yl + base + 8) = *(uint4*)(lb + 8);
}

// ---------------- host: tensormap construction ----------------
typedef CUresult (*PFN_encodeTiled)(
    CUtensorMap*, CUtensorMapDataType, cuuint32_t, void*,
    const cuuint64_t*, const cuuint64_t*, const cuuint32_t*, const cuuint32_t*,
    CUtensorMapInterleave, CUtensorMapSwizzle, CUtensorMapL2promotion, CUtensorMapFloatOOBfill);

static void mk2d(PFN_encodeTiled enc, CUtensorMap* m, void* ptr, uint64_t k, uint64_t rows)
{
    cuuint64_t dims[2]    = {k, rows};
    cuuint64_t strides[1] = {k * 2};
    cuuint32_t box[2]     = {64, 128};
    cuuint32_t es[2]      = {1, 1};
    enc(m, CU_TENSOR_MAP_DATA_TYPE_BFLOAT16, 2, ptr, dims, strides, box, es,
        CU_TENSOR_MAP_INTERLEAVE_NONE, CU_TENSOR_MAP_SWIZZLE_128B,
        CU_TENSOR_MAP_L2_PROMOTION_L2_128B, CU_TENSOR_MAP_FLOAT_OOB_FILL_NONE);
}

// ---------------- launcher ----------------
extern "C" void kernel_launch(void* const* d_in, const int* in_sizes, int n_in,
                              void* d_out, int out_size)
{
    const float* x    = (const float*)d_in[0];
    const float* Win  = (const float*)d_in[1];
    const float* Wth  = (const float*)d_in[2];
    const float* Wla  = (const float*)d_in[3];
    const float* Wout = (const float*)d_in[4];
    const float* Bb   = (const float*)d_in[5];
    const float* Cb   = (const float*)d_in[6];
    const float* Alog = (const float*)d_in[7];
    const float* Dp   = (const float*)d_in[8];
    const float* dtb  = (const float*)d_in[9];
    float* out = (float*)d_out;

    __nv_bfloat16 *pWq, *pWoq, *pxh, *pxl, *pYh, *pYl;
    float *pWs, *pWos, *pP;
    cudaGetSymbolAddress((void**)&pWq,  g_Wq);
    cudaGetSymbolAddress((void**)&pWs,  g_Ws);
    cudaGetSymbolAddress((void**)&pWoq, g_Woq);
    cudaGetSymbolAddress((void**)&pWos, g_Wos);
    cudaGetSymbolAddress((void**)&pxh,  g_xh);
    cudaGetSymbolAddress((void**)&pxl,  g_xl);
    cudaGetSymbolAddress((void**)&pYh,  g_Yh);
    cudaGetSymbolAddress((void**)&pYl,  g_Yl);
    cudaGetSymbolAddress((void**)&pP,   g_P);

    PFN_encodeTiled enc = nullptr;
    {
        void* fp = nullptr;
        cudaDriverEntryPointQueryResult qr;
        cudaGetDriverEntryPoint("cuTensorMapEncodeTiled", &fp, cudaEnableDefault, &qr);
        enc = (PFN_encodeTiled)fp;
    }
    CUtensorMap t1Ah, t1Al, t1Bq, t2Ah, t2Al, t2Bq;
    mk2d(enc, &t1Ah, pxh,  DIMK,    ROWS);
    mk2d(enc, &t1Al, pxl,  DIMK,    ROWS);
    mk2d(enc, &t1Bq, pWq,  DIMK,    NPROJ_PAD);
    mk2d(enc, &t2Ah, pYh,  D_INNER, ROWS);
    mk2d(enc, &t2Al, pYl,  D_INNER, ROWS);
    mk2d(enc, &t2Bq, pWoq, D_INNER, DIMK);

    const int smem1 = SSB_OFF + 16 * 132 * 4;
    const int smem2 = SSB_OFF + 32 * 132 * 4;

    cudaFuncSetAttribute(k_chunk,    cudaFuncAttributeMaxDynamicSharedMemorySize, SM_CHUNK_BYTES);
    cudaFuncSetAttribute(k_mmt<16>,  cudaFuncAttributeMaxDynamicSharedMemorySize, smem1);
    cudaFuncSetAttribute(k_mmt<32>,  cudaFuncAttributeMaxDynamicSharedMemorySize, smem2);

    k_dequantq<<<(8384*16 + 3)/4, 128>>>(Win, pWq, pWs, 8384*16);
    k_dequantq<<<(512 + 3)/4,    128>>>(Wth, pWq + (size_t)8384*DIMK, pWs + (size_t)8384*16, 512);
    k_dequantq<<<(1024 + 3)/4,   128>>>(Wla, pWq + (size_t)8416*DIMK, pWs + (size_t)8416*16, 1024);
    k_dequantq<<<65536/4,        128>>>(Wout, pWoq, pWos, 65536);

    k_split<<<ROWS*DIMK/1024, 256>>>(x, pxh, pxl);

    k_mmt<16><<<dim3(ROWS/128, NPROJ_PAD/128), 512, smem1>>>(
        t1Ah, t1Al, t1Bq, pWs, pP, NPROJ, NPROJ, DIMK);

    k_point<<<ROWS, 64>>>(Bb, Cb, Alog, dtb);
    k_scan <<<64, 256>>>();
    k_rope <<<ROWS, 32>>>();

    k_chunk<<<dim3(NHEADS, NCHUNK, BATCH), 256, SM_CHUNK_BYTES>>>(Dp);
    k_cscan<<<512, 256>>>();
    k_off  <<<dim3(NHEADS, NCHUNK, BATCH), 256>>>();

    k_rms<<<ROWS, 256>>>();

    k_mmt<32><<<dim3(ROWS/128, DIMK/128), 512, smem2>>>(
        t2Ah, t2Al, t2Bq, pWos, out, DIMK, DIMK, D_INNER);
}

// round 16
// speedup vs baseline: 1.2581x; 1.0067x over previous
#include <cuda.h>
#include <cuda_runtime.h>
#include <cuda_bf16.h>
#include <math.h>
#include <stdint.h>

#define SEQ     4096
#define BATCH   2
#define ROWS    (BATCH*SEQ)     // 8192
#define DIMK    2048
#define D_INNER 4096
#define NHEADS  64
#define NPROJ   8480
#define NPROJ_PAD 8576          // 67 * 128
#define OFF_Z   0
#define OFF_XC  4096
#define OFF_B   8192
#define OFF_C   8256
#define OFF_DT  8320
#define OFF_TH  8384
#define OFF_LAM 8416
#define NCHUNK  64
#define RMS_EPS 1.1920929e-07f

// ---------------- device scratch (no allocation allowed) ----------------
__device__ __nv_bfloat16 g_Wq [NPROJ_PAD * DIMK];
__device__ float         g_Ws [NPROJ_PAD * 16];
__device__ __nv_bfloat16 g_Woq[DIMK * D_INNER];
__device__ float         g_Wos[DIMK * 32];
__device__ __nv_bfloat16 g_xh [ROWS * DIMK];
__device__ __nv_bfloat16 g_xl [ROWS * DIMK];
__device__ __nv_bfloat16 g_Yh [ROWS * D_INNER];
__device__ __nv_bfloat16 g_Yl [ROWS * D_INNER];
__device__ float g_P [ROWS * NPROJ];
__device__ float g_Bv[ROWS * 64];
__device__ float g_Cv[ROWS * 64];
__device__ float g_Ad[ROWS * 64];
__device__ float g_ga[ROWS * 64];
__device__ float g_be[ROWS * 64];
__device__ float g_td[ROWS * 32];
__device__ float g_Y [ROWS * D_INNER];          // Y_diag (+D skip) between chunk and off
__device__ float g_S [BATCH * NCHUNK * NHEADS * 64 * 64];
__device__ float g_eA[BATCH * NCHUNK * NHEADS * 64];
__device__ float g_cd[BATCH * NCHUNK * NHEADS];
__device__ float g_ss[ROWS];                     // row sum-of-squares -> rsqrt factor

__device__ __forceinline__ float siluf(float x) { return x / (1.f + expf(-x)); }

__device__ __forceinline__ uint32_t s2u(const void* p) {
    uint32_t a;
    asm("{ .reg .u64 t; cvta.to.shared.u64 t, %1; cvt.u32.u64 %0, t; }" : "=r"(a) : "l"(p));
    return a;
}

__device__ __forceinline__ void sp2(float v, __nv_bfloat16* ph, __nv_bfloat16* pl) {
    __nv_bfloat16 h = __float2bfloat16(v);
    *ph = h;
    *pl = __float2bfloat16(v - __bfloat162float(h));
}

// ================= TMA-fed quant-aware emulated-fp32 GEMM =================
#define TILE_B  16384
#define STAGE_B (3*TILE_B)
#define MB_OFF  (3*STAGE_B)
#define SSB_OFF (MB_OFF + 64)

#define SWZ(o) ((o) ^ ((((uint32_t)(o)) >> 3) & 0x70u))

#define LDSM4(r0,r1,r2,r3,a) \
    asm volatile("ldmatrix.sync.aligned.m8n8.x4.shared.b16 {%0,%1,%2,%3}, [%4];" \
        : "=r"(r0),"=r"(r1),"=r"(r2),"=r"(r3) : "r"(a))

#define MMA16816(d,a,b0,b1) \
    asm volatile("mma.sync.aligned.m16n8k16.row.col.f32.bf16.bf16.f32 " \
        "{%0,%1,%2,%3}, {%4,%5,%6,%7}, {%8,%9}, {%0,%1,%2,%3};" \
        : "+f"((d)[0]),"+f"((d)[1]),"+f"((d)[2]),"+f"((d)[3]) \
        : "r"((a)[0]),"r"((a)[1]),"r"((a)[2]),"r"((a)[3]),"r"(b0),"r"(b1))

#define MBAR_INIT(a, c) asm volatile("mbarrier.init.shared.b64 [%0], %1;" :: "r"(a), "r"(c) : "memory")
#define FENCE_ASYNC()   asm volatile("fence.proxy.async.shared::cta;" ::: "memory")
#define MBAR_EXPECT(a, bytes) \
    asm volatile("mbarrier.arrive.expect_tx.shared.b64 _, [%0], %1;" :: "r"(a), "r"(bytes) : "memory")
#define MBAR_ARRIVE(a) \
    asm volatile("mbarrier.arrive.release.cta.shared::cta.b64 _, [%0];" :: "r"(a) : "memory")

__device__ __forceinline__ void mbar_wait(uint32_t a, uint32_t ph) {
    asm volatile(
        "{\n\t.reg .pred P;\n\t"
        "WL%=:\n\tmbarrier.try_wait.parity.acquire.cta.shared::cta.b64 P, [%0], %1, 0x989680;\n\t"
        "@P bra WD%=;\n\tbra WL%=;\n\tWD%=:\n\t}"
        :: "r"(a), "r"(ph) : "memory");
}

__device__ __forceinline__ void tma2d(uint32_t dst, const CUtensorMap* m, int x, int y, uint32_t mbar) {
    asm volatile(
        "cp.async.bulk.tensor.2d.shared::cta.global.tile.mbarrier::complete_tx::bytes "
        "[%0], [%1, {%2, %3}], [%4];"
        :: "r"(dst), "l"(m), "r"(x), "r"(y), "r"(mbar) : "memory");
}

template<int NG>
__global__ void __launch_bounds__(512, 1)
k_mmt(const __grid_constant__ CUtensorMap tAh,
      const __grid_constant__ CUtensorMap tAl,
      const __grid_constant__ CUtensorMap tBq,
      const float* __restrict__ Bs, const float* __restrict__ Rs,
      float* __restrict__ C, int Nw, int Nlim, int K)
{
    extern __shared__ __align__(1024) uint8_t sh8[];
    float* ss = (float*)(sh8 + SSB_OFF);
    const uint32_t sb = s2u(sh8);
    const uint32_t mb = sb + MB_OFF;
    const int tid  = threadIdx.x;
    const int lane = tid & 31;
    const int wid  = tid >> 5;
    const int m0 = blockIdx.x * 128;
    const int n0 = blockIdx.y * 128;
    const int mw = (wid >> 2) * 32;
    const int nw = (wid & 3) * 32;

    if (tid == 0) {
        MBAR_INIT(mb + 0, 1);
        MBAR_INIT(mb + 8, 1);
        MBAR_INIT(mb + 16, 1);
        MBAR_INIT(mb + 24, 16);
        MBAR_INIT(mb + 32, 16);
        MBAR_INIT(mb + 40, 16);
    }
    for (int idx = tid; idx < 128 * NG; idx += 512) {
        int g = idx >> 7, nl = idx & 127;
        ss[g * 132 + nl] = Bs[(size_t)(n0 + nl) * NG + g];
    }
    __syncthreads();

    const int NK = K >> 6;

#define TFILL(buf, kc) do {                                   \
        uint32_t mba = mb + (buf) * 8;                        \
        MBAR_EXPECT(mba, 3 * TILE_B);                         \
        uint32_t d = sb + (buf) * STAGE_B;                    \
        tma2d(d,             &tAh, (kc) * 64, m0, mba);       \
        tma2d(d + TILE_B,    &tAl, (kc) * 64, m0, mba);       \
        tma2d(d + 2*TILE_B,  &tBq, (kc) * 64, n0, mba);       \
    } while (0)

    if (tid == 0) {
        FENCE_ASYNC();
        TFILL(0, 0);
        TFILL(1, 1);
    }
    if (lane == 0) {
        MBAR_ARRIVE(mb + 24);
        MBAR_ARRIVE(mb + 32);
        MBAR_ARRIVE(mb + 40);
    }

    float acc[2][4][4];
#pragma unroll
    for (int i = 0; i < 2; i++)
#pragma unroll
        for (int j = 0; j < 4; j++)
#pragma unroll
            for (int k = 0; k < 4; k++) acc[i][j][k] = 0.f;

    const int rowoff = (lane & 7) + ((lane >> 3) & 1) * 8;
    const int colb2  = (lane >> 4) * 16;
    const int c0 = (lane & 3) * 2;

    for (int g = 0; g < NG; g++) {
        float accg[2][4][4];
#pragma unroll
        for (int i = 0; i < 2; i++)
#pragma unroll
            for (int j = 0; j < 4; j++)
#pragma unroll
                for (int k = 0; k < 4; k++) accg[i][j][k] = 0.f;

#pragma unroll
        for (int kq = 0; kq < 2; kq++) {
            const int kc = g * 2 + kq;
            const int buf = kc % 3;

            mbar_wait(mb + buf * 8, (kc / 3) & 1);

            if (tid == 0 && kc + 2 < NK) {
                const int tbuf = (kc + 2) % 3;
                mbar_wait(mb + 24 + tbuf * 8, ((kc + 2) / 3) & 1);
                FENCE_ASYNC();
                TFILL(tbuf, kc + 2);
            }

            const uint32_t stg = sb + buf * STAGE_B;
#pragma unroll
            for (int kk = 0; kk < 4; kk++) {
                uint32_t afr[2][2][4];
                uint32_t bfr[2][4];
#pragma unroll
                for (int hl = 0; hl < 2; hl++)
#pragma unroll
                    for (int mi = 0; mi < 2; mi++) {
                        uint32_t off = (uint32_t)(mw + mi * 16 + rowoff) * 128 + kk * 32 + colb2;
                        uint32_t a = stg + hl * TILE_B + SWZ(off);
                        LDSM4(afr[hl][mi][0], afr[hl][mi][1], afr[hl][mi][2], afr[hl][mi][3], a);
                    }
#pragma unroll
                for (int nj = 0; nj < 2; nj++) {
                    uint32_t off = (uint32_t)(nw + nj * 16 + rowoff) * 128 + kk * 32 + colb2;
                    uint32_t a = stg + 2 * TILE_B + SWZ(off);
                    LDSM4(bfr[nj][0], bfr[nj][1], bfr[nj][2], bfr[nj][3], a);
                }
#pragma unroll
                for (int term = 0; term < 2; term++)
#pragma unroll
                    for (int mi = 0; mi < 2; mi++)
#pragma unroll
                        for (int ni = 0; ni < 4; ni++) {
                            int nj = ni >> 1, s = ni & 1;
                            MMA16816(accg[mi][ni], afr[term][mi],
                                     bfr[nj][s], bfr[nj][s + 2]);
                        }
            }

            if (lane == 0) MBAR_ARRIVE(mb + 24 + buf * 8);
        }

#pragma unroll
        for (int ni = 0; ni < 4; ni++) {
            float2 sv = *(const float2*)&ss[g * 132 + nw + ni * 8 + c0];
#pragma unroll
            for (int mi = 0; mi < 2; mi++) {
                acc[mi][ni][0] = fmaf(sv.x, accg[mi][ni][0], acc[mi][ni][0]);
                acc[mi][ni][1] = fmaf(sv.y, accg[mi][ni][1], acc[mi][ni][1]);
                acc[mi][ni][2] = fmaf(sv.x, accg[mi][ni][2], acc[mi][ni][2]);
                acc[mi][ni][3] = fmaf(sv.y, accg[mi][ni][3], acc[mi][ni][3]);
            }
        }
    }

    const int r0 = lane >> 2;
#pragma unroll
    for (int mi = 0; mi < 2; mi++) {
        int m = m0 + mw + mi * 16 + r0;
        float rlo = Rs ? Rs[m]     : 1.f;
        float rhi = Rs ? Rs[m + 8] : 1.f;
#pragma unroll
        for (int ni = 0; ni < 4; ni++) {
            int n = n0 + nw + ni * 8 + c0;
            if (n < Nlim) {
                *(float2*)&C[(size_t)m * Nw + n]       = make_float2(rlo*acc[mi][ni][0], rlo*acc[mi][ni][1]);
                *(float2*)&C[(size_t)(m + 8) * Nw + n] = make_float2(rhi*acc[mi][ni][2], rhi*acc[mi][ni][3]);
            }
        }
    }
#undef TFILL
}

// ---------------- fq4 dequantization -> q (bf16, exact) + group scale ----------------
__global__ void k_dequantq(const float* __restrict__ src, __nv_bfloat16* __restrict__ dq,
                           float* __restrict__ ds, int ngroups)
{
    int g = blockIdx.x * 4 + (threadIdx.x >> 5);
    if (g >= ngroups) return;
    int lane = threadIdx.x & 31;
    const float* s = src + (size_t)g * 128;
    float v[4];
    float m = 0.f;
#pragma unroll
    for (int i = 0; i < 4; i++) { v[i] = s[lane + 32*i]; m = fmaxf(m, fabsf(v[i])); }
#pragma unroll
    for (int o = 16; o; o >>= 1) m = fmaxf(m, __shfl_xor_sync(0xffffffffu, m, o));
    float scale = fmaxf(m, 1e-10f) / 7.0f;
    if (lane == 0) ds[g] = scale;
#pragma unroll
    for (int i = 0; i < 4; i++) {
        float q = rintf(v[i] / scale);
        q = fminf(fmaxf(q, -8.f), 7.f);
        dq[(size_t)g * 128 + lane + 32*i] = __float2bfloat16(q);
    }
}

// ---------------- split fp32 -> bf16 hi/lo ----------------
__global__ void k_split(const float* __restrict__ src, __nv_bfloat16* __restrict__ dh,
                        __nv_bfloat16* __restrict__ dl)
{
    size_t i = ((size_t)blockIdx.x * 256 + threadIdx.x) * 4;
    float4 v = *(const float4*)(src + i);
    float vv[4] = {v.x, v.y, v.z, v.w};
#pragma unroll
    for (int k = 0; k < 4; k++) sp2(vv[k], dh + i + k, dl + i + k);
}

// ---------------- pointwise epilogue per (b,l) row: 64 threads ----------------
__global__ void k_point(const float* __restrict__ Bb, const float* __restrict__ Cb,
                        const float* __restrict__ Alog, const float* __restrict__ dtb)
{
    int row = blockIdx.x;
    int t = threadIdx.x;
    const float* pr = g_P + (size_t)row * NPROJ;
    __shared__ float red[6];

    float dtr = pr[OFF_DT + t] + dtb[t];
    float dt = (dtr > 20.f) ? dtr : log1pf(expf(dtr));
    float Ad = -expf(Alog[t]) * dt;
    float lam = 1.f / (1.f + expf(-pr[OFF_LAM + t]));
    g_Ad[row*64 + t] = Ad;
    g_ga[row*64 + t] = lam * dt;
    g_be[row*64 + t] = (1.f - lam) * dt * expf(Ad);

    float bv = pr[OFF_B + t];
    float cv = pr[OFF_C + t];

    float s0 = dt, s1 = bv*bv, s2 = cv*cv;
#pragma unroll
    for (int o = 16; o; o >>= 1) {
        s0 += __shfl_xor_sync(0xffffffffu, s0, o);
        s1 += __shfl_xor_sync(0xffffffffu, s1, o);
        s2 += __shfl_xor_sync(0xffffffffu, s2, o);
    }
    int w = t >> 5;
    if ((t & 31) == 0) { red[w*3+0] = s0; red[w*3+1] = s1; red[w*3+2] = s2; }
    __syncthreads();
    float dt_avg = (red[0] + red[3]) * (1.f/64.f);
    float rb = rsqrtf((red[1] + red[4]) * (1.f/64.f) + RMS_EPS);
    float rc = rsqrtf((red[2] + red[5]) * (1.f/64.f) + RMS_EPS);

    g_Bv[row*64 + t] = bv * rb + Bb[t];
    g_Cv[row*64 + t] = cv * rc + Cb[t];
    if (t < 32) g_td[row*32 + t] = pr[OFF_TH + t] * dt_avg;
}

// ---------------- cumsum of theta*dt_avg over L per (b, n) ----------------
__global__ void k_scan()
{
    int b = blockIdx.x >> 5;
    int n = blockIdx.x & 31;
    int tid = threadIdx.x;
    __shared__ float ps[256];
    float loc[16];
    float run = 0.f;
    int base = (b*SEQ + tid*16) * 32 + n;
#pragma unroll
    for (int j = 0; j < 16; j++) { run += g_td[base + j*32]; loc[j] = run; }
    ps[tid] = run;
    __syncthreads();
#pragma unroll
    for (int o = 1; o < 256; o <<= 1) {
        float v = (tid >= o) ? ps[tid - o] : 0.f;
        __syncthreads();
        ps[tid] += v;
        __syncthreads();
    }
    float off = (tid > 0) ? ps[tid - 1] : 0.f;
#pragma unroll
    for (int j = 0; j < 16; j++) g_td[base + j*32] = loc[j] + off;
}

// ---------------- rope on B and C (in place) ----------------
__global__ void k_rope()
{
    int row = blockIdx.x;
    int t = threadIdx.x;
    float a = g_td[row*32 + t];
    float ca = cosf(a), sa = sinf(a);
    float br = g_Bv[row*64 + t], bi = g_Bv[row*64 + 32 + t];
    g_Bv[row*64 + t]      = br*ca - bi*sa;
    g_Bv[row*64 + 32 + t] = br*sa + bi*ca;
    float cr = g_Cv[row*64 + t], ci = g_Cv[row*64 + 32 + t];
    g_Cv[row*64 + t]      = cr*ca - ci*sa;
    g_Cv[row*64 + 32 + t] = cr*sa + ci*ca;
}

// ---------------- intra-chunk: Y_diag (+ D skip) + per-chunk states ----------------
#define SM_CHUNK_BYTES ((4352*5 + 128) * 4)
__launch_bounds__(256)
__global__ void k_chunk(const float* __restrict__ Dp)
{
    extern __shared__ float sm[];
    float* sX  = sm;
    float* sB  = sm + 4352;
    float* sBT = sm + 8704;
    float* sCT = sm + 13056;
    float* sGT = sm + 17408;
    float* sA  = sm + 21760;
    float* sW  = sm + 21824;

    const int h = blockIdx.x, c = blockIdx.y, b = blockIdx.z;
    const int tid = threadIdx.x;

    if (tid < 64) {
        int row_g = b*SEQ + c*64 + tid;
        sA[tid] = g_Ad[row_g*64 + h];
    }
    __syncthreads();
#pragma unroll
    for (int o = 1; o < 64; o <<= 1) {
        float v = (tid < 64 && tid >= o) ? sA[tid - o] : 0.f;
        __syncthreads();
        if (tid < 64) sA[tid] += v;
        __syncthreads();
    }
    float Alast = sA[63];
    if (tid < 64) {
        sW[tid] = expf(Alast - sA[tid]);
        g_eA[((b*NCHUNK + c)*NHEADS + h)*64 + tid] = expf(sA[tid]);
    }
    if (tid == 0) g_cd[(b*NCHUNK + c)*NHEADS + h] = expf(Alast);

#pragma unroll
    for (int it = 0; it < 4; it++) {
        int idx = tid + it*256;
        int l = idx >> 4;
        int p4 = (idx & 15) << 2;
        int row_g = b*SEQ + c*64 + l;
        const float* xp = g_P + (size_t)row_g*NPROJ + OFF_XC + h*64 + p4;
        float4 xc = *(const float4*)xp;
        float ga = g_ga[row_g*64 + h];
        float be = g_be[row_g*64 + h];
        float4 xv;
        xv.x = siluf(xc.x)*ga; xv.y = siluf(xc.y)*ga; xv.z = siluf(xc.z)*ga; xv.w = siluf(xc.w)*ga;
        if (c*64 + l > 0) {
            float4 xq = *(const float4*)(xp - NPROJ);
            xv.x += siluf(xq.x)*be; xv.y += siluf(xq.y)*be; xv.z += siluf(xq.z)*be; xv.w += siluf(xq.w)*be;
        }
        *(float4*)&sX[l*68 + p4] = xv;
        float4 bb = *(const float4*)&g_Bv[row_g*64 + p4];
        *(float4*)&sB[l*68 + p4] = bb;
        sBT[(p4+0)*68 + l] = bb.x; sBT[(p4+1)*68 + l] = bb.y;
        sBT[(p4+2)*68 + l] = bb.z; sBT[(p4+3)*68 + l] = bb.w;
        float4 cc = *(const float4*)&g_Cv[row_g*64 + p4];
        sCT[(p4+0)*68 + l] = cc.x; sCT[(p4+1)*68 + l] = cc.y;
        sCT[(p4+2)*68 + l] = cc.z; sCT[(p4+3)*68 + l] = cc.w;
    }
    __syncthreads();

    const int ti = tid >> 4, tj = tid & 15;

    if (tj <= ti) {
        const int l0 = ti*4, s0 = tj*4;
        float acc[4][4];
#pragma unroll
        for (int i = 0; i < 4; i++)
#pragma unroll
            for (int j = 0; j < 4; j++) acc[i][j] = 0.f;
#pragma unroll
        for (int n = 0; n < 64; n++) {
            float4 cl = *(const float4*)&sCT[n*68 + l0];
            float4 bs = *(const float4*)&sBT[n*68 + s0];
            float clv[4] = {cl.x, cl.y, cl.z, cl.w};
            float bsv[4] = {bs.x, bs.y, bs.z, bs.w};
#pragma unroll
            for (int i = 0; i < 4; i++)
#pragma unroll
                for (int j = 0; j < 4; j++)
                    acc[i][j] = fmaf(clv[i], bsv[j], acc[i][j]);
        }
        float al[4];
#pragma unroll
        for (int i = 0; i < 4; i++) al[i] = sA[l0 + i];
#pragma unroll
        for (int j = 0; j < 4; j++) {
            int s = s0 + j;
            float as = sA[s];
#pragma unroll
            for (int i = 0; i < 4; i++) {
                int l = l0 + i;
                sGT[s*68 + l] = (s <= l) ? acc[i][j] * expf(al[i] - as) : 0.f;
            }
        }
    }
    __syncthreads();

    {
        const int l0 = ti*4, p0 = tj*4;
        float acc[4][4];
#pragma unroll
        for (int i = 0; i < 4; i++)
#pragma unroll
            for (int j = 0; j < 4; j++) acc[i][j] = 0.f;
        const int smax = l0 + 4;
#pragma unroll 4
        for (int s = 0; s < smax; s++) {
            float4 gt = *(const float4*)&sGT[s*68 + l0];
            float4 xr = *(const float4*)&sX[s*68 + p0];
            float gv[4] = {gt.x, gt.y, gt.z, gt.w};
            float xvv[4] = {xr.x, xr.y, xr.z, xr.w};
#pragma unroll
            for (int i = 0; i < 4; i++)
#pragma unroll
                for (int j = 0; j < 4; j++)
                    acc[i][j] = fmaf(gv[i], xvv[j], acc[i][j]);
        }
        float Dh = Dp[h];
#pragma unroll
        for (int i = 0; i < 4; i++) {
            int row_g = b*SEQ + c*64 + l0 + i;
            float4 xc = *(const float4*)&g_P[(size_t)row_g*NPROJ + OFF_XC + h*64 + p0];
            float4 o;
            o.x = acc[i][0] + Dh*siluf(xc.x);
            o.y = acc[i][1] + Dh*siluf(xc.y);
            o.z = acc[i][2] + Dh*siluf(xc.z);
            o.w = acc[i][3] + Dh*siluf(xc.w);
            *(float4*)&g_Y[(size_t)row_g*D_INNER + h*64 + p0] = o;
        }
    }

    {
        const int p0 = ti*4, n0 = tj*4;
        float acc[4][4];
#pragma unroll
        for (int i = 0; i < 4; i++)
#pragma unroll
            for (int j = 0; j < 4; j++) acc[i][j] = 0.f;
#pragma unroll
        for (int l = 0; l < 64; l++) {
            float w = sW[l];
            float4 xr = *(const float4*)&sX[l*68 + p0];
            float4 br = *(const float4*)&sB[l*68 + n0];
            float wx[4] = {w*xr.x, w*xr.y, w*xr.z, w*xr.w};
            float bvv[4] = {br.x, br.y, br.z, br.w};
#pragma unroll
            for (int i = 0; i < 4; i++)
#pragma unroll
                for (int j = 0; j < 4; j++)
                    acc[i][j] = fmaf(wx[i], bvv[j], acc[i][j]);
        }
        size_t base = (size_t)((b*NCHUNK + c)*NHEADS + h) * 4096;
#pragma unroll
        for (int i = 0; i < 4; i++)
            *(float4*)&g_S[base + (p0 + i)*64 + n0] =
                make_float4(acc[i][0], acc[i][1], acc[i][2], acc[i][3]);
    }
}

// ---------------- inter-chunk scan: 512 CTAs ----------------
__global__ void k_cscan()
{
    int q = blockIdx.x & 3;
    int h = (blockIdx.x >> 2) & 63;
    int b = blockIdx.x >> 8;
    int tid = threadIdx.x;
    int off = q * 1024 + tid * 4;
    float s0 = 0.f, s1 = 0.f, s2 = 0.f, s3 = 0.f;
    const float* cdp = g_cd + b * NCHUNK * NHEADS + h;
    for (int c = 0; c < NCHUNK; c++) {
        size_t base = ((size_t)((b*NCHUNK + c)*NHEADS + h) << 12) + off;
        float cd = cdp[c * NHEADS];
        float4 t = *(const float4*)&g_S[base];
        *(float4*)&g_S[base] = make_float4(s0, s1, s2, s3);
        s0 = fmaf(cd, s0, t.x);
        s1 = fmaf(cd, s1, t.y);
        s2 = fmaf(cd, s2, t.z);
        s3 = fmaf(cd, s3, t.w);
    }
}

// ---------------- Y_off + z gating -> bf16 hi/lo (+ row sumsq atomics) ----------------
__launch_bounds__(256)
__global__ void k_off()
{
    __shared__ float sST[64*68];
    __shared__ float sCT[64*68];
    const int h = blockIdx.x, c = blockIdx.y, b = blockIdx.z;
    const int tid = threadIdx.x;
    const int lane = tid & 31;
    size_t sbase = (size_t)((b*NCHUNK + c)*NHEADS + h) * 4096;
#pragma unroll
    for (int it = 0; it < 4; it++) {
        int idx = tid + it*256;
        int r = idx >> 4;
        int n4 = (idx & 15) << 2;
        float4 sv = *(const float4*)&g_S[sbase + r*64 + n4];
        sST[(n4+0)*68 + r] = sv.x; sST[(n4+1)*68 + r] = sv.y;
        sST[(n4+2)*68 + r] = sv.z; sST[(n4+3)*68 + r] = sv.w;
        int row_g = b*SEQ + c*64 + r;
        float4 cv = *(const float4*)&g_Cv[row_g*64 + n4];
        sCT[(n4+0)*68 + r] = cv.x; sCT[(n4+1)*68 + r] = cv.y;
        sCT[(n4+2)*68 + r] = cv.z; sCT[(n4+3)*68 + r] = cv.w;
    }
    __syncthreads();
    const int ti = tid >> 4, tj = tid & 15;
    const int l0 = ti*4, p0 = tj*4;
    float acc[4][4];
#pragma unroll
    for (int i = 0; i < 4; i++)
#pragma unroll
        for (int j = 0; j < 4; j++) acc[i][j] = 0.f;
#pragma unroll
    for (int n = 0; n < 64; n++) {
        float4 cl = *(const float4*)&sCT[n*68 + l0];
        float4 sp = *(const float4*)&sST[n*68 + p0];
        float clv[4] = {cl.x, cl.y, cl.z, cl.w};
        float spv[4] = {sp.x, sp.y, sp.z, sp.w};
#pragma unroll
        for (int i = 0; i < 4; i++)
#pragma unroll
            for (int j = 0; j < 4; j++)
                acc[i][j] = fmaf(clv[i], spv[j], acc[i][j]);
    }
    float sq[4];
#pragma unroll
    for (int i = 0; i < 4; i++) {
        int l = l0 + i;
        int row_g = b*SEQ + c*64 + l;
        float e = g_eA[((b*NCHUNK + c)*NHEADS + h)*64 + l];
        const float* pr = g_P + (size_t)row_g*NPROJ;
        float4 zz = *(const float4*)&pr[OFF_Z + h*64 + p0];
        const float* yp = &g_Y[(size_t)row_g*D_INNER + h*64 + p0];
        float4 yd = *(const float4*)yp;
        float o0 = (yd.x + e*acc[i][0]) * siluf(zz.x);
        float o1 = (yd.y + e*acc[i][1]) * siluf(zz.y);
        float o2 = (yd.z + e*acc[i][2]) * siluf(zz.z);
        float o3 = (yd.w + e*acc[i][3]) * siluf(zz.w);
        sq[i] = o0*o0 + o1*o1 + o2*o2 + o3*o3;
        size_t ob = (size_t)row_g*D_INNER + h*64 + p0;
        __nv_bfloat16 hbuf[4], lbuf[4];
        sp2(o0, hbuf + 0, lbuf + 0);
        sp2(o1, hbuf + 1, lbuf + 1);
        sp2(o2, hbuf + 2, lbuf + 2);
        sp2(o3, hbuf + 3, lbuf + 3);
        *(uint2*)(g_Yh + ob) = *(uint2*)hbuf;
        *(uint2*)(g_Yl + ob) = *(uint2*)lbuf;
    }
    // reduce sq over the 16 lanes sharing this row group, then atomic-add
#pragma unroll
    for (int o = 8; o; o >>= 1)
#pragma unroll
        for (int i = 0; i < 4; i++)
            sq[i] += __shfl_xor_sync(0xffffffffu, sq[i], o);
    if ((lane & 15) == 0) {
        int row_g = b*SEQ + c*64 + l0;
#pragma unroll
        for (int i = 0; i < 4; i++)
            atomicAdd(&g_ss[row_g + i], sq[i]);
    }
}

// ---------------- ss -> rsqrt factor (in place) ----------------
__global__ void k_rfac()
{
    int i = blockIdx.x * 1024 + threadIdx.x;
    g_ss[i] = rsqrtf(g_ss[i] * (1.f/4096.f) + RMS_EPS);
}

// ---------------- host: tensormap construction ----------------
typedef CUresult (*PFN_encodeTiled)(
    CUtensorMap*, CUtensorMapDataType, cuuint32_t, void*,
    const cuuint64_t*, const cuuint64_t*, const cuuint32_t*, const cuuint32_t*,
    CUtensorMapInterleave, CUtensorMapSwizzle, CUtensorMapL2promotion, CUtensorMapFloatOOBfill);

static void mk2d(PFN_encodeTiled enc, CUtensorMap* m, void* ptr, uint64_t k, uint64_t rows)
{
    cuuint64_t dims[2]    = {k, rows};
    cuuint64_t strides[1] = {k * 2};
    cuuint32_t box[2]     = {64, 128};
    cuuint32_t es[2]      = {1, 1};
    enc(m, CU_TENSOR_MAP_DATA_TYPE_BFLOAT16, 2, ptr, dims, strides, box, es,
        CU_TENSOR_MAP_INTERLEAVE_NONE, CU_TENSOR_MAP_SWIZZLE_128B,
        CU_TENSOR_MAP_L2_PROMOTION_L2_128B, CU_TENSOR_MAP_FLOAT_OOB_FILL_NONE);
}

// ---------------- launcher ----------------
extern "C" void kernel_launch(void* const* d_in, const int* in_sizes, int n_in,
                              void* d_out, int out_size)
{
    const float* x    = (const float*)d_in[0];
    const float* Win  = (const float*)d_in[1];
    const float* Wth  = (const float*)d_in[2];
    const float* Wla  = (const float*)d_in[3];
    const float* Wout = (const float*)d_in[4];
    const float* Bb   = (const float*)d_in[5];
    const float* Cb   = (const float*)d_in[6];
    const float* Alog = (const float*)d_in[7];
    const float* Dp   = (const float*)d_in[8];
    const float* dtb  = (const float*)d_in[9];
    float* out = (float*)d_out;

    __nv_bfloat16 *pWq, *pWoq, *pxh, *pxl, *pYh, *pYl;
    float *pWs, *pWos, *pP, *pss;
    cudaGetSymbolAddress((void**)&pWq,  g_Wq);
    cudaGetSymbolAddress((void**)&pWs,  g_Ws);
    cudaGetSymbolAddress((void**)&pWoq, g_Woq);
    cudaGetSymbolAddress((void**)&pWos, g_Wos);
    cudaGetSymbolAddress((void**)&pxh,  g_xh);
    cudaGetSymbolAddress((void**)&pxl,  g_xl);
    cudaGetSymbolAddress((void**)&pYh,  g_Yh);
    cudaGetSymbolAddress((void**)&pYl,  g_Yl);
    cudaGetSymbolAddress((void**)&pP,   g_P);
    cudaGetSymbolAddress((void**)&pss,  g_ss);

    PFN_encodeTiled enc = nullptr;
    {
        void* fp = nullptr;
        cudaDriverEntryPointQueryResult qr;
        cudaGetDriverEntryPoint("cuTensorMapEncodeTiled", &fp, cudaEnableDefault, &qr);
        enc = (PFN_encodeTiled)fp;
    }
    CUtensorMap t1Ah, t1Al, t1Bq, t2Ah, t2Al, t2Bq;
    mk2d(enc, &t1Ah, pxh,  DIMK,    ROWS);
    mk2d(enc, &t1Al, pxl,  DIMK,    ROWS);
    mk2d(enc, &t1Bq, pWq,  DIMK,    NPROJ_PAD);
    mk2d(enc, &t2Ah, pYh,  D_INNER, ROWS);
    mk2d(enc, &t2Al, pYl,  D_INNER, ROWS);
    mk2d(enc, &t2Bq, pWoq, D_INNER, DIMK);

    const int smem1 = SSB_OFF + 16 * 132 * 4;
    const int smem2 = SSB_OFF + 32 * 132 * 4;

    cudaFuncSetAttribute(k_chunk,    cudaFuncAttributeMaxDynamicSharedMemorySize, SM_CHUNK_BYTES);
    cudaFuncSetAttribute(k_mmt<16>,  cudaFuncAttributeMaxDynamicSharedMemorySize, smem1);
    cudaFuncSetAttribute(k_mmt<32>,  cudaFuncAttributeMaxDynamicSharedMemorySize, smem2);

    k_dequantq<<<(8384*16 + 3)/4, 128>>>(Win, pWq, pWs, 8384*16);
    k_dequantq<<<(512 + 3)/4,    128>>>(Wth, pWq + (size_t)8384*DIMK, pWs + (size_t)8384*16, 512);
    k_dequantq<<<(1024 + 3)/4,   128>>>(Wla, pWq + (size_t)8416*DIMK, pWs + (size_t)8416*16, 1024);
    k_dequantq<<<65536/4,        128>>>(Wout, pWoq, pWos, 65536);

    k_split<<<ROWS*DIMK/1024, 256>>>(x, pxh, pxl);
    cudaMemsetAsync(pss, 0, ROWS * sizeof(float));

    k_mmt<16><<<dim3(ROWS/128, NPROJ_PAD/128), 512, smem1>>>(
        t1Ah, t1Al, t1Bq, pWs, nullptr, pP, NPROJ, NPROJ, DIMK);

    k_point<<<ROWS, 64>>>(Bb, Cb, Alog, dtb);
    k_scan <<<64, 256>>>();
    k_rope <<<ROWS, 32>>>();

    k_chunk<<<dim3(NHEADS, NCHUNK, BATCH), 256, SM_CHUNK_BYTES>>>(Dp);
    k_cscan<<<512, 256>>>();
    k_off  <<<dim3(NHEADS, NCHUNK, BATCH), 256>>>();

    k_rfac<<<ROWS/1024, 1024>>>();

    k_mmt<32><<<dim3(ROWS/128, DIMK/128), 512, smem2>>>(
        t2Ah, t2Al, t2Bq, pWos, pss, out, DIMK, DIMK, D_INNER);
}

// round 17
// speedup vs baseline: 1.2781x; 1.0159x over previous
#include <cuda.h>
#include <cuda_runtime.h>
#include <cuda_bf16.h>
#include <math.h>
#include <stdint.h>

#define SEQ     4096
#define BATCH   2
#define ROWS    (BATCH*SEQ)     // 8192
#define DIMK    2048
#define D_INNER 4096
#define NHEADS  64
#define NPROJ   8480
#define NPROJ_PAD 8576          // 67 * 128
#define OFF_Z   0
#define OFF_XC  4096
#define OFF_B   8192
#define OFF_C   8256
#define OFF_DT  8320
#define OFF_TH  8384
#define OFF_LAM 8416
#define NCHUNK  64
#define RMS_EPS 1.1920929e-07f

// ---------------- device scratch (no allocation allowed) ----------------
__device__ __nv_bfloat16 g_Wq [NPROJ_PAD * DIMK];
__device__ float         g_Ws [NPROJ_PAD * 16];
__device__ __nv_bfloat16 g_Woq[DIMK * D_INNER];
__device__ float         g_Wos[DIMK * 32];
__device__ __nv_bfloat16 g_xh [ROWS * DIMK];
__device__ __nv_bfloat16 g_xl [ROWS * DIMK];
__device__ __nv_bfloat16 g_Yh [ROWS * D_INNER];
__device__ __nv_bfloat16 g_Yl [ROWS * D_INNER];
__device__ float g_P [ROWS * NPROJ];
__device__ float g_Bv[ROWS * 64];
__device__ float g_Cv[ROWS * 64];
__device__ float g_Ad[ROWS * 64];
__device__ float g_ga[ROWS * 64];
__device__ float g_be[ROWS * 64];
__device__ float g_td[ROWS * 32];
__device__ float g_Y [ROWS * D_INNER];
__device__ float g_S [BATCH * NCHUNK * NHEADS * 64 * 64];
__device__ float g_eA[BATCH * NCHUNK * NHEADS * 64];
__device__ float g_cd[BATCH * NCHUNK * NHEADS];
__device__ float g_ss[ROWS];

__device__ __forceinline__ float siluf(float x) { return x / (1.f + expf(-x)); }

__device__ __forceinline__ uint32_t s2u(const void* p) {
    uint32_t a;
    asm("{ .reg .u64 t; cvta.to.shared.u64 t, %1; cvt.u32.u64 %0, t; }" : "=r"(a) : "l"(p));
    return a;
}

__device__ __forceinline__ void sp2(float v, __nv_bfloat16* ph, __nv_bfloat16* pl) {
    __nv_bfloat16 h = __float2bfloat16(v);
    *ph = h;
    *pl = __float2bfloat16(v - __bfloat162float(h));
}

// ================= TMA-fed quant-aware emulated-fp32 GEMM =================
#define TILE_B  16384
#define STAGE_B (3*TILE_B)
#define MB_OFF  (3*STAGE_B)
#define SSB_OFF (MB_OFF + 64)

#define SWZ(o) ((o) ^ ((((uint32_t)(o)) >> 3) & 0x70u))

#define LDSM4(r0,r1,r2,r3,a) \
    asm volatile("ldmatrix.sync.aligned.m8n8.x4.shared.b16 {%0,%1,%2,%3}, [%4];" \
        : "=r"(r0),"=r"(r1),"=r"(r2),"=r"(r3) : "r"(a))

#define MMA16816(d,a,b0,b1) \
    asm volatile("mma.sync.aligned.m16n8k16.row.col.f32.bf16.bf16.f32 " \
        "{%0,%1,%2,%3}, {%4,%5,%6,%7}, {%8,%9}, {%0,%1,%2,%3};" \
        : "+f"((d)[0]),"+f"((d)[1]),"+f"((d)[2]),"+f"((d)[3]) \
        : "r"((a)[0]),"r"((a)[1]),"r"((a)[2]),"r"((a)[3]),"r"(b0),"r"(b1))

#define MBAR_INIT(a, c) asm volatile("mbarrier.init.shared.b64 [%0], %1;" :: "r"(a), "r"(c) : "memory")
#define FENCE_ASYNC()   asm volatile("fence.proxy.async.shared::cta;" ::: "memory")
#define MBAR_EXPECT(a, bytes) \
    asm volatile("mbarrier.arrive.expect_tx.shared.b64 _, [%0], %1;" :: "r"(a), "r"(bytes) : "memory")
#define MBAR_ARRIVE(a) \
    asm volatile("mbarrier.arrive.release.cta.shared::cta.b64 _, [%0];" :: "r"(a) : "memory")

__device__ __forceinline__ void mbar_wait(uint32_t a, uint32_t ph) {
    asm volatile(
        "{\n\t.reg .pred P;\n\t"
        "WL%=:\n\tmbarrier.try_wait.parity.acquire.cta.shared::cta.b64 P, [%0], %1, 0x989680;\n\t"
        "@P bra WD%=;\n\tbra WL%=;\n\tWD%=:\n\t}"
        :: "r"(a), "r"(ph) : "memory");
}

__device__ __forceinline__ void tma2d(uint32_t dst, const CUtensorMap* m, int x, int y, uint32_t mbar) {
    asm volatile(
        "cp.async.bulk.tensor.2d.shared::cta.global.tile.mbarrier::complete_tx::bytes "
        "[%0], [%1, {%2, %3}], [%4];"
        :: "r"(dst), "l"(m), "r"(x), "r"(y), "r"(mbar) : "memory");
}

template<int NG>
__global__ void __launch_bounds__(512, 1)
k_mmt(const __grid_constant__ CUtensorMap tAh,
      const __grid_constant__ CUtensorMap tAl,
      const __grid_constant__ CUtensorMap tBq,
      const float* __restrict__ Bs, const float* __restrict__ Rs,
      float* __restrict__ C, int Nw, int Nlim, int K)
{
    extern __shared__ __align__(1024) uint8_t sh8[];
    float* ss = (float*)(sh8 + SSB_OFF);
    const uint32_t sb = s2u(sh8);
    const uint32_t mb = sb + MB_OFF;
    const int tid  = threadIdx.x;
    const int lane = tid & 31;
    const int wid  = tid >> 5;
    const int m0 = blockIdx.x * 128;
    const int n0 = blockIdx.y * 128;
    const int mw = (wid >> 2) * 32;
    const int nw = (wid & 3) * 32;

    if (tid == 0) {
        MBAR_INIT(mb + 0, 1);
        MBAR_INIT(mb + 8, 1);
        MBAR_INIT(mb + 16, 1);
        MBAR_INIT(mb + 24, 16);
        MBAR_INIT(mb + 32, 16);
        MBAR_INIT(mb + 40, 16);
    }
    for (int idx = tid; idx < 128 * NG; idx += 512) {
        int g = idx >> 7, nl = idx & 127;
        ss[g * 132 + nl] = Bs[(size_t)(n0 + nl) * NG + g];
    }
    __syncthreads();

    const int NK = K >> 6;

#define TFILL(buf, kc) do {                                   \
        uint32_t mba = mb + (buf) * 8;                        \
        MBAR_EXPECT(mba, 3 * TILE_B);                         \
        uint32_t d = sb + (buf) * STAGE_B;                    \
        tma2d(d,             &tAh, (kc) * 64, m0, mba);       \
        tma2d(d + TILE_B,    &tAl, (kc) * 64, m0, mba);       \
        tma2d(d + 2*TILE_B,  &tBq, (kc) * 64, n0, mba);       \
    } while (0)

    if (tid == 0) {
        FENCE_ASYNC();
        TFILL(0, 0);
        TFILL(1, 1);
    }
    if (lane == 0) {
        MBAR_ARRIVE(mb + 24);
        MBAR_ARRIVE(mb + 32);
        MBAR_ARRIVE(mb + 40);
    }

    float acc[2][4][4];
#pragma unroll
    for (int i = 0; i < 2; i++)
#pragma unroll
        for (int j = 0; j < 4; j++)
#pragma unroll
            for (int k = 0; k < 4; k++) acc[i][j][k] = 0.f;

    const int rowoff = (lane & 7) + ((lane >> 3) & 1) * 8;
    const int colb2  = (lane >> 4) * 16;
    const int c0 = (lane & 3) * 2;

    for (int g = 0; g < NG; g++) {
        float accg[2][4][4];
#pragma unroll
        for (int i = 0; i < 2; i++)
#pragma unroll
            for (int j = 0; j < 4; j++)
#pragma unroll
                for (int k = 0; k < 4; k++) accg[i][j][k] = 0.f;

#pragma unroll
        for (int kq = 0; kq < 2; kq++) {
            const int kc = g * 2 + kq;
            const int buf = kc % 3;

            mbar_wait(mb + buf * 8, (kc / 3) & 1);

            if (tid == 0 && kc + 2 < NK) {
                const int tbuf = (kc + 2) % 3;
                mbar_wait(mb + 24 + tbuf * 8, ((kc + 2) / 3) & 1);
                FENCE_ASYNC();
                TFILL(tbuf, kc + 2);
            }

            const uint32_t stg = sb + buf * STAGE_B;
#pragma unroll
            for (int kk = 0; kk < 4; kk++) {
                uint32_t afr[2][2][4];
                uint32_t bfr[2][4];
#pragma unroll
                for (int hl = 0; hl < 2; hl++)
#pragma unroll
                    for (int mi = 0; mi < 2; mi++) {
                        uint32_t off = (uint32_t)(mw + mi * 16 + rowoff) * 128 + kk * 32 + colb2;
                        uint32_t a = stg + hl * TILE_B + SWZ(off);
                        LDSM4(afr[hl][mi][0], afr[hl][mi][1], afr[hl][mi][2], afr[hl][mi][3], a);
                    }
#pragma unroll
                for (int nj = 0; nj < 2; nj++) {
                    uint32_t off = (uint32_t)(nw + nj * 16 + rowoff) * 128 + kk * 32 + colb2;
                    uint32_t a = stg + 2 * TILE_B + SWZ(off);
                    LDSM4(bfr[nj][0], bfr[nj][1], bfr[nj][2], bfr[nj][3], a);
                }
#pragma unroll
                for (int term = 0; term < 2; term++)
#pragma unroll
                    for (int mi = 0; mi < 2; mi++)
#pragma unroll
                        for (int ni = 0; ni < 4; ni++) {
                            int nj = ni >> 1, s = ni & 1;
                            MMA16816(accg[mi][ni], afr[term][mi],
                                     bfr[nj][s], bfr[nj][s + 2]);
                        }
            }

            if (lane == 0) MBAR_ARRIVE(mb + 24 + buf * 8);
        }

#pragma unroll
        for (int ni = 0; ni < 4; ni++) {
            float2 sv = *(const float2*)&ss[g * 132 + nw + ni * 8 + c0];
#pragma unroll
            for (int mi = 0; mi < 2; mi++) {
                acc[mi][ni][0] = fmaf(sv.x, accg[mi][ni][0], acc[mi][ni][0]);
                acc[mi][ni][1] = fmaf(sv.y, accg[mi][ni][1], acc[mi][ni][1]);
                acc[mi][ni][2] = fmaf(sv.x, accg[mi][ni][2], acc[mi][ni][2]);
                acc[mi][ni][3] = fmaf(sv.y, accg[mi][ni][3], acc[mi][ni][3]);
            }
        }
    }

    const int r0 = lane >> 2;
#pragma unroll
    for (int mi = 0; mi < 2; mi++) {
        int m = m0 + mw + mi * 16 + r0;
        float rlo = Rs ? Rs[m]     : 1.f;
        float rhi = Rs ? Rs[m + 8] : 1.f;
#pragma unroll
        for (int ni = 0; ni < 4; ni++) {
            int n = n0 + nw + ni * 8 + c0;
            if (n < Nlim) {
                *(float2*)&C[(size_t)m * Nw + n]       = make_float2(rlo*acc[mi][ni][0], rlo*acc[mi][ni][1]);
                *(float2*)&C[(size_t)(m + 8) * Nw + n] = make_float2(rhi*acc[mi][ni][2], rhi*acc[mi][ni][3]);
            }
        }
    }
#undef TFILL
}

// ---------------- fq4 dequantization -> q (bf16, exact) + group scale ----------------
__global__ void k_dequantq(const float* __restrict__ src, __nv_bfloat16* __restrict__ dq,
                           float* __restrict__ ds, int ngroups)
{
    int g = blockIdx.x * 4 + (threadIdx.x >> 5);
    if (g >= ngroups) return;
    int lane = threadIdx.x & 31;
    const float* s = src + (size_t)g * 128;
    float v[4];
    float m = 0.f;
#pragma unroll
    for (int i = 0; i < 4; i++) { v[i] = s[lane + 32*i]; m = fmaxf(m, fabsf(v[i])); }
#pragma unroll
    for (int o = 16; o; o >>= 1) m = fmaxf(m, __shfl_xor_sync(0xffffffffu, m, o));
    float scale = fmaxf(m, 1e-10f) / 7.0f;
    if (lane == 0) ds[g] = scale;
#pragma unroll
    for (int i = 0; i < 4; i++) {
        float q = rintf(v[i] / scale);
        q = fminf(fmaxf(q, -8.f), 7.f);
        dq[(size_t)g * 128 + lane + 32*i] = __float2bfloat16(q);
    }
}

// ---------------- split fp32 -> bf16 hi/lo ----------------
__global__ void k_split(const float* __restrict__ src, __nv_bfloat16* __restrict__ dh,
                        __nv_bfloat16* __restrict__ dl)
{
    size_t i = ((size_t)blockIdx.x * 256 + threadIdx.x) * 4;
    float4 v = *(const float4*)(src + i);
    float vv[4] = {v.x, v.y, v.z, v.w};
#pragma unroll
    for (int k = 0; k < 4; k++) sp2(vv[k], dh + i + k, dl + i + k);
}

// ---------------- pointwise epilogue: 256 threads, 4 rows per block ----------------
__global__ void __launch_bounds__(256)
k_point(const float* __restrict__ Bb, const float* __restrict__ Cb,
        const float* __restrict__ Alog, const float* __restrict__ dtb)
{
    int rg  = threadIdx.x >> 6;            // row group 0..3
    int t   = threadIdx.x & 63;
    int row = blockIdx.x * 4 + rg;
    const float* pr = g_P + (size_t)row * NPROJ;
    __shared__ float red[4][6];

    float dtr = pr[OFF_DT + t] + dtb[t];
    float dt = (dtr > 20.f) ? dtr : log1pf(expf(dtr));
    float Ad = -expf(Alog[t]) * dt;
    float lam = 1.f / (1.f + expf(-pr[OFF_LAM + t]));
    g_Ad[row*64 + t] = Ad;
    g_ga[row*64 + t] = lam * dt;
    g_be[row*64 + t] = (1.f - lam) * dt * expf(Ad);

    float bv = pr[OFF_B + t];
    float cv = pr[OFF_C + t];

    float s0 = dt, s1 = bv*bv, s2 = cv*cv;
#pragma unroll
    for (int o = 16; o; o >>= 1) {
        s0 += __shfl_xor_sync(0xffffffffu, s0, o);
        s1 += __shfl_xor_sync(0xffffffffu, s1, o);
        s2 += __shfl_xor_sync(0xffffffffu, s2, o);
    }
    int w = (threadIdx.x >> 5) & 1;
    if ((t & 31) == 0 && w == 0) { red[rg][0] = s0; red[rg][1] = s1; red[rg][2] = s2; }
    if ((t & 31) == 0 && w == 1) { red[rg][3] = s0; red[rg][4] = s1; red[rg][5] = s2; }
    __syncthreads();
    float dt_avg = (red[rg][0] + red[rg][3]) * (1.f/64.f);
    float rb = rsqrtf((red[rg][1] + red[rg][4]) * (1.f/64.f) + RMS_EPS);
    float rc = rsqrtf((red[rg][2] + red[rg][5]) * (1.f/64.f) + RMS_EPS);

    g_Bv[row*64 + t] = bv * rb + Bb[t];
    g_Cv[row*64 + t] = cv * rc + Cb[t];
    if (t < 32) g_td[row*32 + t] = pr[OFF_TH + t] * dt_avg;
}

// ---------------- cumsum of theta*dt_avg over L per (b, n) ----------------
__global__ void k_scan()
{
    int b = blockIdx.x >> 5;
    int n = blockIdx.x & 31;
    int tid = threadIdx.x;
    __shared__ float ps[256];
    float loc[16];
    float run = 0.f;
    int base = (b*SEQ + tid*16) * 32 + n;
#pragma unroll
    for (int j = 0; j < 16; j++) { run += g_td[base + j*32]; loc[j] = run; }
    ps[tid] = run;
    __syncthreads();
#pragma unroll
    for (int o = 1; o < 256; o <<= 1) {
        float v = (tid >= o) ? ps[tid - o] : 0.f;
        __syncthreads();
        ps[tid] += v;
        __syncthreads();
    }
    float off = (tid > 0) ? ps[tid - 1] : 0.f;
#pragma unroll
    for (int j = 0; j < 16; j++) g_td[base + j*32] = loc[j] + off;
}

// ---------------- rope on B and C: 256 threads, 8 rows per block ----------------
__global__ void __launch_bounds__(256)
k_rope()
{
    int row = blockIdx.x * 8 + (threadIdx.x >> 5);
    int t   = threadIdx.x & 31;
    float a = g_td[row*32 + t];
    float ca = cosf(a), sa = sinf(a);
    float br = g_Bv[row*64 + t], bi = g_Bv[row*64 + 32 + t];
    g_Bv[row*64 + t]      = br*ca - bi*sa;
    g_Bv[row*64 + 32 + t] = br*sa + bi*ca;
    float cr = g_Cv[row*64 + t], ci = g_Cv[row*64 + 32 + t];
    g_Cv[row*64 + t]      = cr*ca - ci*sa;
    g_Cv[row*64 + 32 + t] = cr*sa + ci*ca;
}

// ---------------- intra-chunk: Y_diag (+ D skip) + per-chunk states ----------------
#define SM_CHUNK_BYTES ((4352*5 + 128) * 4)
__launch_bounds__(256)
__global__ void k_chunk(const float* __restrict__ Dp)
{
    extern __shared__ float sm[];
    float* sX  = sm;
    float* sB  = sm + 4352;
    float* sBT = sm + 8704;
    float* sCT = sm + 13056;
    float* sGT = sm + 17408;
    float* sA  = sm + 21760;
    float* sW  = sm + 21824;

    const int h = blockIdx.x, c = blockIdx.y, b = blockIdx.z;
    const int tid = threadIdx.x;

    if (tid < 64) {
        int row_g = b*SEQ + c*64 + tid;
        sA[tid] = g_Ad[row_g*64 + h];
    }
    __syncthreads();
#pragma unroll
    for (int o = 1; o < 64; o <<= 1) {
        float v = (tid < 64 && tid >= o) ? sA[tid - o] : 0.f;
        __syncthreads();
        if (tid < 64) sA[tid] += v;
        __syncthreads();
    }
    float Alast = sA[63];
    if (tid < 64) {
        sW[tid] = expf(Alast - sA[tid]);
        g_eA[((b*NCHUNK + c)*NHEADS + h)*64 + tid] = expf(sA[tid]);
    }
    if (tid == 0) g_cd[(b*NCHUNK + c)*NHEADS + h] = expf(Alast);

#pragma unroll
    for (int it = 0; it < 4; it++) {
        int idx = tid + it*256;
        int l = idx >> 4;
        int p4 = (idx & 15) << 2;
        int row_g = b*SEQ + c*64 + l;
        const float* xp = g_P + (size_t)row_g*NPROJ + OFF_XC + h*64 + p4;
        float4 xc = *(const float4*)xp;
        float ga = g_ga[row_g*64 + h];
        float be = g_be[row_g*64 + h];
        float4 xv;
        xv.x = siluf(xc.x)*ga; xv.y = siluf(xc.y)*ga; xv.z = siluf(xc.z)*ga; xv.w = siluf(xc.w)*ga;
        if (c*64 + l > 0) {
            float4 xq = *(const float4*)(xp - NPROJ);
            xv.x += siluf(xq.x)*be; xv.y += siluf(xq.y)*be; xv.z += siluf(xq.z)*be; xv.w += siluf(xq.w)*be;
        }
        *(float4*)&sX[l*68 + p4] = xv;
        float4 bb = *(const float4*)&g_Bv[row_g*64 + p4];
        *(float4*)&sB[l*68 + p4] = bb;
        sBT[(p4+0)*68 + l] = bb.x; sBT[(p4+1)*68 + l] = bb.y;
        sBT[(p4+2)*68 + l] = bb.z; sBT[(p4+3)*68 + l] = bb.w;
        float4 cc = *(const float4*)&g_Cv[row_g*64 + p4];
        sCT[(p4+0)*68 + l] = cc.x; sCT[(p4+1)*68 + l] = cc.y;
        sCT[(p4+2)*68 + l] = cc.z; sCT[(p4+3)*68 + l] = cc.w;
    }
    __syncthreads();

    const int ti = tid >> 4, tj = tid & 15;

    if (tj <= ti) {
        const int l0 = ti*4, s0 = tj*4;
        float acc[4][4];
#pragma unroll
        for (int i = 0; i < 4; i++)
#pragma unroll
            for (int j = 0; j < 4; j++) acc[i][j] = 0.f;
#pragma unroll
        for (int n = 0; n < 64; n++) {
            float4 cl = *(const float4*)&sCT[n*68 + l0];
            float4 bs = *(const float4*)&sBT[n*68 + s0];
            float clv[4] = {cl.x, cl.y, cl.z, cl.w};
            float bsv[4] = {bs.x, bs.y, bs.z, bs.w};
#pragma unroll
            for (int i = 0; i < 4; i++)
#pragma unroll
                for (int j = 0; j < 4; j++)
                    acc[i][j] = fmaf(clv[i], bsv[j], acc[i][j]);
        }
        float al[4];
#pragma unroll
        for (int i = 0; i < 4; i++) al[i] = sA[l0 + i];
#pragma unroll
        for (int j = 0; j < 4; j++) {
            int s = s0 + j;
            float as = sA[s];
#pragma unroll
            for (int i = 0; i < 4; i++) {
                int l = l0 + i;
                sGT[s*68 + l] = (s <= l) ? acc[i][j] * expf(al[i] - as) : 0.f;
            }
        }
    }
    __syncthreads();

    {
        const int l0 = ti*4, p0 = tj*4;
        float acc[4][4];
#pragma unroll
        for (int i = 0; i < 4; i++)
#pragma unroll
            for (int j = 0; j < 4; j++) acc[i][j] = 0.f;
        const int smax = l0 + 4;
#pragma unroll 4
        for (int s = 0; s < smax; s++) {
            float4 gt = *(const float4*)&sGT[s*68 + l0];
            float4 xr = *(const float4*)&sX[s*68 + p0];
            float gv[4] = {gt.x, gt.y, gt.z, gt.w};
            float xvv[4] = {xr.x, xr.y, xr.z, xr.w};
#pragma unroll
            for (int i = 0; i < 4; i++)
#pragma unroll
                for (int j = 0; j < 4; j++)
                    acc[i][j] = fmaf(gv[i], xvv[j], acc[i][j]);
        }
        float Dh = Dp[h];
#pragma unroll
        for (int i = 0; i < 4; i++) {
            int row_g = b*SEQ + c*64 + l0 + i;
            float4 xc = *(const float4*)&g_P[(size_t)row_g*NPROJ + OFF_XC + h*64 + p0];
            float4 o;
            o.x = acc[i][0] + Dh*siluf(xc.x);
            o.y = acc[i][1] + Dh*siluf(xc.y);
            o.z = acc[i][2] + Dh*siluf(xc.z);
            o.w = acc[i][3] + Dh*siluf(xc.w);
            *(float4*)&g_Y[(size_t)row_g*D_INNER + h*64 + p0] = o;
        }
    }

    {
        const int p0 = ti*4, n0 = tj*4;
        float acc[4][4];
#pragma unroll
        for (int i = 0; i < 4; i++)
#pragma unroll
            for (int j = 0; j < 4; j++) acc[i][j] = 0.f;
#pragma unroll
        for (int l = 0; l < 64; l++) {
            float w = sW[l];
            float4 xr = *(const float4*)&sX[l*68 + p0];
            float4 br = *(const float4*)&sB[l*68 + n0];
            float wx[4] = {w*xr.x, w*xr.y, w*xr.z, w*xr.w};
            float bvv[4] = {br.x, br.y, br.z, br.w};
#pragma unroll
            for (int i = 0; i < 4; i++)
#pragma unroll
                for (int j = 0; j < 4; j++)
                    acc[i][j] = fmaf(wx[i], bvv[j], acc[i][j]);
        }
        size_t base = (size_t)((b*NCHUNK + c)*NHEADS + h) * 4096;
#pragma unroll
        for (int i = 0; i < 4; i++)
            *(float4*)&g_S[base + (p0 + i)*64 + n0] =
                make_float4(acc[i][0], acc[i][1], acc[i][2], acc[i][3]);
    }
}

// ---------------- inter-chunk scan: 512 CTAs, prefetched ----------------
__global__ void k_cscan()
{
    int q = blockIdx.x & 3;
    int h = (blockIdx.x >> 2) & 63;
    int b = blockIdx.x >> 8;
    int tid = threadIdx.x;
    int off = q * 1024 + tid * 4;
    float s0 = 0.f, s1 = 0.f, s2 = 0.f, s3 = 0.f;
    const float* cdp = g_cd + b * NCHUNK * NHEADS + h;

    size_t base = ((size_t)((b*NCHUNK + 0)*NHEADS + h) << 12) + off;
    float4 t = *(const float4*)&g_S[base];
    float cd = cdp[0];
    for (int c = 0; c < NCHUNK; c++) {
        float4 tn;
        float cdn = 0.f;
        if (c + 1 < NCHUNK) {
            size_t bn = ((size_t)((b*NCHUNK + c + 1)*NHEADS + h) << 12) + off;
            tn = *(const float4*)&g_S[bn];
            cdn = cdp[(c + 1) * NHEADS];
        }
        *(float4*)&g_S[base] = make_float4(s0, s1, s2, s3);
        s0 = fmaf(cd, s0, t.x);
        s1 = fmaf(cd, s1, t.y);
        s2 = fmaf(cd, s2, t.z);
        s3 = fmaf(cd, s3, t.w);
        t = tn;
        cd = cdn;
        base += (size_t)NHEADS << 12;
    }
}

// ---------------- Y_off + z gating -> bf16 hi/lo (+ row sumsq atomics) ----------------
__launch_bounds__(256)
__global__ void k_off()
{
    __shared__ float sST[64*68];
    __shared__ float sCT[64*68];
    const int h = blockIdx.x, c = blockIdx.y, b = blockIdx.z;
    const int tid = threadIdx.x;
    const int lane = tid & 31;
    size_t sbase = (size_t)((b*NCHUNK + c)*NHEADS + h) * 4096;
#pragma unroll
    for (int it = 0; it < 4; it++) {
        int idx = tid + it*256;
        int r = idx >> 4;
        int n4 = (idx & 15) << 2;
        float4 sv = *(const float4*)&g_S[sbase + r*64 + n4];
        sST[(n4+0)*68 + r] = sv.x; sST[(n4+1)*68 + r] = sv.y;
        sST[(n4+2)*68 + r] = sv.z; sST[(n4+3)*68 + r] = sv.w;
        int row_g = b*SEQ + c*64 + r;
        float4 cv = *(const float4*)&g_Cv[row_g*64 + n4];
        sCT[(n4+0)*68 + r] = cv.x; sCT[(n4+1)*68 + r] = cv.y;
        sCT[(n4+2)*68 + r] = cv.z; sCT[(n4+3)*68 + r] = cv.w;
    }
    __syncthreads();
    const int ti = tid >> 4, tj = tid & 15;
    const int l0 = ti*4, p0 = tj*4;
    float acc[4][4];
#pragma unroll
    for (int i = 0; i < 4; i++)
#pragma unroll
        for (int j = 0; j < 4; j++) acc[i][j] = 0.f;
#pragma unroll
    for (int n = 0; n < 64; n++) {
        float4 cl = *(const float4*)&sCT[n*68 + l0];
        float4 sp = *(const float4*)&sST[n*68 + p0];
        float clv[4] = {cl.x, cl.y, cl.z, cl.w};
        float spv[4] = {sp.x, sp.y, sp.z, sp.w};
#pragma unroll
        for (int i = 0; i < 4; i++)
#pragma unroll
            for (int j = 0; j < 4; j++)
                acc[i][j] = fmaf(clv[i], spv[j], acc[i][j]);
    }
    float sq[4];
#pragma unroll
    for (int i = 0; i < 4; i++) {
        int l = l0 + i;
        int row_g = b*SEQ + c*64 + l;
        float e = g_eA[((b*NCHUNK + c)*NHEADS + h)*64 + l];
        const float* pr = g_P + (size_t)row_g*NPROJ;
        float4 zz = *(const float4*)&pr[OFF_Z + h*64 + p0];
        const float* yp = &g_Y[(size_t)row_g*D_INNER + h*64 + p0];
        float4 yd = *(const float4*)yp;
        float o0 = (yd.x + e*acc[i][0]) * siluf(zz.x);
        float o1 = (yd.y + e*acc[i][1]) * siluf(zz.y);
        float o2 = (yd.z + e*acc[i][2]) * siluf(zz.z);
        float o3 = (yd.w + e*acc[i][3]) * siluf(zz.w);
        sq[i] = o0*o0 + o1*o1 + o2*o2 + o3*o3;
        size_t ob = (size_t)row_g*D_INNER + h*64 + p0;
        __nv_bfloat16 hbuf[4], lbuf[4];
        sp2(o0, hbuf + 0, lbuf + 0);
        sp2(o1, hbuf + 1, lbuf + 1);
        sp2(o2, hbuf + 2, lbuf + 2);
        sp2(o3, hbuf + 3, lbuf + 3);
        *(uint2*)(g_Yh + ob) = *(uint2*)hbuf;
        *(uint2*)(g_Yl + ob) = *(uint2*)lbuf;
    }
#pragma unroll
    for (int o = 8; o; o >>= 1)
#pragma unroll
        for (int i = 0; i < 4; i++)
            sq[i] += __shfl_xor_sync(0xffffffffu, sq[i], o);
    if ((lane & 15) == 0) {
        int row_g = b*SEQ + c*64 + l0;
#pragma unroll
        for (int i = 0; i < 4; i++)
            atomicAdd(&g_ss[row_g + i], sq[i]);
    }
}

// ---------------- ss -> rsqrt factor (in place) ----------------
__global__ void k_rfac()
{
    int i = blockIdx.x * 1024 + threadIdx.x;
    g_ss[i] = rsqrtf(g_ss[i] * (1.f/4096.f) + RMS_EPS);
}

// ---------------- host: tensormap construction ----------------
typedef CUresult (*PFN_encodeTiled)(
    CUtensorMap*, CUtensorMapDataType, cuuint32_t, void*,
    const cuuint64_t*, const cuuint64_t*, const cuuint32_t*, const cuuint32_t*,
    CUtensorMapInterleave, CUtensorMapSwizzle, CUtensorMapL2promotion, CUtensorMapFloatOOBfill);

static void mk2d(PFN_encodeTiled enc, CUtensorMap* m, void* ptr, uint64_t k, uint64_t rows)
{
    cuuint64_t dims[2]    = {k, rows};
    cuuint64_t strides[1] = {k * 2};
    cuuint32_t box[2]     = {64, 128};
    cuuint32_t es[2]      = {1, 1};
    enc(m, CU_TENSOR_MAP_DATA_TYPE_BFLOAT16, 2, ptr, dims, strides, box, es,
        CU_TENSOR_MAP_INTERLEAVE_NONE, CU_TENSOR_MAP_SWIZZLE_128B,
        CU_TENSOR_MAP_L2_PROMOTION_L2_128B, CU_TENSOR_MAP_FLOAT_OOB_FILL_NONE);
}

// ---------------- launcher ----------------
extern "C" void kernel_launch(void* const* d_in, const int* in_sizes, int n_in,
                              void* d_out, int out_size)
{
    const float* x    = (const float*)d_in[0];
    const float* Win  = (const float*)d_in[1];
    const float* Wth  = (const float*)d_in[2];
    const float* Wla  = (const float*)d_in[3];
    const float* Wout = (const float*)d_in[4];
    const float* Bb   = (const float*)d_in[5];
    const float* Cb   = (const float*)d_in[6];
    const float* Alog = (const float*)d_in[7];
    const float* Dp   = (const float*)d_in[8];
    const float* dtb  = (const float*)d_in[9];
    float* out = (float*)d_out;

    __nv_bfloat16 *pWq, *pWoq, *pxh, *pxl, *pYh, *pYl;
    float *pWs, *pWos, *pP, *pss;
    cudaGetSymbolAddress((void**)&pWq,  g_Wq);
    cudaGetSymbolAddress((void**)&pWs,  g_Ws);
    cudaGetSymbolAddress((void**)&pWoq, g_Woq);
    cudaGetSymbolAddress((void**)&pWos, g_Wos);
    cudaGetSymbolAddress((void**)&pxh,  g_xh);
    cudaGetSymbolAddress((void**)&pxl,  g_xl);
    cudaGetSymbolAddress((void**)&pYh,  g_Yh);
    cudaGetSymbolAddress((void**)&pYl,  g_Yl);
    cudaGetSymbolAddress((void**)&pP,   g_P);
    cudaGetSymbolAddress((void**)&pss,  g_ss);

    PFN_encodeTiled enc = nullptr;
    {
        void* fp = nullptr;
        cudaDriverEntryPointQueryResult qr;
        cudaGetDriverEntryPoint("cuTensorMapEncodeTiled", &fp, cudaEnableDefault, &qr);
        enc = (PFN_encodeTiled)fp;
    }
    CUtensorMap t1Ah, t1Al, t1Bq, t2Ah, t2Al, t2Bq;
    mk2d(enc, &t1Ah, pxh,  DIMK,    ROWS);
    mk2d(enc, &t1Al, pxl,  DIMK,    ROWS);
    mk2d(enc, &t1Bq, pWq,  DIMK,    NPROJ_PAD);
    mk2d(enc, &t2Ah, pYh,  D_INNER, ROWS);
    mk2d(enc, &t2Al, pYl,  D_INNER, ROWS);
    mk2d(enc, &t2Bq, pWoq, D_INNER, DIMK);

    const int smem1 = SSB_OFF + 16 * 132 * 4;
    const int smem2 = SSB_OFF + 32 * 132 * 4;

    cudaFuncSetAttribute(k_chunk,    cudaFuncAttributeMaxDynamicSharedMemorySize, SM_CHUNK_BYTES);
    cudaFuncSetAttribute(k_mmt<16>,  cudaFuncAttributeMaxDynamicSharedMemorySize, smem1);
    cudaFuncSetAttribute(k_mmt<32>,  cudaFuncAttributeMaxDynamicSharedMemorySize, smem2);

    k_dequantq<<<(8384*16 + 3)/4, 128>>>(Win, pWq, pWs, 8384*16);
    k_dequantq<<<(512 + 3)/4,    128>>>(Wth, pWq + (size_t)8384*DIMK, pWs + (size_t)8384*16, 512);
    k_dequantq<<<(1024 + 3)/4,   128>>>(Wla, pWq + (size_t)8416*DIMK, pWs + (size_t)8416*16, 1024);
    k_dequantq<<<65536/4,        128>>>(Wout, pWoq, pWos, 65536);

    k_split<<<ROWS*DIMK/1024, 256>>>(x, pxh, pxl);
    cudaMemsetAsync(pss, 0, ROWS * sizeof(float));

    k_mmt<16><<<dim3(ROWS/128, NPROJ_PAD/128), 512, smem1>>>(
        t1Ah, t1Al, t1Bq, pWs, nullptr, pP, NPROJ, NPROJ, DIMK);

    k_point<<<ROWS/4, 256>>>(Bb, Cb, Alog, dtb);
    k_scan <<<64, 256>>>();
    k_rope <<<ROWS/8, 256>>>();

    k_chunk<<<dim3(NHEADS, NCHUNK, BATCH), 256, SM_CHUNK_BYTES>>>(Dp);
    k_cscan<<<512, 256>>>();
    k_off  <<<dim3(NHEADS, NCHUNK, BATCH), 256>>>();

    k_rfac<<<ROWS/1024, 1024>>>();

    k_mmt<32><<<dim3(ROWS/128, DIMK/128), 512, smem2>>>(
        t2Ah, t2Al, t2Bq, pWos, pss, out, DIMK, DIMK, D_INNER);
}